// round 6
// baseline (speedup 1.0000x reference)
#include <cuda_runtime.h>
#include <cuda_bf16.h>
#include <cstdint>

// ---------------------------------------------------------------------------
// MultiheadAttention: b=2, n=2048, c=1024, h=16, d=64
// Round 6: pre-split bf16 hi/lo everywhere; cp.async GEMM pipelines.
//   K0: split q,k,v + weights into bf16 hi/lo global buffers
//   K1: QKV GEMMs (pure cp.async + ldmatrix + mma loop) -> head-layout hi/lo
//   K2: tensor-core flash attention -> AO hi/lo
//   K3: out-proj GEMM -> fp32 out
// ---------------------------------------------------------------------------

namespace {
constexpr int B_ = 2;
constexpr int N_ = 2048;
constexpr int C_ = 1024;
constexpr int H_ = 16;
constexpr int D_ = 64;
constexpr float QSCALE = 0.125f * 1.44269504088896340736f;  // scale * log2(e)

constexpr int XSEG = 4096 * 1024;   // one [4096,1024] matrix
constexpr int WSEG = 1024 * 1024;   // one [1024,1024] weight

// GEMM tiling
constexpr int BM = 128, BN = 128;
constexpr int PITCH_PS = 80;                 // 32 bf16 (64B) + 16B pad
constexpr int TILE_PS = BM * PITCH_PS;       // 10240 B
constexpr int STAGE_PS = 4 * TILE_PS;        // Ahi,Alo,Bhi,Blo
constexpr int GEMM_SMEM = 2 * STAGE_PS;      // 81920 B

// Attention tiling (round-5 proven)
constexpr int APITCH = 144;
constexpr int AHALF = 128 * APITCH;
constexpr int KV_STAGE = 4 * AHALF;
constexpr int ATTN_SMEM = 2 * AHALF + 2 * KV_STAGE;
}

// Pre-split inputs/weights
__device__ __nv_bfloat16 g_Xhi[3 * XSEG];
__device__ __nv_bfloat16 g_Xlo[3 * XSEG];
__device__ __nv_bfloat16 g_Whi[4 * WSEG];
__device__ __nv_bfloat16 g_Wlo[4 * WSEG];
// Head-layout projections
__device__ __nv_bfloat16 g_Qhi[B_ * H_ * N_ * D_];
__device__ __nv_bfloat16 g_Qlo[B_ * H_ * N_ * D_];
__device__ __nv_bfloat16 g_Khi[B_ * H_ * N_ * D_];
__device__ __nv_bfloat16 g_Klo[B_ * H_ * N_ * D_];
__device__ __nv_bfloat16 g_Vhi[B_ * H_ * N_ * D_];
__device__ __nv_bfloat16 g_Vlo[B_ * H_ * N_ * D_];
// Attention output (pre-split for out-proj)
__device__ __nv_bfloat16 g_AOhi[XSEG];
__device__ __nv_bfloat16 g_AOlo[XSEG];

// ---------------------------------------------------------------------------
__device__ __forceinline__ uint32_t smem_u32(const void* p) {
    uint32_t a;
    asm("{ .reg .u64 t; cvta.to.shared.u64 t, %1; cvt.u32.u64 %0, t; }" : "=r"(a) : "l"(p));
    return a;
}
__device__ __forceinline__ void ldm_x4(uint32_t* r, uint32_t addr) {
    asm volatile("ldmatrix.sync.aligned.m8n8.x4.shared.b16 {%0,%1,%2,%3}, [%4];"
                 : "=r"(r[0]), "=r"(r[1]), "=r"(r[2]), "=r"(r[3]) : "r"(addr));
}
__device__ __forceinline__ void ldm_x4_t(uint32_t* r, uint32_t addr) {
    asm volatile("ldmatrix.sync.aligned.m8n8.x4.trans.shared.b16 {%0,%1,%2,%3}, [%4];"
                 : "=r"(r[0]), "=r"(r[1]), "=r"(r[2]), "=r"(r[3]) : "r"(addr));
}
__device__ __forceinline__ void mma16816(float* c, const uint32_t* a, const uint32_t* b) {
    asm volatile(
        "mma.sync.aligned.m16n8k16.row.col.f32.bf16.bf16.f32 "
        "{%0,%1,%2,%3}, {%4,%5,%6,%7}, {%8,%9}, {%0,%1,%2,%3};"
        : "+f"(c[0]), "+f"(c[1]), "+f"(c[2]), "+f"(c[3])
        : "r"(a[0]), "r"(a[1]), "r"(a[2]), "r"(a[3]), "r"(b[0]), "r"(b[1]));
}
__device__ __forceinline__ uint32_t pack_bf16(float a, float b) {
    __nv_bfloat162 t = __floats2bfloat162_rn(a, b);
    return *reinterpret_cast<uint32_t*>(&t);
}
__device__ __forceinline__ void split2(float a, float b, uint32_t& hi, uint32_t& lo) {
    uint32_t h = pack_bf16(a, b);
    float ha = __uint_as_float(h << 16);
    float hb = __uint_as_float(h & 0xffff0000u);
    lo = pack_bf16(a - ha, b - hb);
    hi = h;
}
__device__ __forceinline__ float ex2f(float x) {
    float y;
    asm("ex2.approx.ftz.f32 %0, %1;" : "=f"(y) : "f"(x));
    return y;
}
__device__ __forceinline__ void cpa16(uint32_t dst, const void* src) {
    asm volatile("cp.async.cg.shared.global [%0], [%1], 16;" :: "r"(dst), "l"(src));
}
__device__ __forceinline__ void cp_commit() {
    asm volatile("cp.async.commit_group;" ::: "memory");
}
template <int n> __device__ __forceinline__ void cp_wait() {
    asm volatile("cp.async.wait_group %0;" :: "n"(n) : "memory");
}

// ---------------------------------------------------------------------------
// K0: fp32 -> bf16 hi/lo splitter. gridDim.y = segment (0..2: q,k,v; 3..6: w's)
// ---------------------------------------------------------------------------
__global__ __launch_bounds__(256)
void split_convert_kernel(const float* __restrict__ q, const float* __restrict__ k,
                          const float* __restrict__ v,
                          const float* __restrict__ wq, const float* __restrict__ wk,
                          const float* __restrict__ wv, const float* __restrict__ wo)
{
    const int seg = blockIdx.y;
    const float* src;
    __nv_bfloat16 *hi, *lo;
    int n4;
    switch (seg) {
        case 0: src = q;  hi = g_Xhi;            lo = g_Xlo;            n4 = XSEG / 4; break;
        case 1: src = k;  hi = g_Xhi + XSEG;     lo = g_Xlo + XSEG;     n4 = XSEG / 4; break;
        case 2: src = v;  hi = g_Xhi + 2 * XSEG; lo = g_Xlo + 2 * XSEG; n4 = XSEG / 4; break;
        case 3: src = wq; hi = g_Whi;            lo = g_Wlo;            n4 = WSEG / 4; break;
        case 4: src = wk; hi = g_Whi + WSEG;     lo = g_Wlo + WSEG;     n4 = WSEG / 4; break;
        case 5: src = wv; hi = g_Whi + 2 * WSEG; lo = g_Wlo + 2 * WSEG; n4 = WSEG / 4; break;
        default: src = wo; hi = g_Whi + 3 * WSEG; lo = g_Wlo + 3 * WSEG; n4 = WSEG / 4; break;
    }
    const int idx = blockIdx.x * 256 + threadIdx.x;
    if (idx >= n4) return;
    float4 x = reinterpret_cast<const float4*>(src)[idx];
    uint32_t h01, l01, h23, l23;
    split2(x.x, x.y, h01, l01);
    split2(x.z, x.w, h23, l23);
    reinterpret_cast<uint2*>(hi)[idx] = make_uint2(h01, h23);
    reinterpret_cast<uint2*>(lo)[idx] = make_uint2(l01, l23);
}

// ---------------------------------------------------------------------------
// Pre-split GEMM tile: Y = A @ B^T + bias (A,B given as bf16 hi/lo, K=1024)
// ---------------------------------------------------------------------------
__device__ __forceinline__ void gemm_ps_tile(
    const __nv_bfloat16* __restrict__ Ahi, const __nv_bfloat16* __restrict__ Alo,
    const __nv_bfloat16* __restrict__ Bhi, const __nv_bfloat16* __restrict__ Blo,
    const float* __restrict__ bias,
    float* __restrict__ Yf32, __nv_bfloat16* __restrict__ Yhi, __nv_bfloat16* __restrict__ Ylo,
    float oscale, int rowBase, int colBase, char* sm)
{
    const int tid = threadIdx.x;
    const int lane = tid & 31;
    const int wid = tid >> 5;
    const int warp_m = wid & 3;
    const int warp_n = wid >> 2;
    const uint32_t sb = smem_u32(sm);

    float acc[2][8][4] = {};

    const uint32_t aRow = (uint32_t)(warp_m * 32 + (lane & 15)) * PITCH_PS + (uint32_t)(lane & 16);
    const uint32_t bRow = (uint32_t)(warp_n * 64 + ((lane & 7) | ((lane & 16) >> 1))) * PITCH_PS
                          + (uint32_t)((lane & 8) * 2);

    // cp.async loader for one K-chunk (32 cols) into a stage
    auto load_chunk = [&](int k0, int stage) {
        const uint32_t base = sb + (uint32_t)stage * STAGE_PS;
        #pragma unroll
        for (int l = 0; l < 2; ++l) {
            const int id = tid + l * 256;       // 0..511
            const int r = id >> 2, c = id & 3;
            const uint32_t off = (uint32_t)(r * PITCH_PS + c * 16);
            const size_t ga = (size_t)(rowBase + r) * C_ + k0 + c * 8;
            const size_t gb = (size_t)(colBase + r) * C_ + k0 + c * 8;
            cpa16(base + off,               Ahi + ga);
            cpa16(base + TILE_PS + off,     Alo + ga);
            cpa16(base + 2 * TILE_PS + off, Bhi + gb);
            cpa16(base + 3 * TILE_PS + off, Blo + gb);
        }
    };

    load_chunk(0, 0);
    cp_commit();

    for (int chunk = 0; chunk < C_ / 32; ++chunk) {
        cp_wait<0>();
        __syncthreads();
        if (chunk + 1 < C_ / 32) {
            load_chunk((chunk + 1) * 32, (chunk + 1) & 1);
            cp_commit();
        }

        const uint32_t stB = sb + (uint32_t)(chunk & 1) * STAGE_PS;
        #pragma unroll
        for (int ks = 0; ks < 2; ++ks) {
            uint32_t ah[2][4], al[2][4];
            ldm_x4(ah[0], stB + aRow + ks * 32);
            ldm_x4(ah[1], stB + aRow + 16 * PITCH_PS + ks * 32);
            ldm_x4(al[0], stB + TILE_PS + aRow + ks * 32);
            ldm_x4(al[1], stB + TILE_PS + aRow + 16 * PITCH_PS + ks * 32);
            #pragma unroll
            for (int t = 0; t < 4; ++t) {
                uint32_t bh4[4], bl4[4];
                ldm_x4(bh4, stB + 2 * TILE_PS + bRow + t * 16 * PITCH_PS + ks * 32);
                ldm_x4(bl4, stB + 3 * TILE_PS + bRow + t * 16 * PITCH_PS + ks * 32);
                #pragma unroll
                for (int f = 0; f < 2; ++f) {
                    #pragma unroll
                    for (int sub = 0; sub < 2; ++sub) {
                        float* c = acc[f][t * 2 + sub];
                        mma16816(c, ah[f], &bh4[2 * sub]);
                        mma16816(c, ah[f], &bl4[2 * sub]);
                        mma16816(c, al[f], &bh4[2 * sub]);
                    }
                }
            }
        }
        __syncthreads();
    }

    // Epilogue
    const int r = lane >> 2;
    const int cc = (lane & 3) * 2;
    #pragma unroll
    for (int f = 0; f < 2; ++f) {
        #pragma unroll
        for (int nf = 0; nf < 8; ++nf) {
            const float* c = acc[f][nf];
            const int col0 = colBase + warp_n * 64 + nf * 8 + cc;
            const int row0 = rowBase + warp_m * 32 + f * 16 + r;
            const float b0 = bias[col0], b1 = bias[col0 + 1];
            if (Yhi) {
                #pragma unroll
                for (int rr = 0; rr < 2; ++rr) {
                    const int row = row0 + rr * 8;
                    const int bb = row >> 11, i = row & (N_ - 1);
                    const int h = col0 >> 6, dd = col0 & 63;
                    const size_t idx = ((size_t)(bb * H_ + h) * N_ + i) * D_ + dd;
                    float v0 = (c[rr * 2 + 0] + b0) * oscale;
                    float v1 = (c[rr * 2 + 1] + b1) * oscale;
                    uint32_t hi, lo;
                    split2(v0, v1, hi, lo);
                    *reinterpret_cast<uint32_t*>(&Yhi[idx]) = hi;
                    *reinterpret_cast<uint32_t*>(&Ylo[idx]) = lo;
                }
            } else {
                #pragma unroll
                for (int rr = 0; rr < 2; ++rr) {
                    const int row = row0 + rr * 8;
                    float* p = &Yf32[(size_t)row * C_ + col0];
                    p[0] = c[rr * 2 + 0] + b0;
                    p[1] = c[rr * 2 + 1] + b1;
                }
            }
        }
    }
}

// K1: QKV projections
__global__ __launch_bounds__(256, 1)
void mha_qkv_ps_kernel(const float* __restrict__ bq, const float* __restrict__ bk,
                       const float* __restrict__ bv)
{
    extern __shared__ __align__(16) char sm[];
    const int z = blockIdx.z;
    const __nv_bfloat16* Ahi = g_Xhi + (size_t)z * XSEG;
    const __nv_bfloat16* Alo = g_Xlo + (size_t)z * XSEG;
    const __nv_bfloat16* Bhi = g_Whi + (size_t)z * WSEG;
    const __nv_bfloat16* Blo = g_Wlo + (size_t)z * WSEG;
    const float* bias; __nv_bfloat16 *Yhi, *Ylo; float sc;
    if (z == 0)      { bias = bq; Yhi = g_Qhi; Ylo = g_Qlo; sc = QSCALE; }
    else if (z == 1) { bias = bk; Yhi = g_Khi; Ylo = g_Klo; sc = 1.0f; }
    else             { bias = bv; Yhi = g_Vhi; Ylo = g_Vlo; sc = 1.0f; }
    gemm_ps_tile(Ahi, Alo, Bhi, Blo, bias, nullptr, Yhi, Ylo, sc,
                 blockIdx.y * BM, blockIdx.x * BN, sm);
}

// K3: output projection
__global__ __launch_bounds__(256, 1)
void mha_out_ps_kernel(const float* __restrict__ bo, float* __restrict__ out)
{
    extern __shared__ __align__(16) char sm[];
    gemm_ps_tile(g_AOhi, g_AOlo, g_Whi + 3 * WSEG, g_Wlo + 3 * WSEG, bo,
                 out, nullptr, nullptr, 1.0f, blockIdx.y * BM, blockIdx.x * BN, sm);
}

// ---------------------------------------------------------------------------
// K2: tensor-core flash attention (round-5 core; epilogue writes hi/lo)
// ---------------------------------------------------------------------------
__device__ __forceinline__ void issue_kv(uint32_t dstbase, int tid,
                                         const __nv_bfloat16* kh, const __nv_bfloat16* kl,
                                         const __nv_bfloat16* vh, const __nv_bfloat16* vl)
{
    #pragma unroll
    for (int l = 0; l < 4; l++) {
        int cid = tid + l * 256;
        int row = cid >> 3, c8 = cid & 7;
        uint32_t off = (uint32_t)(row * APITCH + c8 * 16);
        const size_t g = (size_t)row * 64 + c8 * 8;
        cpa16(dstbase + off,             kh + g);
        cpa16(dstbase + AHALF + off,     kl + g);
        cpa16(dstbase + 2 * AHALF + off, vh + g);
        cpa16(dstbase + 3 * AHALF + off, vl + g);
    }
}

__global__ __launch_bounds__(256, 1)
void mha_attn_tc_kernel()
{
    extern __shared__ __align__(16) char sm[];
    const uint32_t sb = smem_u32(sm);
    const int tid = threadIdx.x;
    const int lane = tid & 31;
    const int wid = tid >> 5;
    const int bh = blockIdx.y;
    const int qt = blockIdx.x;

    const size_t hbase = (size_t)bh * N_ * D_;
    {
        const __nv_bfloat16* qh = g_Qhi + hbase + (size_t)qt * 128 * D_;
        const __nv_bfloat16* ql = g_Qlo + hbase + (size_t)qt * 128 * D_;
        #pragma unroll
        for (int l = 0; l < 4; l++) {
            int cid = tid + l * 256;
            int row = cid >> 3, c8 = cid & 7;
            const size_t g = (size_t)row * 64 + c8 * 8;
            uint32_t off = (uint32_t)(row * APITCH + c8 * 16);
            *reinterpret_cast<uint4*>(sm + off) = *reinterpret_cast<const uint4*>(qh + g);
            *reinterpret_cast<uint4*>(sm + AHALF + off) = *reinterpret_cast<const uint4*>(ql + g);
        }
    }

    issue_kv(sb + 2 * AHALF, tid, g_Khi + hbase, g_Klo + hbase, g_Vhi + hbase, g_Vlo + hbase);
    cp_commit();

    float mA = -1e30f, mB = -1e30f, lA = 0.0f, lB = 0.0f;
    float oacc[8][4] = {};

    const uint32_t qrow = sb + (uint32_t)((wid * 16 + (lane & 15)) * APITCH + (lane >> 4) * 16);
    const uint32_t krow = (uint32_t)((((lane & 7) | ((lane & 16) >> 1)) * APITCH) + (lane & 8) * 2);
    const uint32_t vrow = (uint32_t)((lane & 15) * APITCH + (lane >> 4) * 16);

    for (int kt = 0; kt < 16; ++kt) {
        if (kt + 1 < 16) {
            issue_kv(sb + 2 * AHALF + (uint32_t)((kt + 1) & 1) * KV_STAGE, tid,
                     g_Khi + hbase + (size_t)(kt + 1) * 128 * D_,
                     g_Klo + hbase + (size_t)(kt + 1) * 128 * D_,
                     g_Vhi + hbase + (size_t)(kt + 1) * 128 * D_,
                     g_Vlo + hbase + (size_t)(kt + 1) * 128 * D_);
            cp_commit();
            cp_wait<1>();
        } else {
            cp_wait<0>();
        }
        __syncthreads();

        const uint32_t kb = sb + 2 * AHALF + (uint32_t)(kt & 1) * KV_STAGE;
        const uint32_t Khs = kb, Kls = kb + AHALF, Vhs = kb + 2 * AHALF, Vls = kb + 3 * AHALF;

        float sacc[16][4] = {};
        #pragma unroll
        for (int ks = 0; ks < 4; ++ks) {
            uint32_t ah[4], al[4];
            ldm_x4(ah, qrow + ks * 32);
            ldm_x4(al, qrow + AHALF + ks * 32);
            #pragma unroll
            for (int t = 0; t < 8; ++t) {
                uint32_t bh4[4], bl4[4];
                ldm_x4(bh4, Khs + krow + t * 16 * APITCH + ks * 32);
                ldm_x4(bl4, Kls + krow + t * 16 * APITCH + ks * 32);
                #pragma unroll
                for (int sub = 0; sub < 2; ++sub) {
                    float* c = sacc[t * 2 + sub];
                    mma16816(c, ah, &bh4[2 * sub]);
                    mma16816(c, ah, &bl4[2 * sub]);
                    mma16816(c, al, &bh4[2 * sub]);
                }
            }
        }

        float tA = -1e30f, tB = -1e30f;
        #pragma unroll
        for (int f = 0; f < 16; ++f) {
            tA = fmaxf(tA, fmaxf(sacc[f][0], sacc[f][1]));
            tB = fmaxf(tB, fmaxf(sacc[f][2], sacc[f][3]));
        }
        tA = fmaxf(tA, __shfl_xor_sync(0xffffffffu, tA, 1));
        tA = fmaxf(tA, __shfl_xor_sync(0xffffffffu, tA, 2));
        tB = fmaxf(tB, __shfl_xor_sync(0xffffffffu, tB, 1));
        tB = fmaxf(tB, __shfl_xor_sync(0xffffffffu, tB, 2));
        const float nmA = fmaxf(mA, tA), nmB = fmaxf(mB, tB);
        const float cA = ex2f(mA - nmA), cB = ex2f(mB - nmB);
        mA = nmA; mB = nmB;

        float psA = 0.0f, psB = 0.0f;
        #pragma unroll
        for (int f = 0; f < 16; ++f) {
            float p0 = ex2f(sacc[f][0] - mA);
            float p1 = ex2f(sacc[f][1] - mA);
            float p2 = ex2f(sacc[f][2] - mB);
            float p3 = ex2f(sacc[f][3] - mB);
            sacc[f][0] = p0; sacc[f][1] = p1; sacc[f][2] = p2; sacc[f][3] = p3;
            psA += p0 + p1; psB += p2 + p3;
        }
        lA = lA * cA + psA;
        lB = lB * cB + psB;
        #pragma unroll
        for (int nf = 0; nf < 8; ++nf) {
            oacc[nf][0] *= cA; oacc[nf][1] *= cA;
            oacc[nf][2] *= cB; oacc[nf][3] *= cB;
        }

        #pragma unroll
        for (int ks = 0; ks < 8; ++ks) {
            uint32_t phi[4], plo[4];
            split2(sacc[2 * ks][0],     sacc[2 * ks][1],     phi[0], plo[0]);
            split2(sacc[2 * ks][2],     sacc[2 * ks][3],     phi[1], plo[1]);
            split2(sacc[2 * ks + 1][0], sacc[2 * ks + 1][1], phi[2], plo[2]);
            split2(sacc[2 * ks + 1][2], sacc[2 * ks + 1][3], phi[3], plo[3]);
            const uint32_t vb = vrow + (uint32_t)(16 * ks * APITCH);
            #pragma unroll
            for (int dg = 0; dg < 4; ++dg) {
                uint32_t vh4[4], vl4[4];
                ldm_x4_t(vh4, Vhs + vb + dg * 32);
                ldm_x4_t(vl4, Vls + vb + dg * 32);
                mma16816(oacc[2 * dg],     phi, &vh4[0]);
                mma16816(oacc[2 * dg + 1], phi, &vh4[2]);
                mma16816(oacc[2 * dg],     phi, &vl4[0]);
                mma16816(oacc[2 * dg + 1], phi, &vl4[2]);
                mma16816(oacc[2 * dg],     plo, &vh4[0]);
                mma16816(oacc[2 * dg + 1], plo, &vh4[2]);
            }
        }
        __syncthreads();
    }

    lA += __shfl_xor_sync(0xffffffffu, lA, 1);
    lA += __shfl_xor_sync(0xffffffffu, lA, 2);
    lB += __shfl_xor_sync(0xffffffffu, lB, 1);
    lB += __shfl_xor_sync(0xffffffffu, lB, 2);
    const float iA = 1.0f / lA, iB = 1.0f / lB;

    const int b = bh >> 4;
    const int h = bh & 15;
    const int rowA = qt * 128 + wid * 16 + (lane >> 2);
    #pragma unroll
    for (int nf = 0; nf < 8; ++nf) {
        const int d0 = nf * 8 + (lane & 3) * 2;
        const size_t iA0 = (size_t)(b * N_ + rowA) * C_ + h * 64 + d0;
        const size_t iB0 = (size_t)(b * N_ + rowA + 8) * C_ + h * 64 + d0;
        uint32_t hi, lo;
        split2(oacc[nf][0] * iA, oacc[nf][1] * iA, hi, lo);
        *reinterpret_cast<uint32_t*>(&g_AOhi[iA0]) = hi;
        *reinterpret_cast<uint32_t*>(&g_AOlo[iA0]) = lo;
        split2(oacc[nf][2] * iB, oacc[nf][3] * iB, hi, lo);
        *reinterpret_cast<uint32_t*>(&g_AOhi[iB0]) = hi;
        *reinterpret_cast<uint32_t*>(&g_AOlo[iB0]) = lo;
    }
}

// ---------------------------------------------------------------------------
extern "C" void kernel_launch(void* const* d_in, const int* in_sizes, int n_in,
                              void* d_out, int out_size)
{
    (void)in_sizes; (void)n_in; (void)out_size;
    const float* q  = (const float*)d_in[0];
    const float* k  = (const float*)d_in[1];
    const float* v  = (const float*)d_in[2];
    const float* wq = (const float*)d_in[3];
    const float* bq = (const float*)d_in[4];
    const float* wk = (const float*)d_in[5];
    const float* bk = (const float*)d_in[6];
    const float* wv = (const float*)d_in[7];
    const float* bv = (const float*)d_in[8];
    const float* wo = (const float*)d_in[9];
    const float* bo = (const float*)d_in[10];
    float* out = (float*)d_out;

    cudaFuncSetAttribute(mha_qkv_ps_kernel,
                         cudaFuncAttributeMaxDynamicSharedMemorySize, GEMM_SMEM);
    cudaFuncSetAttribute(mha_out_ps_kernel,
                         cudaFuncAttributeMaxDynamicSharedMemorySize, GEMM_SMEM);
    cudaFuncSetAttribute(mha_attn_tc_kernel,
                         cudaFuncAttributeMaxDynamicSharedMemorySize, ATTN_SMEM);

    dim3 gsplit(XSEG / 4 / 256, 7);   // 4096 x 7
    split_convert_kernel<<<gsplit, 256>>>(q, k, v, wq, wk, wv, wo);

    dim3 gproj(C_ / BN, (B_ * N_) / BM, 3);   // 8 x 32 x 3
    mha_qkv_ps_kernel<<<gproj, 256, GEMM_SMEM>>>(bq, bk, bv);

    dim3 gattn(N_ / 128, B_ * H_);            // 16 x 32
    mha_attn_tc_kernel<<<gattn, 256, ATTN_SMEM>>>();

    dim3 gout(C_ / BN, (B_ * N_) / BM);       // 8 x 32
    mha_out_ps_kernel<<<gout, 256, GEMM_SMEM>>>(bo, out);
}

// round 7
// speedup vs baseline: 1.0660x; 1.0660x over previous
#include <cuda_runtime.h>
#include <cuda_bf16.h>
#include <cstdint>

// ---------------------------------------------------------------------------
// MultiheadAttention: b=2, n=2048, c=1024, h=16, d=64
// Round 7: occupancy push. 512-thread GEMM CTAs (4 warps/SMSP);
//          attention K-tile 64 + 2 CTAs/SM.
// ---------------------------------------------------------------------------

namespace {
constexpr int B_ = 2;
constexpr int N_ = 2048;
constexpr int C_ = 1024;
constexpr int H_ = 16;
constexpr int D_ = 64;
constexpr float QSCALE = 0.125f * 1.44269504088896340736f;  // scale * log2(e)

constexpr int XSEG = 4096 * 1024;
constexpr int WSEG = 1024 * 1024;

// GEMM tiling: 128x128 CTA tile, 16 warps (4x4), 32x32 warp tile, K-chunk 32
constexpr int BM = 128, BN = 128;
constexpr int PITCH_PS = 80;
constexpr int TILE_PS = BM * PITCH_PS;       // 10240 B
constexpr int STAGE_PS = 4 * TILE_PS;        // Ahi,Alo,Bhi,Blo
constexpr int GEMM_SMEM = 2 * STAGE_PS;      // 81920 B

// Attention tiling: q-tile 128 (8 warps x 16 rows), K-tile 64, double-buffered
constexpr int APITCH = 144;
constexpr int QHALF = 128 * APITCH;          // 18432 B (Q hi or lo)
constexpr int KTILE = 64 * APITCH;           // 9216 B  (64-row K/V hi or lo)
constexpr int KV_STAGE = 4 * KTILE;          // 36864 B
constexpr int ATTN_SMEM = 2 * QHALF + 2 * KV_STAGE;  // 110592 B -> 2 CTAs/SM
}

// Pre-split inputs/weights
__device__ __nv_bfloat16 g_Xhi[3 * XSEG];
__device__ __nv_bfloat16 g_Xlo[3 * XSEG];
__device__ __nv_bfloat16 g_Whi[4 * WSEG];
__device__ __nv_bfloat16 g_Wlo[4 * WSEG];
// Head-layout projections
__device__ __nv_bfloat16 g_Qhi[B_ * H_ * N_ * D_];
__device__ __nv_bfloat16 g_Qlo[B_ * H_ * N_ * D_];
__device__ __nv_bfloat16 g_Khi[B_ * H_ * N_ * D_];
__device__ __nv_bfloat16 g_Klo[B_ * H_ * N_ * D_];
__device__ __nv_bfloat16 g_Vhi[B_ * H_ * N_ * D_];
__device__ __nv_bfloat16 g_Vlo[B_ * H_ * N_ * D_];
// Attention output (pre-split)
__device__ __nv_bfloat16 g_AOhi[XSEG];
__device__ __nv_bfloat16 g_AOlo[XSEG];

// ---------------------------------------------------------------------------
__device__ __forceinline__ uint32_t smem_u32(const void* p) {
    uint32_t a;
    asm("{ .reg .u64 t; cvta.to.shared.u64 t, %1; cvt.u32.u64 %0, t; }" : "=r"(a) : "l"(p));
    return a;
}
__device__ __forceinline__ void ldm_x4(uint32_t* r, uint32_t addr) {
    asm volatile("ldmatrix.sync.aligned.m8n8.x4.shared.b16 {%0,%1,%2,%3}, [%4];"
                 : "=r"(r[0]), "=r"(r[1]), "=r"(r[2]), "=r"(r[3]) : "r"(addr));
}
__device__ __forceinline__ void ldm_x4_t(uint32_t* r, uint32_t addr) {
    asm volatile("ldmatrix.sync.aligned.m8n8.x4.trans.shared.b16 {%0,%1,%2,%3}, [%4];"
                 : "=r"(r[0]), "=r"(r[1]), "=r"(r[2]), "=r"(r[3]) : "r"(addr));
}
__device__ __forceinline__ void mma16816(float* c, const uint32_t* a, const uint32_t* b) {
    asm volatile(
        "mma.sync.aligned.m16n8k16.row.col.f32.bf16.bf16.f32 "
        "{%0,%1,%2,%3}, {%4,%5,%6,%7}, {%8,%9}, {%0,%1,%2,%3};"
        : "+f"(c[0]), "+f"(c[1]), "+f"(c[2]), "+f"(c[3])
        : "r"(a[0]), "r"(a[1]), "r"(a[2]), "r"(a[3]), "r"(b[0]), "r"(b[1]));
}
__device__ __forceinline__ uint32_t pack_bf16(float a, float b) {
    __nv_bfloat162 t = __floats2bfloat162_rn(a, b);
    return *reinterpret_cast<uint32_t*>(&t);
}
__device__ __forceinline__ void split2(float a, float b, uint32_t& hi, uint32_t& lo) {
    uint32_t h = pack_bf16(a, b);
    float ha = __uint_as_float(h << 16);
    float hb = __uint_as_float(h & 0xffff0000u);
    lo = pack_bf16(a - ha, b - hb);
    hi = h;
}
__device__ __forceinline__ float ex2f(float x) {
    float y;
    asm("ex2.approx.ftz.f32 %0, %1;" : "=f"(y) : "f"(x));
    return y;
}
__device__ __forceinline__ void cpa16(uint32_t dst, const void* src) {
    asm volatile("cp.async.cg.shared.global [%0], [%1], 16;" :: "r"(dst), "l"(src));
}
__device__ __forceinline__ void cp_commit() {
    asm volatile("cp.async.commit_group;" ::: "memory");
}
template <int n> __device__ __forceinline__ void cp_wait() {
    asm volatile("cp.async.wait_group %0;" :: "n"(n) : "memory");
}

// ---------------------------------------------------------------------------
// K0: fp32 -> bf16 hi/lo splitter
// ---------------------------------------------------------------------------
__global__ __launch_bounds__(256)
void split_convert_kernel(const float* __restrict__ q, const float* __restrict__ k,
                          const float* __restrict__ v,
                          const float* __restrict__ wq, const float* __restrict__ wk,
                          const float* __restrict__ wv, const float* __restrict__ wo)
{
    const int seg = blockIdx.y;
    const float* src;
    __nv_bfloat16 *hi, *lo;
    int n4;
    switch (seg) {
        case 0: src = q;  hi = g_Xhi;            lo = g_Xlo;            n4 = XSEG / 4; break;
        case 1: src = k;  hi = g_Xhi + XSEG;     lo = g_Xlo + XSEG;     n4 = XSEG / 4; break;
        case 2: src = v;  hi = g_Xhi + 2 * XSEG; lo = g_Xlo + 2 * XSEG; n4 = XSEG / 4; break;
        case 3: src = wq; hi = g_Whi;            lo = g_Wlo;            n4 = WSEG / 4; break;
        case 4: src = wk; hi = g_Whi + WSEG;     lo = g_Wlo + WSEG;     n4 = WSEG / 4; break;
        case 5: src = wv; hi = g_Whi + 2 * WSEG; lo = g_Wlo + 2 * WSEG; n4 = WSEG / 4; break;
        default: src = wo; hi = g_Whi + 3 * WSEG; lo = g_Wlo + 3 * WSEG; n4 = WSEG / 4; break;
    }
    const int idx = blockIdx.x * 256 + threadIdx.x;
    if (idx >= n4) return;
    float4 x = reinterpret_cast<const float4*>(src)[idx];
    uint32_t h01, l01, h23, l23;
    split2(x.x, x.y, h01, l01);
    split2(x.z, x.w, h23, l23);
    reinterpret_cast<uint2*>(hi)[idx] = make_uint2(h01, h23);
    reinterpret_cast<uint2*>(lo)[idx] = make_uint2(l01, l23);
}

// ---------------------------------------------------------------------------
// GEMM tile, 512 threads: 16 warps (4 M x 4 N), warp tile 32x32.
// ---------------------------------------------------------------------------
__device__ __forceinline__ void gemm_ps_tile(
    const __nv_bfloat16* __restrict__ Ahi, const __nv_bfloat16* __restrict__ Alo,
    const __nv_bfloat16* __restrict__ Bhi, const __nv_bfloat16* __restrict__ Blo,
    const float* __restrict__ bias,
    float* __restrict__ Yf32, __nv_bfloat16* __restrict__ Yhi, __nv_bfloat16* __restrict__ Ylo,
    float oscale, int rowBase, int colBase, char* sm)
{
    const int tid = threadIdx.x;
    const int lane = tid & 31;
    const int wid = tid >> 5;
    const int warp_m = wid & 3;        // 0..3 -> 32-row band
    const int warp_n = wid >> 2;       // 0..3 -> 32-col band
    const uint32_t sb = smem_u32(sm);

    float acc[2][4][4] = {};

    const uint32_t aRow = (uint32_t)(warp_m * 32 + (lane & 15)) * PITCH_PS + (uint32_t)(lane & 16);
    const uint32_t bRow = (uint32_t)(warp_n * 32 + ((lane & 7) | ((lane & 16) >> 1))) * PITCH_PS
                          + (uint32_t)((lane & 8) * 2);

    auto load_chunk = [&](int k0, int stage) {
        const uint32_t base = sb + (uint32_t)stage * STAGE_PS;
        const int r = tid >> 2, c = tid & 3;      // 512 threads: 128 rows x 4 x16B
        const uint32_t off = (uint32_t)(r * PITCH_PS + c * 16);
        const size_t ga = (size_t)(rowBase + r) * C_ + k0 + c * 8;
        const size_t gb = (size_t)(colBase + r) * C_ + k0 + c * 8;
        cpa16(base + off,               Ahi + ga);
        cpa16(base + TILE_PS + off,     Alo + ga);
        cpa16(base + 2 * TILE_PS + off, Bhi + gb);
        cpa16(base + 3 * TILE_PS + off, Blo + gb);
    };

    load_chunk(0, 0);
    cp_commit();

    for (int chunk = 0; chunk < C_ / 32; ++chunk) {
        cp_wait<0>();
        __syncthreads();
        if (chunk + 1 < C_ / 32) {
            load_chunk((chunk + 1) * 32, (chunk + 1) & 1);
            cp_commit();
        }

        const uint32_t stB = sb + (uint32_t)(chunk & 1) * STAGE_PS;
        #pragma unroll
        for (int ks = 0; ks < 2; ++ks) {
            uint32_t ah[2][4], al[2][4];
            ldm_x4(ah[0], stB + aRow + ks * 32);
            ldm_x4(ah[1], stB + aRow + 16 * PITCH_PS + ks * 32);
            ldm_x4(al[0], stB + TILE_PS + aRow + ks * 32);
            ldm_x4(al[1], stB + TILE_PS + aRow + 16 * PITCH_PS + ks * 32);
            #pragma unroll
            for (int t = 0; t < 2; ++t) {
                uint32_t bh4[4], bl4[4];
                ldm_x4(bh4, stB + 2 * TILE_PS + bRow + t * 16 * PITCH_PS + ks * 32);
                ldm_x4(bl4, stB + 3 * TILE_PS + bRow + t * 16 * PITCH_PS + ks * 32);
                #pragma unroll
                for (int f = 0; f < 2; ++f) {
                    #pragma unroll
                    for (int sub = 0; sub < 2; ++sub) {
                        float* c = acc[f][t * 2 + sub];
                        mma16816(c, ah[f], &bh4[2 * sub]);
                        mma16816(c, ah[f], &bl4[2 * sub]);
                        mma16816(c, al[f], &bh4[2 * sub]);
                    }
                }
            }
        }
        __syncthreads();
    }

    const int r = lane >> 2;
    const int cc = (lane & 3) * 2;
    #pragma unroll
    for (int f = 0; f < 2; ++f) {
        #pragma unroll
        for (int nf = 0; nf < 4; ++nf) {
            const float* c = acc[f][nf];
            const int col0 = colBase + warp_n * 32 + nf * 8 + cc;
            const int row0 = rowBase + warp_m * 32 + f * 16 + r;
            const float b0 = bias[col0], b1 = bias[col0 + 1];
            if (Yhi) {
                #pragma unroll
                for (int rr = 0; rr < 2; ++rr) {
                    const int row = row0 + rr * 8;
                    const int bb = row >> 11, i = row & (N_ - 1);
                    const int h = col0 >> 6, dd = col0 & 63;
                    const size_t idx = ((size_t)(bb * H_ + h) * N_ + i) * D_ + dd;
                    float v0 = (c[rr * 2 + 0] + b0) * oscale;
                    float v1 = (c[rr * 2 + 1] + b1) * oscale;
                    uint32_t hi, lo;
                    split2(v0, v1, hi, lo);
                    *reinterpret_cast<uint32_t*>(&Yhi[idx]) = hi;
                    *reinterpret_cast<uint32_t*>(&Ylo[idx]) = lo;
                }
            } else {
                #pragma unroll
                for (int rr = 0; rr < 2; ++rr) {
                    const int row = row0 + rr * 8;
                    float* p = &Yf32[(size_t)row * C_ + col0];
                    p[0] = c[rr * 2 + 0] + b0;
                    p[1] = c[rr * 2 + 1] + b1;
                }
            }
        }
    }
}

__global__ __launch_bounds__(512, 1)
void mha_qkv_ps_kernel(const float* __restrict__ bq, const float* __restrict__ bk,
                       const float* __restrict__ bv)
{
    extern __shared__ __align__(16) char sm[];
    const int z = blockIdx.z;
    const __nv_bfloat16* Ahi = g_Xhi + (size_t)z * XSEG;
    const __nv_bfloat16* Alo = g_Xlo + (size_t)z * XSEG;
    const __nv_bfloat16* Bhi = g_Whi + (size_t)z * WSEG;
    const __nv_bfloat16* Blo = g_Wlo + (size_t)z * WSEG;
    const float* bias; __nv_bfloat16 *Yhi, *Ylo; float sc;
    if (z == 0)      { bias = bq; Yhi = g_Qhi; Ylo = g_Qlo; sc = QSCALE; }
    else if (z == 1) { bias = bk; Yhi = g_Khi; Ylo = g_Klo; sc = 1.0f; }
    else             { bias = bv; Yhi = g_Vhi; Ylo = g_Vlo; sc = 1.0f; }
    gemm_ps_tile(Ahi, Alo, Bhi, Blo, bias, nullptr, Yhi, Ylo, sc,
                 blockIdx.y * BM, blockIdx.x * BN, sm);
}

__global__ __launch_bounds__(512, 1)
void mha_out_ps_kernel(const float* __restrict__ bo, float* __restrict__ out)
{
    extern __shared__ __align__(16) char sm[];
    gemm_ps_tile(g_AOhi, g_AOlo, g_Whi + 3 * WSEG, g_Wlo + 3 * WSEG, bo,
                 out, nullptr, nullptr, 1.0f, blockIdx.y * BM, blockIdx.x * BN, sm);
}

// ---------------------------------------------------------------------------
// K2: tensor-core flash attention; K-tile 64, 2 CTAs/SM.
// ---------------------------------------------------------------------------
__device__ __forceinline__ void issue_kv64(uint32_t dstbase, int tid,
                                           const __nv_bfloat16* kh, const __nv_bfloat16* kl,
                                           const __nv_bfloat16* vh, const __nv_bfloat16* vl)
{
    #pragma unroll
    for (int l = 0; l < 2; l++) {
        int cid = tid + l * 256;                 // 0..511
        int row = cid >> 3, c8 = cid & 7;        // 64 rows x 8 chunks
        uint32_t off = (uint32_t)(row * APITCH + c8 * 16);
        const size_t g = (size_t)row * 64 + c8 * 8;
        cpa16(dstbase + off,             kh + g);
        cpa16(dstbase + KTILE + off,     kl + g);
        cpa16(dstbase + 2 * KTILE + off, vh + g);
        cpa16(dstbase + 3 * KTILE + off, vl + g);
    }
}

__global__ __launch_bounds__(256, 2)
void mha_attn_tc_kernel()
{
    extern __shared__ __align__(16) char sm[];
    const uint32_t sb = smem_u32(sm);
    const int tid = threadIdx.x;
    const int lane = tid & 31;
    const int wid = tid >> 5;
    const int bh = blockIdx.y;
    const int qt = blockIdx.x;

    const size_t hbase = (size_t)bh * N_ * D_;
    {
        const __nv_bfloat16* qh = g_Qhi + hbase + (size_t)qt * 128 * D_;
        const __nv_bfloat16* ql = g_Qlo + hbase + (size_t)qt * 128 * D_;
        #pragma unroll
        for (int l = 0; l < 4; l++) {
            int cid = tid + l * 256;
            int row = cid >> 3, c8 = cid & 7;
            const size_t g = (size_t)row * 64 + c8 * 8;
            uint32_t off = (uint32_t)(row * APITCH + c8 * 16);
            *reinterpret_cast<uint4*>(sm + off) = *reinterpret_cast<const uint4*>(qh + g);
            *reinterpret_cast<uint4*>(sm + QHALF + off) = *reinterpret_cast<const uint4*>(ql + g);
        }
    }

    issue_kv64(sb + 2 * QHALF, tid, g_Khi + hbase, g_Klo + hbase, g_Vhi + hbase, g_Vlo + hbase);
    cp_commit();

    float mA = -1e30f, mB = -1e30f, lA = 0.0f, lB = 0.0f;
    float oacc[8][4] = {};

    const uint32_t qrow = sb + (uint32_t)((wid * 16 + (lane & 15)) * APITCH + (lane >> 4) * 16);
    const uint32_t krow = (uint32_t)((((lane & 7) | ((lane & 16) >> 1)) * APITCH) + (lane & 8) * 2);
    const uint32_t vrow = (uint32_t)((lane & 15) * APITCH + (lane >> 4) * 16);

    for (int kt = 0; kt < N_ / 64; ++kt) {
        if (kt + 1 < N_ / 64) {
            issue_kv64(sb + 2 * QHALF + (uint32_t)((kt + 1) & 1) * KV_STAGE, tid,
                       g_Khi + hbase + (size_t)(kt + 1) * 64 * D_,
                       g_Klo + hbase + (size_t)(kt + 1) * 64 * D_,
                       g_Vhi + hbase + (size_t)(kt + 1) * 64 * D_,
                       g_Vlo + hbase + (size_t)(kt + 1) * 64 * D_);
            cp_commit();
            cp_wait<1>();
        } else {
            cp_wait<0>();
        }
        __syncthreads();

        const uint32_t kb = sb + 2 * QHALF + (uint32_t)(kt & 1) * KV_STAGE;
        const uint32_t Khs = kb, Kls = kb + KTILE, Vhs = kb + 2 * KTILE, Vls = kb + 3 * KTILE;

        // S (16 q-rows x 64 keys) in log2 domain
        float sacc[8][4] = {};
        #pragma unroll
        for (int ks = 0; ks < 4; ++ks) {
            uint32_t ah[4], al[4];
            ldm_x4(ah, qrow + ks * 32);
            ldm_x4(al, qrow + QHALF + ks * 32);
            #pragma unroll
            for (int t = 0; t < 4; ++t) {
                uint32_t bh4[4], bl4[4];
                ldm_x4(bh4, Khs + krow + t * 16 * APITCH + ks * 32);
                ldm_x4(bl4, Kls + krow + t * 16 * APITCH + ks * 32);
                #pragma unroll
                for (int sub = 0; sub < 2; ++sub) {
                    float* c = sacc[t * 2 + sub];
                    mma16816(c, ah, &bh4[2 * sub]);
                    mma16816(c, ah, &bl4[2 * sub]);
                    mma16816(c, al, &bh4[2 * sub]);
                }
            }
        }

        // Online softmax (base-2)
        float tA = -1e30f, tB = -1e30f;
        #pragma unroll
        for (int f = 0; f < 8; ++f) {
            tA = fmaxf(tA, fmaxf(sacc[f][0], sacc[f][1]));
            tB = fmaxf(tB, fmaxf(sacc[f][2], sacc[f][3]));
        }
        tA = fmaxf(tA, __shfl_xor_sync(0xffffffffu, tA, 1));
        tA = fmaxf(tA, __shfl_xor_sync(0xffffffffu, tA, 2));
        tB = fmaxf(tB, __shfl_xor_sync(0xffffffffu, tB, 1));
        tB = fmaxf(tB, __shfl_xor_sync(0xffffffffu, tB, 2));
        const float nmA = fmaxf(mA, tA), nmB = fmaxf(mB, tB);
        const float cA = ex2f(mA - nmA), cB = ex2f(mB - nmB);
        mA = nmA; mB = nmB;

        float psA = 0.0f, psB = 0.0f;
        #pragma unroll
        for (int f = 0; f < 8; ++f) {
            float p0 = ex2f(sacc[f][0] - mA);
            float p1 = ex2f(sacc[f][1] - mA);
            float p2 = ex2f(sacc[f][2] - mB);
            float p3 = ex2f(sacc[f][3] - mB);
            sacc[f][0] = p0; sacc[f][1] = p1; sacc[f][2] = p2; sacc[f][3] = p3;
            psA += p0 + p1; psB += p2 + p3;
        }
        lA = lA * cA + psA;
        lB = lB * cB + psB;
        #pragma unroll
        for (int nf = 0; nf < 8; ++nf) {
            oacc[nf][0] *= cA; oacc[nf][1] *= cA;
            oacc[nf][2] *= cB; oacc[nf][3] *= cB;
        }

        // O += P @ V   (P: 16 x 64)
        #pragma unroll
        for (int ks = 0; ks < 4; ++ks) {
            uint32_t phi[4], plo[4];
            split2(sacc[2 * ks][0],     sacc[2 * ks][1],     phi[0], plo[0]);
            split2(sacc[2 * ks][2],     sacc[2 * ks][3],     phi[1], plo[1]);
            split2(sacc[2 * ks + 1][0], sacc[2 * ks + 1][1], phi[2], plo[2]);
            split2(sacc[2 * ks + 1][2], sacc[2 * ks + 1][3], phi[3], plo[3]);
            const uint32_t vb = vrow + (uint32_t)(16 * ks * APITCH);
            #pragma unroll
            for (int dg = 0; dg < 4; ++dg) {
                uint32_t vh4[4], vl4[4];
                ldm_x4_t(vh4, Vhs + vb + dg * 32);
                ldm_x4_t(vl4, Vls + vb + dg * 32);
                mma16816(oacc[2 * dg],     phi, &vh4[0]);
                mma16816(oacc[2 * dg + 1], phi, &vh4[2]);
                mma16816(oacc[2 * dg],     phi, &vl4[0]);
                mma16816(oacc[2 * dg + 1], phi, &vl4[2]);
                mma16816(oacc[2 * dg],     plo, &vh4[0]);
                mma16816(oacc[2 * dg + 1], plo, &vh4[2]);
            }
        }
        __syncthreads();
    }

    lA += __shfl_xor_sync(0xffffffffu, lA, 1);
    lA += __shfl_xor_sync(0xffffffffu, lA, 2);
    lB += __shfl_xor_sync(0xffffffffu, lB, 1);
    lB += __shfl_xor_sync(0xffffffffu, lB, 2);
    const float iA = 1.0f / lA, iB = 1.0f / lB;

    const int b = bh >> 4;
    const int h = bh & 15;
    const int rowA = qt * 128 + wid * 16 + (lane >> 2);
    #pragma unroll
    for (int nf = 0; nf < 8; ++nf) {
        const int d0 = nf * 8 + (lane & 3) * 2;
        const size_t iA0 = (size_t)(b * N_ + rowA) * C_ + h * 64 + d0;
        const size_t iB0 = (size_t)(b * N_ + rowA + 8) * C_ + h * 64 + d0;
        uint32_t hi, lo;
        split2(oacc[nf][0] * iA, oacc[nf][1] * iA, hi, lo);
        *reinterpret_cast<uint32_t*>(&g_AOhi[iA0]) = hi;
        *reinterpret_cast<uint32_t*>(&g_AOlo[iA0]) = lo;
        split2(oacc[nf][2] * iB, oacc[nf][3] * iB, hi, lo);
        *reinterpret_cast<uint32_t*>(&g_AOhi[iB0]) = hi;
        *reinterpret_cast<uint32_t*>(&g_AOlo[iB0]) = lo;
    }
}

// ---------------------------------------------------------------------------
extern "C" void kernel_launch(void* const* d_in, const int* in_sizes, int n_in,
                              void* d_out, int out_size)
{
    (void)in_sizes; (void)n_in; (void)out_size;
    const float* q  = (const float*)d_in[0];
    const float* k  = (const float*)d_in[1];
    const float* v  = (const float*)d_in[2];
    const float* wq = (const float*)d_in[3];
    const float* bq = (const float*)d_in[4];
    const float* wk = (const float*)d_in[5];
    const float* bk = (const float*)d_in[6];
    const float* wv = (const float*)d_in[7];
    const float* bv = (const float*)d_in[8];
    const float* wo = (const float*)d_in[9];
    const float* bo = (const float*)d_in[10];
    float* out = (float*)d_out;

    cudaFuncSetAttribute(mha_qkv_ps_kernel,
                         cudaFuncAttributeMaxDynamicSharedMemorySize, GEMM_SMEM);
    cudaFuncSetAttribute(mha_out_ps_kernel,
                         cudaFuncAttributeMaxDynamicSharedMemorySize, GEMM_SMEM);
    cudaFuncSetAttribute(mha_attn_tc_kernel,
                         cudaFuncAttributeMaxDynamicSharedMemorySize, ATTN_SMEM);

    dim3 gsplit(XSEG / 4 / 256, 7);
    split_convert_kernel<<<gsplit, 256>>>(q, k, v, wq, wk, wv, wo);

    dim3 gproj(C_ / BN, (B_ * N_) / BM, 3);   // 8 x 32 x 3
    mha_qkv_ps_kernel<<<gproj, 512, GEMM_SMEM>>>(bq, bk, bv);

    dim3 gattn(N_ / 128, B_ * H_);            // 16 x 32
    mha_attn_tc_kernel<<<gattn, 256, ATTN_SMEM>>>();

    dim3 gout(C_ / BN, (B_ * N_) / BM);       // 8 x 32
    mha_out_ps_kernel<<<gout, 512, GEMM_SMEM>>>(bo, out);
}

// round 8
// speedup vs baseline: 1.0721x; 1.0058x over previous
#include <cuda_runtime.h>
#include <cuda_bf16.h>
#include <cstdint>

// ---------------------------------------------------------------------------
// MultiheadAttention: b=2, n=2048, c=1024, h=16, d=64
// Round 8: 4-stage GEMM pipeline, single barrier per chunk, term-major MMAs;
//          attention single barrier per kt.
// ---------------------------------------------------------------------------

namespace {
constexpr int B_ = 2;
constexpr int N_ = 2048;
constexpr int C_ = 1024;
constexpr int H_ = 16;
constexpr int D_ = 64;
constexpr float QSCALE = 0.125f * 1.44269504088896340736f;  // scale * log2(e)

constexpr int XSEG = 4096 * 1024;
constexpr int WSEG = 1024 * 1024;

// GEMM tiling: 128x128 CTA tile, 16 warps (4x4), 32x32 warp tile, K-chunk 32
constexpr int BM = 128, BN = 128;
constexpr int PITCH_PS = 80;
constexpr int TILE_PS = BM * PITCH_PS;       // 10240 B
constexpr int STAGE_PS = 4 * TILE_PS;        // Ahi,Alo,Bhi,Blo = 40960 B
constexpr int NSTAGE = 4;
constexpr int GEMM_SMEM = NSTAGE * STAGE_PS; // 163840 B

// Attention tiling: q-tile 128 (8 warps x 16 rows), K-tile 64, double-buffered
constexpr int APITCH = 144;
constexpr int QHALF = 128 * APITCH;          // 18432 B
constexpr int KTILE = 64 * APITCH;           // 9216 B
constexpr int KV_STAGE = 4 * KTILE;          // 36864 B
constexpr int ATTN_SMEM = 2 * QHALF + 2 * KV_STAGE;  // 110592 B -> 2 CTAs/SM
}

// Pre-split inputs/weights
__device__ __nv_bfloat16 g_Xhi[3 * XSEG];
__device__ __nv_bfloat16 g_Xlo[3 * XSEG];
__device__ __nv_bfloat16 g_Whi[4 * WSEG];
__device__ __nv_bfloat16 g_Wlo[4 * WSEG];
// Head-layout projections
__device__ __nv_bfloat16 g_Qhi[B_ * H_ * N_ * D_];
__device__ __nv_bfloat16 g_Qlo[B_ * H_ * N_ * D_];
__device__ __nv_bfloat16 g_Khi[B_ * H_ * N_ * D_];
__device__ __nv_bfloat16 g_Klo[B_ * H_ * N_ * D_];
__device__ __nv_bfloat16 g_Vhi[B_ * H_ * N_ * D_];
__device__ __nv_bfloat16 g_Vlo[B_ * H_ * N_ * D_];
// Attention output (pre-split)
__device__ __nv_bfloat16 g_AOhi[XSEG];
__device__ __nv_bfloat16 g_AOlo[XSEG];

// ---------------------------------------------------------------------------
__device__ __forceinline__ uint32_t smem_u32(const void* p) {
    uint32_t a;
    asm("{ .reg .u64 t; cvta.to.shared.u64 t, %1; cvt.u32.u64 %0, t; }" : "=r"(a) : "l"(p));
    return a;
}
__device__ __forceinline__ void ldm_x4(uint32_t* r, uint32_t addr) {
    asm volatile("ldmatrix.sync.aligned.m8n8.x4.shared.b16 {%0,%1,%2,%3}, [%4];"
                 : "=r"(r[0]), "=r"(r[1]), "=r"(r[2]), "=r"(r[3]) : "r"(addr));
}
__device__ __forceinline__ void ldm_x4_t(uint32_t* r, uint32_t addr) {
    asm volatile("ldmatrix.sync.aligned.m8n8.x4.trans.shared.b16 {%0,%1,%2,%3}, [%4];"
                 : "=r"(r[0]), "=r"(r[1]), "=r"(r[2]), "=r"(r[3]) : "r"(addr));
}
__device__ __forceinline__ void mma16816(float* c, const uint32_t* a, const uint32_t* b) {
    asm volatile(
        "mma.sync.aligned.m16n8k16.row.col.f32.bf16.bf16.f32 "
        "{%0,%1,%2,%3}, {%4,%5,%6,%7}, {%8,%9}, {%0,%1,%2,%3};"
        : "+f"(c[0]), "+f"(c[1]), "+f"(c[2]), "+f"(c[3])
        : "r"(a[0]), "r"(a[1]), "r"(a[2]), "r"(a[3]), "r"(b[0]), "r"(b[1]));
}
__device__ __forceinline__ uint32_t pack_bf16(float a, float b) {
    __nv_bfloat162 t = __floats2bfloat162_rn(a, b);
    return *reinterpret_cast<uint32_t*>(&t);
}
__device__ __forceinline__ void split2(float a, float b, uint32_t& hi, uint32_t& lo) {
    uint32_t h = pack_bf16(a, b);
    float ha = __uint_as_float(h << 16);
    float hb = __uint_as_float(h & 0xffff0000u);
    lo = pack_bf16(a - ha, b - hb);
    hi = h;
}
__device__ __forceinline__ float ex2f(float x) {
    float y;
    asm("ex2.approx.ftz.f32 %0, %1;" : "=f"(y) : "f"(x));
    return y;
}
__device__ __forceinline__ void cpa16(uint32_t dst, const void* src) {
    asm volatile("cp.async.cg.shared.global [%0], [%1], 16;" :: "r"(dst), "l"(src));
}
__device__ __forceinline__ void cp_commit() {
    asm volatile("cp.async.commit_group;" ::: "memory");
}
template <int n> __device__ __forceinline__ void cp_wait() {
    asm volatile("cp.async.wait_group %0;" :: "n"(n) : "memory");
}

// ---------------------------------------------------------------------------
// K0: fp32 -> bf16 hi/lo splitter
// ---------------------------------------------------------------------------
__global__ __launch_bounds__(256)
void split_convert_kernel(const float* __restrict__ q, const float* __restrict__ k,
                          const float* __restrict__ v,
                          const float* __restrict__ wq, const float* __restrict__ wk,
                          const float* __restrict__ wv, const float* __restrict__ wo)
{
    const int seg = blockIdx.y;
    const float* src;
    __nv_bfloat16 *hi, *lo;
    int n4;
    switch (seg) {
        case 0: src = q;  hi = g_Xhi;            lo = g_Xlo;            n4 = XSEG / 4; break;
        case 1: src = k;  hi = g_Xhi + XSEG;     lo = g_Xlo + XSEG;     n4 = XSEG / 4; break;
        case 2: src = v;  hi = g_Xhi + 2 * XSEG; lo = g_Xlo + 2 * XSEG; n4 = XSEG / 4; break;
        case 3: src = wq; hi = g_Whi;            lo = g_Wlo;            n4 = WSEG / 4; break;
        case 4: src = wk; hi = g_Whi + WSEG;     lo = g_Wlo + WSEG;     n4 = WSEG / 4; break;
        case 5: src = wv; hi = g_Whi + 2 * WSEG; lo = g_Wlo + 2 * WSEG; n4 = WSEG / 4; break;
        default: src = wo; hi = g_Whi + 3 * WSEG; lo = g_Wlo + 3 * WSEG; n4 = WSEG / 4; break;
    }
    const int idx = blockIdx.x * 256 + threadIdx.x;
    if (idx >= n4) return;
    float4 x = reinterpret_cast<const float4*>(src)[idx];
    uint32_t h01, l01, h23, l23;
    split2(x.x, x.y, h01, l01);
    split2(x.z, x.w, h23, l23);
    reinterpret_cast<uint2*>(hi)[idx] = make_uint2(h01, h23);
    reinterpret_cast<uint2*>(lo)[idx] = make_uint2(l01, l23);
}

// ---------------------------------------------------------------------------
// GEMM tile, 512 threads, 4-stage pipeline, one barrier per chunk.
// ---------------------------------------------------------------------------
__device__ __forceinline__ void gemm_ps_tile(
    const __nv_bfloat16* __restrict__ Ahi, const __nv_bfloat16* __restrict__ Alo,
    const __nv_bfloat16* __restrict__ Bhi, const __nv_bfloat16* __restrict__ Blo,
    const float* __restrict__ bias,
    float* __restrict__ Yf32, __nv_bfloat16* __restrict__ Yhi, __nv_bfloat16* __restrict__ Ylo,
    float oscale, int rowBase, int colBase, char* sm)
{
    const int tid = threadIdx.x;
    const int lane = tid & 31;
    const int wid = tid >> 5;
    const int warp_m = wid & 3;
    const int warp_n = wid >> 2;
    const uint32_t sb = smem_u32(sm);

    float acc[2][4][4] = {};

    const uint32_t aRow = (uint32_t)(warp_m * 32 + (lane & 15)) * PITCH_PS + (uint32_t)(lane & 16);
    const uint32_t bRow = (uint32_t)(warp_n * 32 + ((lane & 7) | ((lane & 16) >> 1))) * PITCH_PS
                          + (uint32_t)((lane & 8) * 2);

    auto load_chunk = [&](int k0, int stage) {
        const uint32_t base = sb + (uint32_t)stage * STAGE_PS;
        const int r = tid >> 2, c = tid & 3;
        const uint32_t off = (uint32_t)(r * PITCH_PS + c * 16);
        const size_t ga = (size_t)(rowBase + r) * C_ + k0 + c * 8;
        const size_t gb = (size_t)(colBase + r) * C_ + k0 + c * 8;
        cpa16(base + off,               Ahi + ga);
        cpa16(base + TILE_PS + off,     Alo + ga);
        cpa16(base + 2 * TILE_PS + off, Bhi + gb);
        cpa16(base + 3 * TILE_PS + off, Blo + gb);
    };

    // Prologue: stages 0,1,2 in flight
    load_chunk(0, 0);  cp_commit();
    load_chunk(32, 1); cp_commit();
    load_chunk(64, 2); cp_commit();

    constexpr int NCHUNK = C_ / 32;   // 32
    for (int chunk = 0; chunk < NCHUNK; ++chunk) {
        cp_wait<2>();        // stage (chunk & 3) resident
        __syncthreads();     // all warps done with chunk-1 -> its stage reusable

        if (chunk + 3 < NCHUNK) load_chunk((chunk + 3) * 32, (chunk + 3) & 3);
        cp_commit();         // always commit: keeps one group per iteration

        const uint32_t stB = sb + (uint32_t)(chunk & 3) * STAGE_PS;
        #pragma unroll
        for (int ks = 0; ks < 2; ++ks) {
            uint32_t ah[2][4], al[2][4], bh[2][4], bl[2][4];
            ldm_x4(ah[0], stB + aRow + ks * 32);
            ldm_x4(ah[1], stB + aRow + 16 * PITCH_PS + ks * 32);
            ldm_x4(al[0], stB + TILE_PS + aRow + ks * 32);
            ldm_x4(al[1], stB + TILE_PS + aRow + 16 * PITCH_PS + ks * 32);
            ldm_x4(bh[0], stB + 2 * TILE_PS + bRow + ks * 32);
            ldm_x4(bh[1], stB + 2 * TILE_PS + bRow + 16 * PITCH_PS + ks * 32);
            ldm_x4(bl[0], stB + 3 * TILE_PS + bRow + ks * 32);
            ldm_x4(bl[1], stB + 3 * TILE_PS + bRow + 16 * PITCH_PS + ks * 32);

            // term-major: hi*hi, then hi*lo, then lo*hi (RAW distance = 8 MMAs)
            #pragma unroll
            for (int t = 0; t < 2; ++t)
                #pragma unroll
                for (int f = 0; f < 2; ++f)
                    #pragma unroll
                    for (int sub = 0; sub < 2; ++sub)
                        mma16816(acc[f][t * 2 + sub], ah[f], &bh[t][2 * sub]);
            #pragma unroll
            for (int t = 0; t < 2; ++t)
                #pragma unroll
                for (int f = 0; f < 2; ++f)
                    #pragma unroll
                    for (int sub = 0; sub < 2; ++sub)
                        mma16816(acc[f][t * 2 + sub], ah[f], &bl[t][2 * sub]);
            #pragma unroll
            for (int t = 0; t < 2; ++t)
                #pragma unroll
                for (int f = 0; f < 2; ++f)
                    #pragma unroll
                    for (int sub = 0; sub < 2; ++sub)
                        mma16816(acc[f][t * 2 + sub], al[f], &bh[t][2 * sub]);
        }
    }

    const int r = lane >> 2;
    const int cc = (lane & 3) * 2;
    #pragma unroll
    for (int f = 0; f < 2; ++f) {
        #pragma unroll
        for (int nf = 0; nf < 4; ++nf) {
            const float* c = acc[f][nf];
            const int col0 = colBase + warp_n * 32 + nf * 8 + cc;
            const int row0 = rowBase + warp_m * 32 + f * 16 + r;
            const float b0 = bias[col0], b1 = bias[col0 + 1];
            if (Yhi) {
                #pragma unroll
                for (int rr = 0; rr < 2; ++rr) {
                    const int row = row0 + rr * 8;
                    const int bb = row >> 11, i = row & (N_ - 1);
                    const int h = col0 >> 6, dd = col0 & 63;
                    const size_t idx = ((size_t)(bb * H_ + h) * N_ + i) * D_ + dd;
                    float v0 = (c[rr * 2 + 0] + b0) * oscale;
                    float v1 = (c[rr * 2 + 1] + b1) * oscale;
                    uint32_t hi, lo;
                    split2(v0, v1, hi, lo);
                    *reinterpret_cast<uint32_t*>(&Yhi[idx]) = hi;
                    *reinterpret_cast<uint32_t*>(&Ylo[idx]) = lo;
                }
            } else {
                #pragma unroll
                for (int rr = 0; rr < 2; ++rr) {
                    const int row = row0 + rr * 8;
                    float* p = &Yf32[(size_t)row * C_ + col0];
                    p[0] = c[rr * 2 + 0] + b0;
                    p[1] = c[rr * 2 + 1] + b1;
                }
            }
        }
    }
}

__global__ __launch_bounds__(512, 1)
void mha_qkv_ps_kernel(const float* __restrict__ bq, const float* __restrict__ bk,
                       const float* __restrict__ bv)
{
    extern __shared__ __align__(16) char sm[];
    const int z = blockIdx.z;
    const __nv_bfloat16* Ahi = g_Xhi + (size_t)z * XSEG;
    const __nv_bfloat16* Alo = g_Xlo + (size_t)z * XSEG;
    const __nv_bfloat16* Bhi = g_Whi + (size_t)z * WSEG;
    const __nv_bfloat16* Blo = g_Wlo + (size_t)z * WSEG;
    const float* bias; __nv_bfloat16 *Yhi, *Ylo; float sc;
    if (z == 0)      { bias = bq; Yhi = g_Qhi; Ylo = g_Qlo; sc = QSCALE; }
    else if (z == 1) { bias = bk; Yhi = g_Khi; Ylo = g_Klo; sc = 1.0f; }
    else             { bias = bv; Yhi = g_Vhi; Ylo = g_Vlo; sc = 1.0f; }
    gemm_ps_tile(Ahi, Alo, Bhi, Blo, bias, nullptr, Yhi, Ylo, sc,
                 blockIdx.y * BM, blockIdx.x * BN, sm);
}

__global__ __launch_bounds__(512, 1)
void mha_out_ps_kernel(const float* __restrict__ bo, float* __restrict__ out)
{
    extern __shared__ __align__(16) char sm[];
    gemm_ps_tile(g_AOhi, g_AOlo, g_Whi + 3 * WSEG, g_Wlo + 3 * WSEG, bo,
                 out, nullptr, nullptr, 1.0f, blockIdx.y * BM, blockIdx.x * BN, sm);
}

// ---------------------------------------------------------------------------
// K2: tensor-core flash attention; K-tile 64, 2 CTAs/SM, 1 barrier per kt.
// ---------------------------------------------------------------------------
__device__ __forceinline__ void issue_kv64(uint32_t dstbase, int tid,
                                           const __nv_bfloat16* kh, const __nv_bfloat16* kl,
                                           const __nv_bfloat16* vh, const __nv_bfloat16* vl)
{
    #pragma unroll
    for (int l = 0; l < 2; l++) {
        int cid = tid + l * 256;
        int row = cid >> 3, c8 = cid & 7;
        uint32_t off = (uint32_t)(row * APITCH + c8 * 16);
        const size_t g = (size_t)row * 64 + c8 * 8;
        cpa16(dstbase + off,             kh + g);
        cpa16(dstbase + KTILE + off,     kl + g);
        cpa16(dstbase + 2 * KTILE + off, vh + g);
        cpa16(dstbase + 3 * KTILE + off, vl + g);
    }
}

__global__ __launch_bounds__(256, 2)
void mha_attn_tc_kernel()
{
    extern __shared__ __align__(16) char sm[];
    const uint32_t sb = smem_u32(sm);
    const int tid = threadIdx.x;
    const int lane = tid & 31;
    const int wid = tid >> 5;
    const int bh = blockIdx.y;
    const int qt = blockIdx.x;

    const size_t hbase = (size_t)bh * N_ * D_;
    {
        const __nv_bfloat16* qh = g_Qhi + hbase + (size_t)qt * 128 * D_;
        const __nv_bfloat16* ql = g_Qlo + hbase + (size_t)qt * 128 * D_;
        #pragma unroll
        for (int l = 0; l < 4; l++) {
            int cid = tid + l * 256;
            int row = cid >> 3, c8 = cid & 7;
            const size_t g = (size_t)row * 64 + c8 * 8;
            uint32_t off = (uint32_t)(row * APITCH + c8 * 16);
            *reinterpret_cast<uint4*>(sm + off) = *reinterpret_cast<const uint4*>(qh + g);
            *reinterpret_cast<uint4*>(sm + QHALF + off) = *reinterpret_cast<const uint4*>(ql + g);
        }
    }

    issue_kv64(sb + 2 * QHALF, tid, g_Khi + hbase, g_Klo + hbase, g_Vhi + hbase, g_Vlo + hbase);
    cp_commit();

    float mA = -1e30f, mB = -1e30f, lA = 0.0f, lB = 0.0f;
    float oacc[8][4] = {};

    const uint32_t qrow = sb + (uint32_t)((wid * 16 + (lane & 15)) * APITCH + (lane >> 4) * 16);
    const uint32_t krow = (uint32_t)((((lane & 7) | ((lane & 16) >> 1)) * APITCH) + (lane & 8) * 2);
    const uint32_t vrow = (uint32_t)((lane & 15) * APITCH + (lane >> 4) * 16);

    constexpr int NKT = N_ / 64;   // 32
    for (int kt = 0; kt < NKT; ++kt) {
        cp_wait<0>();        // stage kt resident (only its group is in flight)
        __syncthreads();     // all warps done with kt-1 -> other stage reusable
        if (kt + 1 < NKT) {
            issue_kv64(sb + 2 * QHALF + (uint32_t)((kt + 1) & 1) * KV_STAGE, tid,
                       g_Khi + hbase + (size_t)(kt + 1) * 64 * D_,
                       g_Klo + hbase + (size_t)(kt + 1) * 64 * D_,
                       g_Vhi + hbase + (size_t)(kt + 1) * 64 * D_,
                       g_Vlo + hbase + (size_t)(kt + 1) * 64 * D_);
        }
        cp_commit();

        const uint32_t kb = sb + 2 * QHALF + (uint32_t)(kt & 1) * KV_STAGE;
        const uint32_t Khs = kb, Kls = kb + KTILE, Vhs = kb + 2 * KTILE, Vls = kb + 3 * KTILE;

        // S (16 q-rows x 64 keys), log2 domain
        float sacc[8][4] = {};
        #pragma unroll
        for (int ks = 0; ks < 4; ++ks) {
            uint32_t ah[4], al[4];
            ldm_x4(ah, qrow + ks * 32);
            ldm_x4(al, qrow + QHALF + ks * 32);
            #pragma unroll
            for (int t = 0; t < 4; ++t) {
                uint32_t bh4[4], bl4[4];
                ldm_x4(bh4, Khs + krow + t * 16 * APITCH + ks * 32);
                ldm_x4(bl4, Kls + krow + t * 16 * APITCH + ks * 32);
                // term-major within t: RAW distance 2
                mma16816(sacc[t * 2 + 0], ah, &bh4[0]);
                mma16816(sacc[t * 2 + 1], ah, &bh4[2]);
                mma16816(sacc[t * 2 + 0], ah, &bl4[0]);
                mma16816(sacc[t * 2 + 1], ah, &bl4[2]);
                mma16816(sacc[t * 2 + 0], al, &bh4[0]);
                mma16816(sacc[t * 2 + 1], al, &bh4[2]);
            }
        }

        // Online softmax (base-2)
        float tA = -1e30f, tB = -1e30f;
        #pragma unroll
        for (int f = 0; f < 8; ++f) {
            tA = fmaxf(tA, fmaxf(sacc[f][0], sacc[f][1]));
            tB = fmaxf(tB, fmaxf(sacc[f][2], sacc[f][3]));
        }
        tA = fmaxf(tA, __shfl_xor_sync(0xffffffffu, tA, 1));
        tA = fmaxf(tA, __shfl_xor_sync(0xffffffffu, tA, 2));
        tB = fmaxf(tB, __shfl_xor_sync(0xffffffffu, tB, 1));
        tB = fmaxf(tB, __shfl_xor_sync(0xffffffffu, tB, 2));
        const float nmA = fmaxf(mA, tA), nmB = fmaxf(mB, tB);
        const float cA = ex2f(mA - nmA), cB = ex2f(mB - nmB);
        mA = nmA; mB = nmB;

        float psA = 0.0f, psB = 0.0f;
        #pragma unroll
        for (int f = 0; f < 8; ++f) {
            float p0 = ex2f(sacc[f][0] - mA);
            float p1 = ex2f(sacc[f][1] - mA);
            float p2 = ex2f(sacc[f][2] - mB);
            float p3 = ex2f(sacc[f][3] - mB);
            sacc[f][0] = p0; sacc[f][1] = p1; sacc[f][2] = p2; sacc[f][3] = p3;
            psA += p0 + p1; psB += p2 + p3;
        }
        lA = lA * cA + psA;
        lB = lB * cB + psB;
        #pragma unroll
        for (int nf = 0; nf < 8; ++nf) {
            oacc[nf][0] *= cA; oacc[nf][1] *= cA;
            oacc[nf][2] *= cB; oacc[nf][3] *= cB;
        }

        // O += P @ V  (P: 16 x 64)
        #pragma unroll
        for (int ks = 0; ks < 4; ++ks) {
            uint32_t phi[4], plo[4];
            split2(sacc[2 * ks][0],     sacc[2 * ks][1],     phi[0], plo[0]);
            split2(sacc[2 * ks][2],     sacc[2 * ks][3],     phi[1], plo[1]);
            split2(sacc[2 * ks + 1][0], sacc[2 * ks + 1][1], phi[2], plo[2]);
            split2(sacc[2 * ks + 1][2], sacc[2 * ks + 1][3], phi[3], plo[3]);
            const uint32_t vb = vrow + (uint32_t)(16 * ks * APITCH);
            #pragma unroll
            for (int dg = 0; dg < 4; ++dg) {
                uint32_t vh4[4], vl4[4];
                ldm_x4_t(vh4, Vhs + vb + dg * 32);
                ldm_x4_t(vl4, Vls + vb + dg * 32);
                mma16816(oacc[2 * dg],     phi, &vh4[0]);
                mma16816(oacc[2 * dg + 1], phi, &vh4[2]);
                mma16816(oacc[2 * dg],     phi, &vl4[0]);
                mma16816(oacc[2 * dg + 1], phi, &vl4[2]);
                mma16816(oacc[2 * dg],     plo, &vh4[0]);
                mma16816(oacc[2 * dg + 1], plo, &vh4[2]);
            }
        }
    }

    lA += __shfl_xor_sync(0xffffffffu, lA, 1);
    lA += __shfl_xor_sync(0xffffffffu, lA, 2);
    lB += __shfl_xor_sync(0xffffffffu, lB, 1);
    lB += __shfl_xor_sync(0xffffffffu, lB, 2);
    const float iA = 1.0f / lA, iB = 1.0f / lB;

    const int b = bh >> 4;
    const int h = bh & 15;
    const int rowA = qt * 128 + wid * 16 + (lane >> 2);
    #pragma unroll
    for (int nf = 0; nf < 8; ++nf) {
        const int d0 = nf * 8 + (lane & 3) * 2;
        const size_t iA0 = (size_t)(b * N_ + rowA) * C_ + h * 64 + d0;
        const size_t iB0 = (size_t)(b * N_ + rowA + 8) * C_ + h * 64 + d0;
        uint32_t hi, lo;
        split2(oacc[nf][0] * iA, oacc[nf][1] * iA, hi, lo);
        *reinterpret_cast<uint32_t*>(&g_AOhi[iA0]) = hi;
        *reinterpret_cast<uint32_t*>(&g_AOlo[iA0]) = lo;
        split2(oacc[nf][2] * iB, oacc[nf][3] * iB, hi, lo);
        *reinterpret_cast<uint32_t*>(&g_AOhi[iB0]) = hi;
        *reinterpret_cast<uint32_t*>(&g_AOlo[iB0]) = lo;
    }
}

// ---------------------------------------------------------------------------
extern "C" void kernel_launch(void* const* d_in, const int* in_sizes, int n_in,
                              void* d_out, int out_size)
{
    (void)in_sizes; (void)n_in; (void)out_size;
    const float* q  = (const float*)d_in[0];
    const float* k  = (const float*)d_in[1];
    const float* v  = (const float*)d_in[2];
    const float* wq = (const float*)d_in[3];
    const float* bq = (const float*)d_in[4];
    const float* wk = (const float*)d_in[5];
    const float* bk = (const float*)d_in[6];
    const float* wv = (const float*)d_in[7];
    const float* bv = (const float*)d_in[8];
    const float* wo = (const float*)d_in[9];
    const float* bo = (const float*)d_in[10];
    float* out = (float*)d_out;

    cudaFuncSetAttribute(mha_qkv_ps_kernel,
                         cudaFuncAttributeMaxDynamicSharedMemorySize, GEMM_SMEM);
    cudaFuncSetAttribute(mha_out_ps_kernel,
                         cudaFuncAttributeMaxDynamicSharedMemorySize, GEMM_SMEM);
    cudaFuncSetAttribute(mha_attn_tc_kernel,
                         cudaFuncAttributeMaxDynamicSharedMemorySize, ATTN_SMEM);

    dim3 gsplit(XSEG / 4 / 256, 7);
    split_convert_kernel<<<gsplit, 256>>>(q, k, v, wq, wk, wv, wo);

    dim3 gproj(C_ / BN, (B_ * N_) / BM, 3);   // 8 x 32 x 3
    mha_qkv_ps_kernel<<<gproj, 512, GEMM_SMEM>>>(bq, bk, bv);

    dim3 gattn(N_ / 128, B_ * H_);            // 16 x 32
    mha_attn_tc_kernel<<<gattn, 256, ATTN_SMEM>>>();

    dim3 gout(C_ / BN, (B_ * N_) / BM);       // 8 x 32
    mha_out_ps_kernel<<<gout, 512, GEMM_SMEM>>>(bo, out);
}

// round 9
// speedup vs baseline: 1.0928x; 1.0193x over previous
#include <cuda_runtime.h>
#include <cuda_bf16.h>
#include <cstdint>

// ---------------------------------------------------------------------------
// MultiheadAttention: b=2, n=2048, c=1024, h=16, d=64
// Round 9: GEMMs restructured to 2 CTAs/SM (CTA tile 128x64, 8 warps, 2-stage)
//          -- cross-CTA overlap hides barrier/load phases (attention pattern).
// ---------------------------------------------------------------------------

namespace {
constexpr int B_ = 2;
constexpr int N_ = 2048;
constexpr int C_ = 1024;
constexpr int H_ = 16;
constexpr int D_ = 64;
constexpr float QSCALE = 0.125f * 1.44269504088896340736f;  // scale * log2(e)

constexpr int XSEG = 4096 * 1024;
constexpr int WSEG = 1024 * 1024;

// GEMM tiling: CTA tile 128(M) x 64(N), 8 warps (4Mx2N), warp tile 32x32,
// K-chunk 32, 2 stages, 2 CTAs/SM.
constexpr int BM = 128, BN = 64;
constexpr int PITCH_PS = 80;                   // 64B data + 16B pad
constexpr int TILE_A = BM * PITCH_PS;          // 10240 B (128 rows)
constexpr int TILE_B2 = BN * PITCH_PS;         // 5120 B  (64 rows)
constexpr int STAGE_PS = 2 * TILE_A + 2 * TILE_B2;   // Ahi,Alo,Bhi,Blo = 30720
constexpr int GEMM_SMEM = 2 * STAGE_PS;        // 61440 B -> 2 CTAs/SM

// Attention tiling (round-8 proven)
constexpr int APITCH = 144;
constexpr int QHALF = 128 * APITCH;
constexpr int KTILE = 64 * APITCH;
constexpr int KV_STAGE = 4 * KTILE;
constexpr int ATTN_SMEM = 2 * QHALF + 2 * KV_STAGE;  // 110592 B -> 2 CTAs/SM
}

// Pre-split inputs/weights
__device__ __nv_bfloat16 g_Xhi[3 * XSEG];
__device__ __nv_bfloat16 g_Xlo[3 * XSEG];
__device__ __nv_bfloat16 g_Whi[4 * WSEG];
__device__ __nv_bfloat16 g_Wlo[4 * WSEG];
// Head-layout projections
__device__ __nv_bfloat16 g_Qhi[B_ * H_ * N_ * D_];
__device__ __nv_bfloat16 g_Qlo[B_ * H_ * N_ * D_];
__device__ __nv_bfloat16 g_Khi[B_ * H_ * N_ * D_];
__device__ __nv_bfloat16 g_Klo[B_ * H_ * N_ * D_];
__device__ __nv_bfloat16 g_Vhi[B_ * H_ * N_ * D_];
__device__ __nv_bfloat16 g_Vlo[B_ * H_ * N_ * D_];
// Attention output (pre-split)
__device__ __nv_bfloat16 g_AOhi[XSEG];
__device__ __nv_bfloat16 g_AOlo[XSEG];

// ---------------------------------------------------------------------------
__device__ __forceinline__ uint32_t smem_u32(const void* p) {
    uint32_t a;
    asm("{ .reg .u64 t; cvta.to.shared.u64 t, %1; cvt.u32.u64 %0, t; }" : "=r"(a) : "l"(p));
    return a;
}
__device__ __forceinline__ void ldm_x4(uint32_t* r, uint32_t addr) {
    asm volatile("ldmatrix.sync.aligned.m8n8.x4.shared.b16 {%0,%1,%2,%3}, [%4];"
                 : "=r"(r[0]), "=r"(r[1]), "=r"(r[2]), "=r"(r[3]) : "r"(addr));
}
__device__ __forceinline__ void ldm_x4_t(uint32_t* r, uint32_t addr) {
    asm volatile("ldmatrix.sync.aligned.m8n8.x4.trans.shared.b16 {%0,%1,%2,%3}, [%4];"
                 : "=r"(r[0]), "=r"(r[1]), "=r"(r[2]), "=r"(r[3]) : "r"(addr));
}
__device__ __forceinline__ void mma16816(float* c, const uint32_t* a, const uint32_t* b) {
    asm volatile(
        "mma.sync.aligned.m16n8k16.row.col.f32.bf16.bf16.f32 "
        "{%0,%1,%2,%3}, {%4,%5,%6,%7}, {%8,%9}, {%0,%1,%2,%3};"
        : "+f"(c[0]), "+f"(c[1]), "+f"(c[2]), "+f"(c[3])
        : "r"(a[0]), "r"(a[1]), "r"(a[2]), "r"(a[3]), "r"(b[0]), "r"(b[1]));
}
__device__ __forceinline__ uint32_t pack_bf16(float a, float b) {
    __nv_bfloat162 t = __floats2bfloat162_rn(a, b);
    return *reinterpret_cast<uint32_t*>(&t);
}
__device__ __forceinline__ void split2(float a, float b, uint32_t& hi, uint32_t& lo) {
    uint32_t h = pack_bf16(a, b);
    float ha = __uint_as_float(h << 16);
    float hb = __uint_as_float(h & 0xffff0000u);
    lo = pack_bf16(a - ha, b - hb);
    hi = h;
}
__device__ __forceinline__ float ex2f(float x) {
    float y;
    asm("ex2.approx.ftz.f32 %0, %1;" : "=f"(y) : "f"(x));
    return y;
}
__device__ __forceinline__ void cpa16(uint32_t dst, const void* src) {
    asm volatile("cp.async.cg.shared.global [%0], [%1], 16;" :: "r"(dst), "l"(src));
}
__device__ __forceinline__ void cp_commit() {
    asm volatile("cp.async.commit_group;" ::: "memory");
}
template <int n> __device__ __forceinline__ void cp_wait() {
    asm volatile("cp.async.wait_group %0;" :: "n"(n) : "memory");
}

// ---------------------------------------------------------------------------
// K0: fp32 -> bf16 hi/lo splitter
// ---------------------------------------------------------------------------
__global__ __launch_bounds__(256)
void split_convert_kernel(const float* __restrict__ q, const float* __restrict__ k,
                          const float* __restrict__ v,
                          const float* __restrict__ wq, const float* __restrict__ wk,
                          const float* __restrict__ wv, const float* __restrict__ wo)
{
    const int seg = blockIdx.y;
    const float* src;
    __nv_bfloat16 *hi, *lo;
    int n4;
    switch (seg) {
        case 0: src = q;  hi = g_Xhi;            lo = g_Xlo;            n4 = XSEG / 4; break;
        case 1: src = k;  hi = g_Xhi + XSEG;     lo = g_Xlo + XSEG;     n4 = XSEG / 4; break;
        case 2: src = v;  hi = g_Xhi + 2 * XSEG; lo = g_Xlo + 2 * XSEG; n4 = XSEG / 4; break;
        case 3: src = wq; hi = g_Whi;            lo = g_Wlo;            n4 = WSEG / 4; break;
        case 4: src = wk; hi = g_Whi + WSEG;     lo = g_Wlo + WSEG;     n4 = WSEG / 4; break;
        case 5: src = wv; hi = g_Whi + 2 * WSEG; lo = g_Wlo + 2 * WSEG; n4 = WSEG / 4; break;
        default: src = wo; hi = g_Whi + 3 * WSEG; lo = g_Wlo + 3 * WSEG; n4 = WSEG / 4; break;
    }
    const int idx = blockIdx.x * 256 + threadIdx.x;
    if (idx >= n4) return;
    float4 x = reinterpret_cast<const float4*>(src)[idx];
    uint32_t h01, l01, h23, l23;
    split2(x.x, x.y, h01, l01);
    split2(x.z, x.w, h23, l23);
    reinterpret_cast<uint2*>(hi)[idx] = make_uint2(h01, h23);
    reinterpret_cast<uint2*>(lo)[idx] = make_uint2(l01, l23);
}

// ---------------------------------------------------------------------------
// GEMM tile: 256 threads, 8 warps (4M x 2N), warp tile 32x32, 2 stages.
// ---------------------------------------------------------------------------
__device__ __forceinline__ void gemm_ps_tile(
    const __nv_bfloat16* __restrict__ Ahi, const __nv_bfloat16* __restrict__ Alo,
    const __nv_bfloat16* __restrict__ Bhi, const __nv_bfloat16* __restrict__ Blo,
    const float* __restrict__ bias,
    float* __restrict__ Yf32, __nv_bfloat16* __restrict__ Yhi, __nv_bfloat16* __restrict__ Ylo,
    float oscale, int rowBase, int colBase, char* sm)
{
    const int tid = threadIdx.x;
    const int lane = tid & 31;
    const int wid = tid >> 5;
    const int warp_m = wid & 3;        // 4 bands x 32 rows
    const int warp_n = wid >> 2;       // 2 bands x 32 cols
    const uint32_t sb = smem_u32(sm);

    float acc[2][4][4] = {};

    const uint32_t aRow = (uint32_t)(warp_m * 32 + (lane & 15)) * PITCH_PS + (uint32_t)(lane & 16);
    const uint32_t bRow = (uint32_t)(warp_n * 32 + ((lane & 7) | ((lane & 16) >> 1))) * PITCH_PS
                          + (uint32_t)((lane & 8) * 2);

    auto load_chunk = [&](int k0, int stage) {
        const uint32_t base = sb + (uint32_t)stage * STAGE_PS;
        #pragma unroll
        for (int l = 0; l < 2; ++l) {
            const int id = tid + l * 256;        // 0..511: 128 rows x 4 chunks
            const int r = id >> 2, c = id & 3;
            const uint32_t off = (uint32_t)(r * PITCH_PS + c * 16);
            const size_t ga = (size_t)(rowBase + r) * C_ + k0 + c * 8;
            cpa16(base + off,          Ahi + ga);
            cpa16(base + TILE_A + off, Alo + ga);
        }
        {
            const int r = tid >> 2, c = tid & 3; // 64 rows x 4 chunks
            const uint32_t off = (uint32_t)(r * PITCH_PS + c * 16);
            const size_t gb = (size_t)(colBase + r) * C_ + k0 + c * 8;
            cpa16(base + 2 * TILE_A + off,           Bhi + gb);
            cpa16(base + 2 * TILE_A + TILE_B2 + off, Blo + gb);
        }
    };

    load_chunk(0, 0);
    cp_commit();

    constexpr int NCHUNK = C_ / 32;   // 32
    for (int chunk = 0; chunk < NCHUNK; ++chunk) {
        cp_wait<0>();
        __syncthreads();
        if (chunk + 1 < NCHUNK) {
            load_chunk((chunk + 1) * 32, (chunk + 1) & 1);
            cp_commit();
        }

        const uint32_t stB = sb + (uint32_t)(chunk & 1) * STAGE_PS;
        const uint32_t sBh = stB + 2 * TILE_A;
        const uint32_t sBl = sBh + TILE_B2;
        #pragma unroll
        for (int ks = 0; ks < 2; ++ks) {
            uint32_t ah[2][4], al[2][4];
            ldm_x4(ah[0], stB + aRow + ks * 32);
            ldm_x4(ah[1], stB + aRow + 16 * PITCH_PS + ks * 32);
            ldm_x4(al[0], stB + TILE_A + aRow + ks * 32);
            ldm_x4(al[1], stB + TILE_A + aRow + 16 * PITCH_PS + ks * 32);
            #pragma unroll
            for (int t = 0; t < 2; ++t) {
                uint32_t bh4[4], bl4[4];
                ldm_x4(bh4, sBh + bRow + t * 16 * PITCH_PS + ks * 32);
                ldm_x4(bl4, sBl + bRow + t * 16 * PITCH_PS + ks * 32);
                #pragma unroll
                for (int f = 0; f < 2; ++f)
                    #pragma unroll
                    for (int sub = 0; sub < 2; ++sub)
                        mma16816(acc[f][t * 2 + sub], ah[f], &bh4[2 * sub]);
                #pragma unroll
                for (int f = 0; f < 2; ++f)
                    #pragma unroll
                    for (int sub = 0; sub < 2; ++sub)
                        mma16816(acc[f][t * 2 + sub], ah[f], &bl4[2 * sub]);
                #pragma unroll
                for (int f = 0; f < 2; ++f)
                    #pragma unroll
                    for (int sub = 0; sub < 2; ++sub)
                        mma16816(acc[f][t * 2 + sub], al[f], &bh4[2 * sub]);
            }
        }
    }

    const int r = lane >> 2;
    const int cc = (lane & 3) * 2;
    #pragma unroll
    for (int f = 0; f < 2; ++f) {
        #pragma unroll
        for (int nf = 0; nf < 4; ++nf) {
            const float* c = acc[f][nf];
            const int col0 = colBase + warp_n * 32 + nf * 8 + cc;
            const int row0 = rowBase + warp_m * 32 + f * 16 + r;
            const float b0 = bias[col0], b1 = bias[col0 + 1];
            if (Yhi) {
                #pragma unroll
                for (int rr = 0; rr < 2; ++rr) {
                    const int row = row0 + rr * 8;
                    const int bb = row >> 11, i = row & (N_ - 1);
                    const int h = col0 >> 6, dd = col0 & 63;
                    const size_t idx = ((size_t)(bb * H_ + h) * N_ + i) * D_ + dd;
                    float v0 = (c[rr * 2 + 0] + b0) * oscale;
                    float v1 = (c[rr * 2 + 1] + b1) * oscale;
                    uint32_t hi, lo;
                    split2(v0, v1, hi, lo);
                    *reinterpret_cast<uint32_t*>(&Yhi[idx]) = hi;
                    *reinterpret_cast<uint32_t*>(&Ylo[idx]) = lo;
                }
            } else {
                #pragma unroll
                for (int rr = 0; rr < 2; ++rr) {
                    const int row = row0 + rr * 8;
                    float* p = &Yf32[(size_t)row * C_ + col0];
                    p[0] = c[rr * 2 + 0] + b0;
                    p[1] = c[rr * 2 + 1] + b1;
                }
            }
        }
    }
}

__global__ __launch_bounds__(256, 2)
void mha_qkv_ps_kernel(const float* __restrict__ bq, const float* __restrict__ bk,
                       const float* __restrict__ bv)
{
    extern __shared__ __align__(16) char sm[];
    const int z = blockIdx.z;
    const __nv_bfloat16* Ahi = g_Xhi + (size_t)z * XSEG;
    const __nv_bfloat16* Alo = g_Xlo + (size_t)z * XSEG;
    const __nv_bfloat16* Bhi = g_Whi + (size_t)z * WSEG;
    const __nv_bfloat16* Blo = g_Wlo + (size_t)z * WSEG;
    const float* bias; __nv_bfloat16 *Yhi, *Ylo; float sc;
    if (z == 0)      { bias = bq; Yhi = g_Qhi; Ylo = g_Qlo; sc = QSCALE; }
    else if (z == 1) { bias = bk; Yhi = g_Khi; Ylo = g_Klo; sc = 1.0f; }
    else             { bias = bv; Yhi = g_Vhi; Ylo = g_Vlo; sc = 1.0f; }
    gemm_ps_tile(Ahi, Alo, Bhi, Blo, bias, nullptr, Yhi, Ylo, sc,
                 blockIdx.y * BM, blockIdx.x * BN, sm);
}

__global__ __launch_bounds__(256, 2)
void mha_out_ps_kernel(const float* __restrict__ bo, float* __restrict__ out)
{
    extern __shared__ __align__(16) char sm[];
    gemm_ps_tile(g_AOhi, g_AOlo, g_Whi + 3 * WSEG, g_Wlo + 3 * WSEG, bo,
                 out, nullptr, nullptr, 1.0f, blockIdx.y * BM, blockIdx.x * BN, sm);
}

// ---------------------------------------------------------------------------
// K2: tensor-core flash attention (round-8 version, unchanged)
// ---------------------------------------------------------------------------
__device__ __forceinline__ void issue_kv64(uint32_t dstbase, int tid,
                                           const __nv_bfloat16* kh, const __nv_bfloat16* kl,
                                           const __nv_bfloat16* vh, const __nv_bfloat16* vl)
{
    #pragma unroll
    for (int l = 0; l < 2; l++) {
        int cid = tid + l * 256;
        int row = cid >> 3, c8 = cid & 7;
        uint32_t off = (uint32_t)(row * APITCH + c8 * 16);
        const size_t g = (size_t)row * 64 + c8 * 8;
        cpa16(dstbase + off,             kh + g);
        cpa16(dstbase + KTILE + off,     kl + g);
        cpa16(dstbase + 2 * KTILE + off, vh + g);
        cpa16(dstbase + 3 * KTILE + off, vl + g);
    }
}

__global__ __launch_bounds__(256, 2)
void mha_attn_tc_kernel()
{
    extern __shared__ __align__(16) char sm[];
    const uint32_t sb = smem_u32(sm);
    const int tid = threadIdx.x;
    const int lane = tid & 31;
    const int wid = tid >> 5;
    const int bh = blockIdx.y;
    const int qt = blockIdx.x;

    const size_t hbase = (size_t)bh * N_ * D_;
    {
        const __nv_bfloat16* qh = g_Qhi + hbase + (size_t)qt * 128 * D_;
        const __nv_bfloat16* ql = g_Qlo + hbase + (size_t)qt * 128 * D_;
        #pragma unroll
        for (int l = 0; l < 4; l++) {
            int cid = tid + l * 256;
            int row = cid >> 3, c8 = cid & 7;
            const size_t g = (size_t)row * 64 + c8 * 8;
            uint32_t off = (uint32_t)(row * APITCH + c8 * 16);
            *reinterpret_cast<uint4*>(sm + off) = *reinterpret_cast<const uint4*>(qh + g);
            *reinterpret_cast<uint4*>(sm + QHALF + off) = *reinterpret_cast<const uint4*>(ql + g);
        }
    }

    issue_kv64(sb + 2 * QHALF, tid, g_Khi + hbase, g_Klo + hbase, g_Vhi + hbase, g_Vlo + hbase);
    cp_commit();

    float mA = -1e30f, mB = -1e30f, lA = 0.0f, lB = 0.0f;
    float oacc[8][4] = {};

    const uint32_t qrow = sb + (uint32_t)((wid * 16 + (lane & 15)) * APITCH + (lane >> 4) * 16);
    const uint32_t krow = (uint32_t)((((lane & 7) | ((lane & 16) >> 1)) * APITCH) + (lane & 8) * 2);
    const uint32_t vrow = (uint32_t)((lane & 15) * APITCH + (lane >> 4) * 16);

    constexpr int NKT = N_ / 64;   // 32
    for (int kt = 0; kt < NKT; ++kt) {
        cp_wait<0>();
        __syncthreads();
        if (kt + 1 < NKT) {
            issue_kv64(sb + 2 * QHALF + (uint32_t)((kt + 1) & 1) * KV_STAGE, tid,
                       g_Khi + hbase + (size_t)(kt + 1) * 64 * D_,
                       g_Klo + hbase + (size_t)(kt + 1) * 64 * D_,
                       g_Vhi + hbase + (size_t)(kt + 1) * 64 * D_,
                       g_Vlo + hbase + (size_t)(kt + 1) * 64 * D_);
        }
        cp_commit();

        const uint32_t kb = sb + 2 * QHALF + (uint32_t)(kt & 1) * KV_STAGE;
        const uint32_t Khs = kb, Kls = kb + KTILE, Vhs = kb + 2 * KTILE, Vls = kb + 3 * KTILE;

        float sacc[8][4] = {};
        #pragma unroll
        for (int ks = 0; ks < 4; ++ks) {
            uint32_t ah[4], al[4];
            ldm_x4(ah, qrow + ks * 32);
            ldm_x4(al, qrow + QHALF + ks * 32);
            #pragma unroll
            for (int t = 0; t < 4; ++t) {
                uint32_t bh4[4], bl4[4];
                ldm_x4(bh4, Khs + krow + t * 16 * APITCH + ks * 32);
                ldm_x4(bl4, Kls + krow + t * 16 * APITCH + ks * 32);
                mma16816(sacc[t * 2 + 0], ah, &bh4[0]);
                mma16816(sacc[t * 2 + 1], ah, &bh4[2]);
                mma16816(sacc[t * 2 + 0], ah, &bl4[0]);
                mma16816(sacc[t * 2 + 1], ah, &bl4[2]);
                mma16816(sacc[t * 2 + 0], al, &bh4[0]);
                mma16816(sacc[t * 2 + 1], al, &bh4[2]);
            }
        }

        float tA = -1e30f, tB = -1e30f;
        #pragma unroll
        for (int f = 0; f < 8; ++f) {
            tA = fmaxf(tA, fmaxf(sacc[f][0], sacc[f][1]));
            tB = fmaxf(tB, fmaxf(sacc[f][2], sacc[f][3]));
        }
        tA = fmaxf(tA, __shfl_xor_sync(0xffffffffu, tA, 1));
        tA = fmaxf(tA, __shfl_xor_sync(0xffffffffu, tA, 2));
        tB = fmaxf(tB, __shfl_xor_sync(0xffffffffu, tB, 1));
        tB = fmaxf(tB, __shfl_xor_sync(0xffffffffu, tB, 2));
        const float nmA = fmaxf(mA, tA), nmB = fmaxf(mB, tB);
        const float cA = ex2f(mA - nmA), cB = ex2f(mB - nmB);
        mA = nmA; mB = nmB;

        float psA = 0.0f, psB = 0.0f;
        #pragma unroll
        for (int f = 0; f < 8; ++f) {
            float p0 = ex2f(sacc[f][0] - mA);
            float p1 = ex2f(sacc[f][1] - mA);
            float p2 = ex2f(sacc[f][2] - mB);
            float p3 = ex2f(sacc[f][3] - mB);
            sacc[f][0] = p0; sacc[f][1] = p1; sacc[f][2] = p2; sacc[f][3] = p3;
            psA += p0 + p1; psB += p2 + p3;
        }
        lA = lA * cA + psA;
        lB = lB * cB + psB;
        #pragma unroll
        for (int nf = 0; nf < 8; ++nf) {
            oacc[nf][0] *= cA; oacc[nf][1] *= cA;
            oacc[nf][2] *= cB; oacc[nf][3] *= cB;
        }

        #pragma unroll
        for (int ks = 0; ks < 4; ++ks) {
            uint32_t phi[4], plo[4];
            split2(sacc[2 * ks][0],     sacc[2 * ks][1],     phi[0], plo[0]);
            split2(sacc[2 * ks][2],     sacc[2 * ks][3],     phi[1], plo[1]);
            split2(sacc[2 * ks + 1][0], sacc[2 * ks + 1][1], phi[2], plo[2]);
            split2(sacc[2 * ks + 1][2], sacc[2 * ks + 1][3], phi[3], plo[3]);
            const uint32_t vb = vrow + (uint32_t)(16 * ks * APITCH);
            #pragma unroll
            for (int dg = 0; dg < 4; ++dg) {
                uint32_t vh4[4], vl4[4];
                ldm_x4_t(vh4, Vhs + vb + dg * 32);
                ldm_x4_t(vl4, Vls + vb + dg * 32);
                mma16816(oacc[2 * dg],     phi, &vh4[0]);
                mma16816(oacc[2 * dg + 1], phi, &vh4[2]);
                mma16816(oacc[2 * dg],     phi, &vl4[0]);
                mma16816(oacc[2 * dg + 1], phi, &vl4[2]);
                mma16816(oacc[2 * dg],     plo, &vh4[0]);
                mma16816(oacc[2 * dg + 1], plo, &vh4[2]);
            }
        }
    }

    lA += __shfl_xor_sync(0xffffffffu, lA, 1);
    lA += __shfl_xor_sync(0xffffffffu, lA, 2);
    lB += __shfl_xor_sync(0xffffffffu, lB, 1);
    lB += __shfl_xor_sync(0xffffffffu, lB, 2);
    const float iA = 1.0f / lA, iB = 1.0f / lB;

    const int b = bh >> 4;
    const int h = bh & 15;
    const int rowA = qt * 128 + wid * 16 + (lane >> 2);
    #pragma unroll
    for (int nf = 0; nf < 8; ++nf) {
        const int d0 = nf * 8 + (lane & 3) * 2;
        const size_t iA0 = (size_t)(b * N_ + rowA) * C_ + h * 64 + d0;
        const size_t iB0 = (size_t)(b * N_ + rowA + 8) * C_ + h * 64 + d0;
        uint32_t hi, lo;
        split2(oacc[nf][0] * iA, oacc[nf][1] * iA, hi, lo);
        *reinterpret_cast<uint32_t*>(&g_AOhi[iA0]) = hi;
        *reinterpret_cast<uint32_t*>(&g_AOlo[iA0]) = lo;
        split2(oacc[nf][2] * iB, oacc[nf][3] * iB, hi, lo);
        *reinterpret_cast<uint32_t*>(&g_AOhi[iB0]) = hi;
        *reinterpret_cast<uint32_t*>(&g_AOlo[iB0]) = lo;
    }
}

// ---------------------------------------------------------------------------
extern "C" void kernel_launch(void* const* d_in, const int* in_sizes, int n_in,
                              void* d_out, int out_size)
{
    (void)in_sizes; (void)n_in; (void)out_size;
    const float* q  = (const float*)d_in[0];
    const float* k  = (const float*)d_in[1];
    const float* v  = (const float*)d_in[2];
    const float* wq = (const float*)d_in[3];
    const float* bq = (const float*)d_in[4];
    const float* wk = (const float*)d_in[5];
    const float* bk = (const float*)d_in[6];
    const float* wv = (const float*)d_in[7];
    const float* bv = (const float*)d_in[8];
    const float* wo = (const float*)d_in[9];
    const float* bo = (const float*)d_in[10];
    float* out = (float*)d_out;

    cudaFuncSetAttribute(mha_qkv_ps_kernel,
                         cudaFuncAttributeMaxDynamicSharedMemorySize, GEMM_SMEM);
    cudaFuncSetAttribute(mha_out_ps_kernel,
                         cudaFuncAttributeMaxDynamicSharedMemorySize, GEMM_SMEM);
    cudaFuncSetAttribute(mha_attn_tc_kernel,
                         cudaFuncAttributeMaxDynamicSharedMemorySize, ATTN_SMEM);

    dim3 gsplit(XSEG / 4 / 256, 7);
    split_convert_kernel<<<gsplit, 256>>>(q, k, v, wq, wk, wv, wo);

    dim3 gproj(C_ / BN, (B_ * N_) / BM, 3);   // 16 x 32 x 3
    mha_qkv_ps_kernel<<<gproj, 256, GEMM_SMEM>>>(bq, bk, bv);

    dim3 gattn(N_ / 128, B_ * H_);            // 16 x 32
    mha_attn_tc_kernel<<<gattn, 256, ATTN_SMEM>>>();

    dim3 gout(C_ / BN, (B_ * N_) / BM);       // 16 x 32
    mha_out_ps_kernel<<<gout, 256, GEMM_SMEM>>>(bo, out);
}

// round 10
// speedup vs baseline: 1.1115x; 1.0171x over previous
#include <cuda_runtime.h>
#include <cuda_bf16.h>
#include <cstdint>

// ---------------------------------------------------------------------------
// MultiheadAttention: b=2, n=2048, c=1024, h=16, d=64
// Round 10: GEMMs = 2 CTAs/SM (128x64 tile) + 3-stage cp.async pipeline with
//           cp_wait<1> (prefetch distance 2 chunks) -- covers L2 latency.
// ---------------------------------------------------------------------------

namespace {
constexpr int B_ = 2;
constexpr int N_ = 2048;
constexpr int C_ = 1024;
constexpr int H_ = 16;
constexpr int D_ = 64;
constexpr float QSCALE = 0.125f * 1.44269504088896340736f;  // scale * log2(e)

constexpr int XSEG = 4096 * 1024;
constexpr int WSEG = 1024 * 1024;

// GEMM tiling: CTA tile 128(M) x 64(N), 8 warps (4Mx2N), warp tile 32x32,
// K-chunk 32, 3 stages, 2 CTAs/SM.
constexpr int BM = 128, BN = 64;
constexpr int PITCH_PS = 80;                   // 64B data + 16B pad
constexpr int TILE_A = BM * PITCH_PS;          // 10240 B
constexpr int TILE_B2 = BN * PITCH_PS;         // 5120 B
constexpr int STAGE_PS = 2 * TILE_A + 2 * TILE_B2;   // 30720 B
constexpr int NSTAGE = 3;
constexpr int GEMM_SMEM = NSTAGE * STAGE_PS;   // 92160 B -> 2 CTAs/SM (184320)

// Attention tiling (round-8/9 proven)
constexpr int APITCH = 144;
constexpr int QHALF = 128 * APITCH;
constexpr int KTILE = 64 * APITCH;
constexpr int KV_STAGE = 4 * KTILE;
constexpr int ATTN_SMEM = 2 * QHALF + 2 * KV_STAGE;  // 110592 B -> 2 CTAs/SM
}

// Pre-split inputs/weights
__device__ __nv_bfloat16 g_Xhi[3 * XSEG];
__device__ __nv_bfloat16 g_Xlo[3 * XSEG];
__device__ __nv_bfloat16 g_Whi[4 * WSEG];
__device__ __nv_bfloat16 g_Wlo[4 * WSEG];
// Head-layout projections
__device__ __nv_bfloat16 g_Qhi[B_ * H_ * N_ * D_];
__device__ __nv_bfloat16 g_Qlo[B_ * H_ * N_ * D_];
__device__ __nv_bfloat16 g_Khi[B_ * H_ * N_ * D_];
__device__ __nv_bfloat16 g_Klo[B_ * H_ * N_ * D_];
__device__ __nv_bfloat16 g_Vhi[B_ * H_ * N_ * D_];
__device__ __nv_bfloat16 g_Vlo[B_ * H_ * N_ * D_];
// Attention output (pre-split)
__device__ __nv_bfloat16 g_AOhi[XSEG];
__device__ __nv_bfloat16 g_AOlo[XSEG];

// ---------------------------------------------------------------------------
__device__ __forceinline__ uint32_t smem_u32(const void* p) {
    uint32_t a;
    asm("{ .reg .u64 t; cvta.to.shared.u64 t, %1; cvt.u32.u64 %0, t; }" : "=r"(a) : "l"(p));
    return a;
}
__device__ __forceinline__ void ldm_x4(uint32_t* r, uint32_t addr) {
    asm volatile("ldmatrix.sync.aligned.m8n8.x4.shared.b16 {%0,%1,%2,%3}, [%4];"
                 : "=r"(r[0]), "=r"(r[1]), "=r"(r[2]), "=r"(r[3]) : "r"(addr));
}
__device__ __forceinline__ void ldm_x4_t(uint32_t* r, uint32_t addr) {
    asm volatile("ldmatrix.sync.aligned.m8n8.x4.trans.shared.b16 {%0,%1,%2,%3}, [%4];"
                 : "=r"(r[0]), "=r"(r[1]), "=r"(r[2]), "=r"(r[3]) : "r"(addr));
}
__device__ __forceinline__ void mma16816(float* c, const uint32_t* a, const uint32_t* b) {
    asm volatile(
        "mma.sync.aligned.m16n8k16.row.col.f32.bf16.bf16.f32 "
        "{%0,%1,%2,%3}, {%4,%5,%6,%7}, {%8,%9}, {%0,%1,%2,%3};"
        : "+f"(c[0]), "+f"(c[1]), "+f"(c[2]), "+f"(c[3])
        : "r"(a[0]), "r"(a[1]), "r"(a[2]), "r"(a[3]), "r"(b[0]), "r"(b[1]));
}
__device__ __forceinline__ uint32_t pack_bf16(float a, float b) {
    __nv_bfloat162 t = __floats2bfloat162_rn(a, b);
    return *reinterpret_cast<uint32_t*>(&t);
}
__device__ __forceinline__ void split2(float a, float b, uint32_t& hi, uint32_t& lo) {
    uint32_t h = pack_bf16(a, b);
    float ha = __uint_as_float(h << 16);
    float hb = __uint_as_float(h & 0xffff0000u);
    lo = pack_bf16(a - ha, b - hb);
    hi = h;
}
__device__ __forceinline__ float ex2f(float x) {
    float y;
    asm("ex2.approx.ftz.f32 %0, %1;" : "=f"(y) : "f"(x));
    return y;
}
__device__ __forceinline__ void cpa16(uint32_t dst, const void* src) {
    asm volatile("cp.async.cg.shared.global [%0], [%1], 16;" :: "r"(dst), "l"(src));
}
__device__ __forceinline__ void cp_commit() {
    asm volatile("cp.async.commit_group;" ::: "memory");
}
template <int n> __device__ __forceinline__ void cp_wait() {
    asm volatile("cp.async.wait_group %0;" :: "n"(n) : "memory");
}

// ---------------------------------------------------------------------------
// K0: fp32 -> bf16 hi/lo splitter
// ---------------------------------------------------------------------------
__global__ __launch_bounds__(256)
void split_convert_kernel(const float* __restrict__ q, const float* __restrict__ k,
                          const float* __restrict__ v,
                          const float* __restrict__ wq, const float* __restrict__ wk,
                          const float* __restrict__ wv, const float* __restrict__ wo)
{
    const int seg = blockIdx.y;
    const float* src;
    __nv_bfloat16 *hi, *lo;
    int n4;
    switch (seg) {
        case 0: src = q;  hi = g_Xhi;            lo = g_Xlo;            n4 = XSEG / 4; break;
        case 1: src = k;  hi = g_Xhi + XSEG;     lo = g_Xlo + XSEG;     n4 = XSEG / 4; break;
        case 2: src = v;  hi = g_Xhi + 2 * XSEG; lo = g_Xlo + 2 * XSEG; n4 = XSEG / 4; break;
        case 3: src = wq; hi = g_Whi;            lo = g_Wlo;            n4 = WSEG / 4; break;
        case 4: src = wk; hi = g_Whi + WSEG;     lo = g_Wlo + WSEG;     n4 = WSEG / 4; break;
        case 5: src = wv; hi = g_Whi + 2 * WSEG; lo = g_Wlo + 2 * WSEG; n4 = WSEG / 4; break;
        default: src = wo; hi = g_Whi + 3 * WSEG; lo = g_Wlo + 3 * WSEG; n4 = WSEG / 4; break;
    }
    const int idx = blockIdx.x * 256 + threadIdx.x;
    if (idx >= n4) return;
    float4 x = reinterpret_cast<const float4*>(src)[idx];
    uint32_t h01, l01, h23, l23;
    split2(x.x, x.y, h01, l01);
    split2(x.z, x.w, h23, l23);
    reinterpret_cast<uint2*>(hi)[idx] = make_uint2(h01, h23);
    reinterpret_cast<uint2*>(lo)[idx] = make_uint2(l01, l23);
}

// ---------------------------------------------------------------------------
// GEMM tile: 256 threads, 8 warps (4M x 2N), warp tile 32x32, 3 stages,
// prefetch distance 2, cp_wait<1>, one barrier per chunk.
// ---------------------------------------------------------------------------
__device__ __forceinline__ void gemm_ps_tile(
    const __nv_bfloat16* __restrict__ Ahi, const __nv_bfloat16* __restrict__ Alo,
    const __nv_bfloat16* __restrict__ Bhi, const __nv_bfloat16* __restrict__ Blo,
    const float* __restrict__ bias,
    float* __restrict__ Yf32, __nv_bfloat16* __restrict__ Yhi, __nv_bfloat16* __restrict__ Ylo,
    float oscale, int rowBase, int colBase, char* sm)
{
    const int tid = threadIdx.x;
    const int lane = tid & 31;
    const int wid = tid >> 5;
    const int warp_m = wid & 3;
    const int warp_n = wid >> 2;
    const uint32_t sb = smem_u32(sm);

    float acc[2][4][4] = {};

    const uint32_t aRow = (uint32_t)(warp_m * 32 + (lane & 15)) * PITCH_PS + (uint32_t)(lane & 16);
    const uint32_t bRow = (uint32_t)(warp_n * 32 + ((lane & 7) | ((lane & 16) >> 1))) * PITCH_PS
                          + (uint32_t)((lane & 8) * 2);

    auto load_chunk = [&](int k0, int stage) {
        const uint32_t base = sb + (uint32_t)stage * STAGE_PS;
        #pragma unroll
        for (int l = 0; l < 2; ++l) {
            const int id = tid + l * 256;
            const int r = id >> 2, c = id & 3;
            const uint32_t off = (uint32_t)(r * PITCH_PS + c * 16);
            const size_t ga = (size_t)(rowBase + r) * C_ + k0 + c * 8;
            cpa16(base + off,          Ahi + ga);
            cpa16(base + TILE_A + off, Alo + ga);
        }
        {
            const int r = tid >> 2, c = tid & 3;
            const uint32_t off = (uint32_t)(r * PITCH_PS + c * 16);
            const size_t gb = (size_t)(colBase + r) * C_ + k0 + c * 8;
            cpa16(base + 2 * TILE_A + off,           Bhi + gb);
            cpa16(base + 2 * TILE_A + TILE_B2 + off, Blo + gb);
        }
    };

    // Prologue: chunks 0,1 in flight
    load_chunk(0, 0);  cp_commit();
    load_chunk(32, 1); cp_commit();

    constexpr int NCHUNK = C_ / 32;   // 32
    int s_cur = 0;                    // stage holding `chunk`
    int s_ld = 2;                     // stage for `chunk+2`
    for (int chunk = 0; chunk < NCHUNK; ++chunk) {
        cp_wait<1>();        // chunk resident; chunk+1 may still be loading
        __syncthreads();     // all warps finished compute of chunk-1

        if (chunk + 2 < NCHUNK) load_chunk((chunk + 2) * 32, s_ld);
        cp_commit();         // unconditional: one group per iteration

        const uint32_t stB = sb + (uint32_t)s_cur * STAGE_PS;
        const uint32_t sBh = stB + 2 * TILE_A;
        const uint32_t sBl = sBh + TILE_B2;
        #pragma unroll
        for (int ks = 0; ks < 2; ++ks) {
            uint32_t ah[2][4], al[2][4];
            ldm_x4(ah[0], stB + aRow + ks * 32);
            ldm_x4(ah[1], stB + aRow + 16 * PITCH_PS + ks * 32);
            ldm_x4(al[0], stB + TILE_A + aRow + ks * 32);
            ldm_x4(al[1], stB + TILE_A + aRow + 16 * PITCH_PS + ks * 32);
            #pragma unroll
            for (int t = 0; t < 2; ++t) {
                uint32_t bh4[4], bl4[4];
                ldm_x4(bh4, sBh + bRow + t * 16 * PITCH_PS + ks * 32);
                ldm_x4(bl4, sBl + bRow + t * 16 * PITCH_PS + ks * 32);
                #pragma unroll
                for (int f = 0; f < 2; ++f)
                    #pragma unroll
                    for (int sub = 0; sub < 2; ++sub)
                        mma16816(acc[f][t * 2 + sub], ah[f], &bh4[2 * sub]);
                #pragma unroll
                for (int f = 0; f < 2; ++f)
                    #pragma unroll
                    for (int sub = 0; sub < 2; ++sub)
                        mma16816(acc[f][t * 2 + sub], ah[f], &bl4[2 * sub]);
                #pragma unroll
                for (int f = 0; f < 2; ++f)
                    #pragma unroll
                    for (int sub = 0; sub < 2; ++sub)
                        mma16816(acc[f][t * 2 + sub], al[f], &bh4[2 * sub]);
            }
        }

        s_cur = (s_cur == NSTAGE - 1) ? 0 : s_cur + 1;
        s_ld  = (s_ld  == NSTAGE - 1) ? 0 : s_ld  + 1;
    }

    const int r = lane >> 2;
    const int cc = (lane & 3) * 2;
    #pragma unroll
    for (int f = 0; f < 2; ++f) {
        #pragma unroll
        for (int nf = 0; nf < 4; ++nf) {
            const float* c = acc[f][nf];
            const int col0 = colBase + warp_n * 32 + nf * 8 + cc;
            const int row0 = rowBase + warp_m * 32 + f * 16 + r;
            const float b0 = bias[col0], b1 = bias[col0 + 1];
            if (Yhi) {
                #pragma unroll
                for (int rr = 0; rr < 2; ++rr) {
                    const int row = row0 + rr * 8;
                    const int bb = row >> 11, i = row & (N_ - 1);
                    const int h = col0 >> 6, dd = col0 & 63;
                    const size_t idx = ((size_t)(bb * H_ + h) * N_ + i) * D_ + dd;
                    float v0 = (c[rr * 2 + 0] + b0) * oscale;
                    float v1 = (c[rr * 2 + 1] + b1) * oscale;
                    uint32_t hi, lo;
                    split2(v0, v1, hi, lo);
                    *reinterpret_cast<uint32_t*>(&Yhi[idx]) = hi;
                    *reinterpret_cast<uint32_t*>(&Ylo[idx]) = lo;
                }
            } else {
                #pragma unroll
                for (int rr = 0; rr < 2; ++rr) {
                    const int row = row0 + rr * 8;
                    float* p = &Yf32[(size_t)row * C_ + col0];
                    p[0] = c[rr * 2 + 0] + b0;
                    p[1] = c[rr * 2 + 1] + b1;
                }
            }
        }
    }
}

__global__ __launch_bounds__(256, 2)
void mha_qkv_ps_kernel(const float* __restrict__ bq, const float* __restrict__ bk,
                       const float* __restrict__ bv)
{
    extern __shared__ __align__(16) char sm[];
    const int z = blockIdx.z;
    const __nv_bfloat16* Ahi = g_Xhi + (size_t)z * XSEG;
    const __nv_bfloat16* Alo = g_Xlo + (size_t)z * XSEG;
    const __nv_bfloat16* Bhi = g_Whi + (size_t)z * WSEG;
    const __nv_bfloat16* Blo = g_Wlo + (size_t)z * WSEG;
    const float* bias; __nv_bfloat16 *Yhi, *Ylo; float sc;
    if (z == 0)      { bias = bq; Yhi = g_Qhi; Ylo = g_Qlo; sc = QSCALE; }
    else if (z == 1) { bias = bk; Yhi = g_Khi; Ylo = g_Klo; sc = 1.0f; }
    else             { bias = bv; Yhi = g_Vhi; Ylo = g_Vlo; sc = 1.0f; }
    gemm_ps_tile(Ahi, Alo, Bhi, Blo, bias, nullptr, Yhi, Ylo, sc,
                 blockIdx.y * BM, blockIdx.x * BN, sm);
}

__global__ __launch_bounds__(256, 2)
void mha_out_ps_kernel(const float* __restrict__ bo, float* __restrict__ out)
{
    extern __shared__ __align__(16) char sm[];
    gemm_ps_tile(g_AOhi, g_AOlo, g_Whi + 3 * WSEG, g_Wlo + 3 * WSEG, bo,
                 out, nullptr, nullptr, 1.0f, blockIdx.y * BM, blockIdx.x * BN, sm);
}

// ---------------------------------------------------------------------------
// K2: tensor-core flash attention (round-9 version, unchanged)
// ---------------------------------------------------------------------------
__device__ __forceinline__ void issue_kv64(uint32_t dstbase, int tid,
                                           const __nv_bfloat16* kh, const __nv_bfloat16* kl,
                                           const __nv_bfloat16* vh, const __nv_bfloat16* vl)
{
    #pragma unroll
    for (int l = 0; l < 2; l++) {
        int cid = tid + l * 256;
        int row = cid >> 3, c8 = cid & 7;
        uint32_t off = (uint32_t)(row * APITCH + c8 * 16);
        const size_t g = (size_t)row * 64 + c8 * 8;
        cpa16(dstbase + off,             kh + g);
        cpa16(dstbase + KTILE + off,     kl + g);
        cpa16(dstbase + 2 * KTILE + off, vh + g);
        cpa16(dstbase + 3 * KTILE + off, vl + g);
    }
}

__global__ __launch_bounds__(256, 2)
void mha_attn_tc_kernel()
{
    extern __shared__ __align__(16) char sm[];
    const uint32_t sb = smem_u32(sm);
    const int tid = threadIdx.x;
    const int lane = tid & 31;
    const int wid = tid >> 5;
    const int bh = blockIdx.y;
    const int qt = blockIdx.x;

    const size_t hbase = (size_t)bh * N_ * D_;
    {
        const __nv_bfloat16* qh = g_Qhi + hbase + (size_t)qt * 128 * D_;
        const __nv_bfloat16* ql = g_Qlo + hbase + (size_t)qt * 128 * D_;
        #pragma unroll
        for (int l = 0; l < 4; l++) {
            int cid = tid + l * 256;
            int row = cid >> 3, c8 = cid & 7;
            const size_t g = (size_t)row * 64 + c8 * 8;
            uint32_t off = (uint32_t)(row * APITCH + c8 * 16);
            *reinterpret_cast<uint4*>(sm + off) = *reinterpret_cast<const uint4*>(qh + g);
            *reinterpret_cast<uint4*>(sm + QHALF + off) = *reinterpret_cast<const uint4*>(ql + g);
        }
    }

    issue_kv64(sb + 2 * QHALF, tid, g_Khi + hbase, g_Klo + hbase, g_Vhi + hbase, g_Vlo + hbase);
    cp_commit();

    float mA = -1e30f, mB = -1e30f, lA = 0.0f, lB = 0.0f;
    float oacc[8][4] = {};

    const uint32_t qrow = sb + (uint32_t)((wid * 16 + (lane & 15)) * APITCH + (lane >> 4) * 16);
    const uint32_t krow = (uint32_t)((((lane & 7) | ((lane & 16) >> 1)) * APITCH) + (lane & 8) * 2);
    const uint32_t vrow = (uint32_t)((lane & 15) * APITCH + (lane >> 4) * 16);

    constexpr int NKT = N_ / 64;   // 32
    for (int kt = 0; kt < NKT; ++kt) {
        cp_wait<0>();
        __syncthreads();
        if (kt + 1 < NKT) {
            issue_kv64(sb + 2 * QHALF + (uint32_t)((kt + 1) & 1) * KV_STAGE, tid,
                       g_Khi + hbase + (size_t)(kt + 1) * 64 * D_,
                       g_Klo + hbase + (size_t)(kt + 1) * 64 * D_,
                       g_Vhi + hbase + (size_t)(kt + 1) * 64 * D_,
                       g_Vlo + hbase + (size_t)(kt + 1) * 64 * D_);
        }
        cp_commit();

        const uint32_t kb = sb + 2 * QHALF + (uint32_t)(kt & 1) * KV_STAGE;
        const uint32_t Khs = kb, Kls = kb + KTILE, Vhs = kb + 2 * KTILE, Vls = kb + 3 * KTILE;

        float sacc[8][4] = {};
        #pragma unroll
        for (int ks = 0; ks < 4; ++ks) {
            uint32_t ah[4], al[4];
            ldm_x4(ah, qrow + ks * 32);
            ldm_x4(al, qrow + QHALF + ks * 32);
            #pragma unroll
            for (int t = 0; t < 4; ++t) {
                uint32_t bh4[4], bl4[4];
                ldm_x4(bh4, Khs + krow + t * 16 * APITCH + ks * 32);
                ldm_x4(bl4, Kls + krow + t * 16 * APITCH + ks * 32);
                mma16816(sacc[t * 2 + 0], ah, &bh4[0]);
                mma16816(sacc[t * 2 + 1], ah, &bh4[2]);
                mma16816(sacc[t * 2 + 0], ah, &bl4[0]);
                mma16816(sacc[t * 2 + 1], ah, &bl4[2]);
                mma16816(sacc[t * 2 + 0], al, &bh4[0]);
                mma16816(sacc[t * 2 + 1], al, &bh4[2]);
            }
        }

        float tA = -1e30f, tB = -1e30f;
        #pragma unroll
        for (int f = 0; f < 8; ++f) {
            tA = fmaxf(tA, fmaxf(sacc[f][0], sacc[f][1]));
            tB = fmaxf(tB, fmaxf(sacc[f][2], sacc[f][3]));
        }
        tA = fmaxf(tA, __shfl_xor_sync(0xffffffffu, tA, 1));
        tA = fmaxf(tA, __shfl_xor_sync(0xffffffffu, tA, 2));
        tB = fmaxf(tB, __shfl_xor_sync(0xffffffffu, tB, 1));
        tB = fmaxf(tB, __shfl_xor_sync(0xffffffffu, tB, 2));
        const float nmA = fmaxf(mA, tA), nmB = fmaxf(mB, tB);
        const float cA = ex2f(mA - nmA), cB = ex2f(mB - nmB);
        mA = nmA; mB = nmB;

        float psA = 0.0f, psB = 0.0f;
        #pragma unroll
        for (int f = 0; f < 8; ++f) {
            float p0 = ex2f(sacc[f][0] - mA);
            float p1 = ex2f(sacc[f][1] - mA);
            float p2 = ex2f(sacc[f][2] - mB);
            float p3 = ex2f(sacc[f][3] - mB);
            sacc[f][0] = p0; sacc[f][1] = p1; sacc[f][2] = p2; sacc[f][3] = p3;
            psA += p0 + p1; psB += p2 + p3;
        }
        lA = lA * cA + psA;
        lB = lB * cB + psB;
        #pragma unroll
        for (int nf = 0; nf < 8; ++nf) {
            oacc[nf][0] *= cA; oacc[nf][1] *= cA;
            oacc[nf][2] *= cB; oacc[nf][3] *= cB;
        }

        #pragma unroll
        for (int ks = 0; ks < 4; ++ks) {
            uint32_t phi[4], plo[4];
            split2(sacc[2 * ks][0],     sacc[2 * ks][1],     phi[0], plo[0]);
            split2(sacc[2 * ks][2],     sacc[2 * ks][3],     phi[1], plo[1]);
            split2(sacc[2 * ks + 1][0], sacc[2 * ks + 1][1], phi[2], plo[2]);
            split2(sacc[2 * ks + 1][2], sacc[2 * ks + 1][3], phi[3], plo[3]);
            const uint32_t vb = vrow + (uint32_t)(16 * ks * APITCH);
            #pragma unroll
            for (int dg = 0; dg < 4; ++dg) {
                uint32_t vh4[4], vl4[4];
                ldm_x4_t(vh4, Vhs + vb + dg * 32);
                ldm_x4_t(vl4, Vls + vb + dg * 32);
                mma16816(oacc[2 * dg],     phi, &vh4[0]);
                mma16816(oacc[2 * dg + 1], phi, &vh4[2]);
                mma16816(oacc[2 * dg],     phi, &vl4[0]);
                mma16816(oacc[2 * dg + 1], phi, &vl4[2]);
                mma16816(oacc[2 * dg],     plo, &vh4[0]);
                mma16816(oacc[2 * dg + 1], plo, &vh4[2]);
            }
        }
    }

    lA += __shfl_xor_sync(0xffffffffu, lA, 1);
    lA += __shfl_xor_sync(0xffffffffu, lA, 2);
    lB += __shfl_xor_sync(0xffffffffu, lB, 1);
    lB += __shfl_xor_sync(0xffffffffu, lB, 2);
    const float iA = 1.0f / lA, iB = 1.0f / lB;

    const int b = bh >> 4;
    const int h = bh & 15;
    const int rowA = qt * 128 + wid * 16 + (lane >> 2);
    #pragma unroll
    for (int nf = 0; nf < 8; ++nf) {
        const int d0 = nf * 8 + (lane & 3) * 2;
        const size_t iA0 = (size_t)(b * N_ + rowA) * C_ + h * 64 + d0;
        const size_t iB0 = (size_t)(b * N_ + rowA + 8) * C_ + h * 64 + d0;
        uint32_t hi, lo;
        split2(oacc[nf][0] * iA, oacc[nf][1] * iA, hi, lo);
        *reinterpret_cast<uint32_t*>(&g_AOhi[iA0]) = hi;
        *reinterpret_cast<uint32_t*>(&g_AOlo[iA0]) = lo;
        split2(oacc[nf][2] * iB, oacc[nf][3] * iB, hi, lo);
        *reinterpret_cast<uint32_t*>(&g_AOhi[iB0]) = hi;
        *reinterpret_cast<uint32_t*>(&g_AOlo[iB0]) = lo;
    }
}

// ---------------------------------------------------------------------------
extern "C" void kernel_launch(void* const* d_in, const int* in_sizes, int n_in,
                              void* d_out, int out_size)
{
    (void)in_sizes; (void)n_in; (void)out_size;
    const float* q  = (const float*)d_in[0];
    const float* k  = (const float*)d_in[1];
    const float* v  = (const float*)d_in[2];
    const float* wq = (const float*)d_in[3];
    const float* bq = (const float*)d_in[4];
    const float* wk = (const float*)d_in[5];
    const float* bk = (const float*)d_in[6];
    const float* wv = (const float*)d_in[7];
    const float* bv = (const float*)d_in[8];
    const float* wo = (const float*)d_in[9];
    const float* bo = (const float*)d_in[10];
    float* out = (float*)d_out;

    cudaFuncSetAttribute(mha_qkv_ps_kernel,
                         cudaFuncAttributeMaxDynamicSharedMemorySize, GEMM_SMEM);
    cudaFuncSetAttribute(mha_out_ps_kernel,
                         cudaFuncAttributeMaxDynamicSharedMemorySize, GEMM_SMEM);
    cudaFuncSetAttribute(mha_attn_tc_kernel,
                         cudaFuncAttributeMaxDynamicSharedMemorySize, ATTN_SMEM);

    dim3 gsplit(XSEG / 4 / 256, 7);
    split_convert_kernel<<<gsplit, 256>>>(q, k, v, wq, wk, wv, wo);

    dim3 gproj(C_ / BN, (B_ * N_) / BM, 3);   // 16 x 32 x 3
    mha_qkv_ps_kernel<<<gproj, 256, GEMM_SMEM>>>(bq, bk, bv);

    dim3 gattn(N_ / 128, B_ * H_);            // 16 x 32
    mha_attn_tc_kernel<<<gattn, 256, ATTN_SMEM>>>();

    dim3 gout(C_ / BN, (B_ * N_) / BM);       // 16 x 32
    mha_out_ps_kernel<<<gout, 256, GEMM_SMEM>>>(bo, out);
}

// round 11
// speedup vs baseline: 1.1376x; 1.0235x over previous
#include <cuda_runtime.h>
#include <cuda_bf16.h>
#include <cstdint>

// ---------------------------------------------------------------------------
// MultiheadAttention: b=2, n=2048, c=1024, h=16, d=64
// Round 11: GEMM mainloop restructured to the attention pattern:
//   K-super 64, 2 super-buffers, cp_wait<0> + ONE barrier per super,
//   96 warp-MMAs per barrier interval (2x round-10), 2 CTAs/SM.
// ---------------------------------------------------------------------------

namespace {
constexpr int B_ = 2;
constexpr int N_ = 2048;
constexpr int C_ = 1024;
constexpr int H_ = 16;
constexpr int D_ = 64;
constexpr float QSCALE = 0.125f * 1.44269504088896340736f;  // scale * log2(e)

constexpr int XSEG = 4096 * 1024;
constexpr int WSEG = 1024 * 1024;

// GEMM tiling: CTA tile 128(M) x 64(N), 8 warps (4Mx2N), warp tile 32x32.
// K-super 64 (4 k16 steps), ring of 2 super-buffers, barrier per super.
constexpr int BM = 128, BN = 64;
constexpr int GPITCH = 144;                    // 128 B data (64 bf16) + 16 pad
constexpr int TILE_A = BM * GPITCH;            // 18432 B
constexpr int TILE_B2 = BN * GPITCH;           // 9216 B
constexpr int SUPER_PS = 2 * TILE_A + 2 * TILE_B2;   // Ahi,Alo,Bhi,Blo = 55296
constexpr int GEMM_SMEM = 2 * SUPER_PS;        // 110592 B -> 2 CTAs/SM
constexpr int NSUPER = C_ / 64;                // 16

// Attention tiling (round-8/9/10 proven)
constexpr int APITCH = 144;
constexpr int QHALF = 128 * APITCH;
constexpr int KTILE = 64 * APITCH;
constexpr int KV_STAGE = 4 * KTILE;
constexpr int ATTN_SMEM = 2 * QHALF + 2 * KV_STAGE;  // 110592 B -> 2 CTAs/SM
}

// Pre-split inputs/weights
__device__ __nv_bfloat16 g_Xhi[3 * XSEG];
__device__ __nv_bfloat16 g_Xlo[3 * XSEG];
__device__ __nv_bfloat16 g_Whi[4 * WSEG];
__device__ __nv_bfloat16 g_Wlo[4 * WSEG];
// Head-layout projections
__device__ __nv_bfloat16 g_Qhi[B_ * H_ * N_ * D_];
__device__ __nv_bfloat16 g_Qlo[B_ * H_ * N_ * D_];
__device__ __nv_bfloat16 g_Khi[B_ * H_ * N_ * D_];
__device__ __nv_bfloat16 g_Klo[B_ * H_ * N_ * D_];
__device__ __nv_bfloat16 g_Vhi[B_ * H_ * N_ * D_];
__device__ __nv_bfloat16 g_Vlo[B_ * H_ * N_ * D_];
// Attention output (pre-split)
__device__ __nv_bfloat16 g_AOhi[XSEG];
__device__ __nv_bfloat16 g_AOlo[XSEG];

// ---------------------------------------------------------------------------
__device__ __forceinline__ uint32_t smem_u32(const void* p) {
    uint32_t a;
    asm("{ .reg .u64 t; cvta.to.shared.u64 t, %1; cvt.u32.u64 %0, t; }" : "=r"(a) : "l"(p));
    return a;
}
__device__ __forceinline__ void ldm_x4(uint32_t* r, uint32_t addr) {
    asm volatile("ldmatrix.sync.aligned.m8n8.x4.shared.b16 {%0,%1,%2,%3}, [%4];"
                 : "=r"(r[0]), "=r"(r[1]), "=r"(r[2]), "=r"(r[3]) : "r"(addr));
}
__device__ __forceinline__ void ldm_x4_t(uint32_t* r, uint32_t addr) {
    asm volatile("ldmatrix.sync.aligned.m8n8.x4.trans.shared.b16 {%0,%1,%2,%3}, [%4];"
                 : "=r"(r[0]), "=r"(r[1]), "=r"(r[2]), "=r"(r[3]) : "r"(addr));
}
__device__ __forceinline__ void mma16816(float* c, const uint32_t* a, const uint32_t* b) {
    asm volatile(
        "mma.sync.aligned.m16n8k16.row.col.f32.bf16.bf16.f32 "
        "{%0,%1,%2,%3}, {%4,%5,%6,%7}, {%8,%9}, {%0,%1,%2,%3};"
        : "+f"(c[0]), "+f"(c[1]), "+f"(c[2]), "+f"(c[3])
        : "r"(a[0]), "r"(a[1]), "r"(a[2]), "r"(a[3]), "r"(b[0]), "r"(b[1]));
}
__device__ __forceinline__ uint32_t pack_bf16(float a, float b) {
    __nv_bfloat162 t = __floats2bfloat162_rn(a, b);
    return *reinterpret_cast<uint32_t*>(&t);
}
__device__ __forceinline__ void split2(float a, float b, uint32_t& hi, uint32_t& lo) {
    uint32_t h = pack_bf16(a, b);
    float ha = __uint_as_float(h << 16);
    float hb = __uint_as_float(h & 0xffff0000u);
    lo = pack_bf16(a - ha, b - hb);
    hi = h;
}
__device__ __forceinline__ float ex2f(float x) {
    float y;
    asm("ex2.approx.ftz.f32 %0, %1;" : "=f"(y) : "f"(x));
    return y;
}
__device__ __forceinline__ void cpa16(uint32_t dst, const void* src) {
    asm volatile("cp.async.cg.shared.global [%0], [%1], 16;" :: "r"(dst), "l"(src));
}
__device__ __forceinline__ void cp_commit() {
    asm volatile("cp.async.commit_group;" ::: "memory");
}
template <int n> __device__ __forceinline__ void cp_wait() {
    asm volatile("cp.async.wait_group %0;" :: "n"(n) : "memory");
}

// ---------------------------------------------------------------------------
// K0: fp32 -> bf16 hi/lo splitter
// ---------------------------------------------------------------------------
__global__ __launch_bounds__(256)
void split_convert_kernel(const float* __restrict__ q, const float* __restrict__ k,
                          const float* __restrict__ v,
                          const float* __restrict__ wq, const float* __restrict__ wk,
                          const float* __restrict__ wv, const float* __restrict__ wo)
{
    const int seg = blockIdx.y;
    const float* src;
    __nv_bfloat16 *hi, *lo;
    int n4;
    switch (seg) {
        case 0: src = q;  hi = g_Xhi;            lo = g_Xlo;            n4 = XSEG / 4; break;
        case 1: src = k;  hi = g_Xhi + XSEG;     lo = g_Xlo + XSEG;     n4 = XSEG / 4; break;
        case 2: src = v;  hi = g_Xhi + 2 * XSEG; lo = g_Xlo + 2 * XSEG; n4 = XSEG / 4; break;
        case 3: src = wq; hi = g_Whi;            lo = g_Wlo;            n4 = WSEG / 4; break;
        case 4: src = wk; hi = g_Whi + WSEG;     lo = g_Wlo + WSEG;     n4 = WSEG / 4; break;
        case 5: src = wv; hi = g_Whi + 2 * WSEG; lo = g_Wlo + 2 * WSEG; n4 = WSEG / 4; break;
        default: src = wo; hi = g_Whi + 3 * WSEG; lo = g_Wlo + 3 * WSEG; n4 = WSEG / 4; break;
    }
    const int idx = blockIdx.x * 256 + threadIdx.x;
    if (idx >= n4) return;
    float4 x = reinterpret_cast<const float4*>(src)[idx];
    uint32_t h01, l01, h23, l23;
    split2(x.x, x.y, h01, l01);
    split2(x.z, x.w, h23, l23);
    reinterpret_cast<uint2*>(hi)[idx] = make_uint2(h01, h23);
    reinterpret_cast<uint2*>(lo)[idx] = make_uint2(l01, l23);
}

// ---------------------------------------------------------------------------
// GEMM tile: 256 threads, 8 warps (4M x 2N), warp tile 32x32.
// Attention-style mainloop: one cp group + one barrier per K-super (64).
// ---------------------------------------------------------------------------
__device__ __forceinline__ void gemm_ps_tile(
    const __nv_bfloat16* __restrict__ Ahi, const __nv_bfloat16* __restrict__ Alo,
    const __nv_bfloat16* __restrict__ Bhi, const __nv_bfloat16* __restrict__ Blo,
    const float* __restrict__ bias,
    float* __restrict__ Yf32, __nv_bfloat16* __restrict__ Yhi, __nv_bfloat16* __restrict__ Ylo,
    float oscale, int rowBase, int colBase, char* sm)
{
    const int tid = threadIdx.x;
    const int lane = tid & 31;
    const int wid = tid >> 5;
    const int warp_m = wid & 3;
    const int warp_n = wid >> 2;
    const uint32_t sb = smem_u32(sm);

    float acc[2][4][4] = {};

    const uint32_t aRow = (uint32_t)(warp_m * 32 + (lane & 15)) * GPITCH + (uint32_t)(lane & 16);
    const uint32_t bRow = (uint32_t)(warp_n * 32 + ((lane & 7) | ((lane & 16) >> 1))) * GPITCH
                          + (uint32_t)((lane & 8) * 2);

    // Load one K-super (64 cols) into buffer `buf`. 12 cp.async per thread.
    auto load_super = [&](int k0, int buf) {
        const uint32_t base = sb + (uint32_t)buf * SUPER_PS;
        #pragma unroll
        for (int l = 0; l < 4; ++l) {
            const int id = tid + l * 256;            // 0..1023: 128 rows x 8 chunks
            const int r = id >> 3, c = id & 7;
            const uint32_t off = (uint32_t)(r * GPITCH + c * 16);
            const size_t ga = (size_t)(rowBase + r) * C_ + k0 + c * 8;
            cpa16(base + off,          Ahi + ga);
            cpa16(base + TILE_A + off, Alo + ga);
        }
        #pragma unroll
        for (int l = 0; l < 2; ++l) {
            const int id = tid + l * 256;            // 0..511: 64 rows x 8 chunks
            const int r = id >> 3, c = id & 7;
            const uint32_t off = (uint32_t)(r * GPITCH + c * 16);
            const size_t gb = (size_t)(colBase + r) * C_ + k0 + c * 8;
            cpa16(base + 2 * TILE_A + off,           Bhi + gb);
            cpa16(base + 2 * TILE_A + TILE_B2 + off, Blo + gb);
        }
    };

    load_super(0, 0);
    cp_commit();

    for (int s = 0; s < NSUPER; ++s) {
        cp_wait<0>();        // super s fully resident (this thread's share)
        __syncthreads();     // cross-warp visibility + buffer reuse safety

        if (s + 1 < NSUPER) load_super((s + 1) * 64, (s + 1) & 1);
        cp_commit();         // unconditional: one group per iteration

        const uint32_t stB = sb + (uint32_t)(s & 1) * SUPER_PS;
        const uint32_t sBh = stB + 2 * TILE_A;
        const uint32_t sBl = sBh + TILE_B2;
        #pragma unroll
        for (int ks = 0; ks < 4; ++ks) {
            uint32_t ah[2][4], al[2][4];
            ldm_x4(ah[0], stB + aRow + ks * 32);
            ldm_x4(ah[1], stB + aRow + 16 * GPITCH + ks * 32);
            ldm_x4(al[0], stB + TILE_A + aRow + ks * 32);
            ldm_x4(al[1], stB + TILE_A + aRow + 16 * GPITCH + ks * 32);
            #pragma unroll
            for (int t = 0; t < 2; ++t) {
                uint32_t bh4[4], bl4[4];
                ldm_x4(bh4, sBh + bRow + t * 16 * GPITCH + ks * 32);
                ldm_x4(bl4, sBl + bRow + t * 16 * GPITCH + ks * 32);
                #pragma unroll
                for (int f = 0; f < 2; ++f)
                    #pragma unroll
                    for (int sub = 0; sub < 2; ++sub)
                        mma16816(acc[f][t * 2 + sub], ah[f], &bh4[2 * sub]);
                #pragma unroll
                for (int f = 0; f < 2; ++f)
                    #pragma unroll
                    for (int sub = 0; sub < 2; ++sub)
                        mma16816(acc[f][t * 2 + sub], ah[f], &bl4[2 * sub]);
                #pragma unroll
                for (int f = 0; f < 2; ++f)
                    #pragma unroll
                    for (int sub = 0; sub < 2; ++sub)
                        mma16816(acc[f][t * 2 + sub], al[f], &bh4[2 * sub]);
            }
        }
    }

    const int r = lane >> 2;
    const int cc = (lane & 3) * 2;
    #pragma unroll
    for (int f = 0; f < 2; ++f) {
        #pragma unroll
        for (int nf = 0; nf < 4; ++nf) {
            const float* c = acc[f][nf];
            const int col0 = colBase + warp_n * 32 + nf * 8 + cc;
            const int row0 = rowBase + warp_m * 32 + f * 16 + r;
            const float b0 = bias[col0], b1 = bias[col0 + 1];
            if (Yhi) {
                #pragma unroll
                for (int rr = 0; rr < 2; ++rr) {
                    const int row = row0 + rr * 8;
                    const int bb = row >> 11, i = row & (N_ - 1);
                    const int h = col0 >> 6, dd = col0 & 63;
                    const size_t idx = ((size_t)(bb * H_ + h) * N_ + i) * D_ + dd;
                    float v0 = (c[rr * 2 + 0] + b0) * oscale;
                    float v1 = (c[rr * 2 + 1] + b1) * oscale;
                    uint32_t hi, lo;
                    split2(v0, v1, hi, lo);
                    *reinterpret_cast<uint32_t*>(&Yhi[idx]) = hi;
                    *reinterpret_cast<uint32_t*>(&Ylo[idx]) = lo;
                }
            } else {
                #pragma unroll
                for (int rr = 0; rr < 2; ++rr) {
                    const int row = row0 + rr * 8;
                    float* p = &Yf32[(size_t)row * C_ + col0];
                    p[0] = c[rr * 2 + 0] + b0;
                    p[1] = c[rr * 2 + 1] + b1;
                }
            }
        }
    }
}

__global__ __launch_bounds__(256, 2)
void mha_qkv_ps_kernel(const float* __restrict__ bq, const float* __restrict__ bk,
                       const float* __restrict__ bv)
{
    extern __shared__ __align__(16) char sm[];
    const int z = blockIdx.z;
    const __nv_bfloat16* Ahi = g_Xhi + (size_t)z * XSEG;
    const __nv_bfloat16* Alo = g_Xlo + (size_t)z * XSEG;
    const __nv_bfloat16* Bhi = g_Whi + (size_t)z * WSEG;
    const __nv_bfloat16* Blo = g_Wlo + (size_t)z * WSEG;
    const float* bias; __nv_bfloat16 *Yhi, *Ylo; float sc;
    if (z == 0)      { bias = bq; Yhi = g_Qhi; Ylo = g_Qlo; sc = QSCALE; }
    else if (z == 1) { bias = bk; Yhi = g_Khi; Ylo = g_Klo; sc = 1.0f; }
    else             { bias = bv; Yhi = g_Vhi; Ylo = g_Vlo; sc = 1.0f; }
    gemm_ps_tile(Ahi, Alo, Bhi, Blo, bias, nullptr, Yhi, Ylo, sc,
                 blockIdx.y * BM, blockIdx.x * BN, sm);
}

__global__ __launch_bounds__(256, 2)
void mha_out_ps_kernel(const float* __restrict__ bo, float* __restrict__ out)
{
    extern __shared__ __align__(16) char sm[];
    gemm_ps_tile(g_AOhi, g_AOlo, g_Whi + 3 * WSEG, g_Wlo + 3 * WSEG, bo,
                 out, nullptr, nullptr, 1.0f, blockIdx.y * BM, blockIdx.x * BN, sm);
}

// ---------------------------------------------------------------------------
// K2: tensor-core flash attention (round-10 version, unchanged)
// ---------------------------------------------------------------------------
__device__ __forceinline__ void issue_kv64(uint32_t dstbase, int tid,
                                           const __nv_bfloat16* kh, const __nv_bfloat16* kl,
                                           const __nv_bfloat16* vh, const __nv_bfloat16* vl)
{
    #pragma unroll
    for (int l = 0; l < 2; l++) {
        int cid = tid + l * 256;
        int row = cid >> 3, c8 = cid & 7;
        uint32_t off = (uint32_t)(row * APITCH + c8 * 16);
        const size_t g = (size_t)row * 64 + c8 * 8;
        cpa16(dstbase + off,             kh + g);
        cpa16(dstbase + KTILE + off,     kl + g);
        cpa16(dstbase + 2 * KTILE + off, vh + g);
        cpa16(dstbase + 3 * KTILE + off, vl + g);
    }
}

__global__ __launch_bounds__(256, 2)
void mha_attn_tc_kernel()
{
    extern __shared__ __align__(16) char sm[];
    const uint32_t sb = smem_u32(sm);
    const int tid = threadIdx.x;
    const int lane = tid & 31;
    const int wid = tid >> 5;
    const int bh = blockIdx.y;
    const int qt = blockIdx.x;

    const size_t hbase = (size_t)bh * N_ * D_;
    {
        const __nv_bfloat16* qh = g_Qhi + hbase + (size_t)qt * 128 * D_;
        const __nv_bfloat16* ql = g_Qlo + hbase + (size_t)qt * 128 * D_;
        #pragma unroll
        for (int l = 0; l < 4; l++) {
            int cid = tid + l * 256;
            int row = cid >> 3, c8 = cid & 7;
            const size_t g = (size_t)row * 64 + c8 * 8;
            uint32_t off = (uint32_t)(row * APITCH + c8 * 16);
            *reinterpret_cast<uint4*>(sm + off) = *reinterpret_cast<const uint4*>(qh + g);
            *reinterpret_cast<uint4*>(sm + QHALF + off) = *reinterpret_cast<const uint4*>(ql + g);
        }
    }

    issue_kv64(sb + 2 * QHALF, tid, g_Khi + hbase, g_Klo + hbase, g_Vhi + hbase, g_Vlo + hbase);
    cp_commit();

    float mA = -1e30f, mB = -1e30f, lA = 0.0f, lB = 0.0f;
    float oacc[8][4] = {};

    const uint32_t qrow = sb + (uint32_t)((wid * 16 + (lane & 15)) * APITCH + (lane >> 4) * 16);
    const uint32_t krow = (uint32_t)((((lane & 7) | ((lane & 16) >> 1)) * APITCH) + (lane & 8) * 2);
    const uint32_t vrow = (uint32_t)((lane & 15) * APITCH + (lane >> 4) * 16);

    constexpr int NKT = N_ / 64;   // 32
    for (int kt = 0; kt < NKT; ++kt) {
        cp_wait<0>();
        __syncthreads();
        if (kt + 1 < NKT) {
            issue_kv64(sb + 2 * QHALF + (uint32_t)((kt + 1) & 1) * KV_STAGE, tid,
                       g_Khi + hbase + (size_t)(kt + 1) * 64 * D_,
                       g_Klo + hbase + (size_t)(kt + 1) * 64 * D_,
                       g_Vhi + hbase + (size_t)(kt + 1) * 64 * D_,
                       g_Vlo + hbase + (size_t)(kt + 1) * 64 * D_);
        }
        cp_commit();

        const uint32_t kb = sb + 2 * QHALF + (uint32_t)(kt & 1) * KV_STAGE;
        const uint32_t Khs = kb, Kls = kb + KTILE, Vhs = kb + 2 * KTILE, Vls = kb + 3 * KTILE;

        float sacc[8][4] = {};
        #pragma unroll
        for (int ks = 0; ks < 4; ++ks) {
            uint32_t ah[4], al[4];
            ldm_x4(ah, qrow + ks * 32);
            ldm_x4(al, qrow + QHALF + ks * 32);
            #pragma unroll
            for (int t = 0; t < 4; ++t) {
                uint32_t bh4[4], bl4[4];
                ldm_x4(bh4, Khs + krow + t * 16 * APITCH + ks * 32);
                ldm_x4(bl4, Kls + krow + t * 16 * APITCH + ks * 32);
                mma16816(sacc[t * 2 + 0], ah, &bh4[0]);
                mma16816(sacc[t * 2 + 1], ah, &bh4[2]);
                mma16816(sacc[t * 2 + 0], ah, &bl4[0]);
                mma16816(sacc[t * 2 + 1], ah, &bl4[2]);
                mma16816(sacc[t * 2 + 0], al, &bh4[0]);
                mma16816(sacc[t * 2 + 1], al, &bh4[2]);
            }
        }

        float tA = -1e30f, tB = -1e30f;
        #pragma unroll
        for (int f = 0; f < 8; ++f) {
            tA = fmaxf(tA, fmaxf(sacc[f][0], sacc[f][1]));
            tB = fmaxf(tB, fmaxf(sacc[f][2], sacc[f][3]));
        }
        tA = fmaxf(tA, __shfl_xor_sync(0xffffffffu, tA, 1));
        tA = fmaxf(tA, __shfl_xor_sync(0xffffffffu, tA, 2));
        tB = fmaxf(tB, __shfl_xor_sync(0xffffffffu, tB, 1));
        tB = fmaxf(tB, __shfl_xor_sync(0xffffffffu, tB, 2));
        const float nmA = fmaxf(mA, tA), nmB = fmaxf(mB, tB);
        const float cA = ex2f(mA - nmA), cB = ex2f(mB - nmB);
        mA = nmA; mB = nmB;

        float psA = 0.0f, psB = 0.0f;
        #pragma unroll
        for (int f = 0; f < 8; ++f) {
            float p0 = ex2f(sacc[f][0] - mA);
            float p1 = ex2f(sacc[f][1] - mA);
            float p2 = ex2f(sacc[f][2] - mB);
            float p3 = ex2f(sacc[f][3] - mB);
            sacc[f][0] = p0; sacc[f][1] = p1; sacc[f][2] = p2; sacc[f][3] = p3;
            psA += p0 + p1; psB += p2 + p3;
        }
        lA = lA * cA + psA;
        lB = lB * cB + psB;
        #pragma unroll
        for (int nf = 0; nf < 8; ++nf) {
            oacc[nf][0] *= cA; oacc[nf][1] *= cA;
            oacc[nf][2] *= cB; oacc[nf][3] *= cB;
        }

        #pragma unroll
        for (int ks = 0; ks < 4; ++ks) {
            uint32_t phi[4], plo[4];
            split2(sacc[2 * ks][0],     sacc[2 * ks][1],     phi[0], plo[0]);
            split2(sacc[2 * ks][2],     sacc[2 * ks][3],     phi[1], plo[1]);
            split2(sacc[2 * ks + 1][0], sacc[2 * ks + 1][1], phi[2], plo[2]);
            split2(sacc[2 * ks + 1][2], sacc[2 * ks + 1][3], phi[3], plo[3]);
            const uint32_t vb = vrow + (uint32_t)(16 * ks * APITCH);
            #pragma unroll
            for (int dg = 0; dg < 4; ++dg) {
                uint32_t vh4[4], vl4[4];
                ldm_x4_t(vh4, Vhs + vb + dg * 32);
                ldm_x4_t(vl4, Vls + vb + dg * 32);
                mma16816(oacc[2 * dg],     phi, &vh4[0]);
                mma16816(oacc[2 * dg + 1], phi, &vh4[2]);
                mma16816(oacc[2 * dg],     phi, &vl4[0]);
                mma16816(oacc[2 * dg + 1], phi, &vl4[2]);
                mma16816(oacc[2 * dg],     plo, &vh4[0]);
                mma16816(oacc[2 * dg + 1], plo, &vh4[2]);
            }
        }
    }

    lA += __shfl_xor_sync(0xffffffffu, lA, 1);
    lA += __shfl_xor_sync(0xffffffffu, lA, 2);
    lB += __shfl_xor_sync(0xffffffffu, lB, 1);
    lB += __shfl_xor_sync(0xffffffffu, lB, 2);
    const float iA = 1.0f / lA, iB = 1.0f / lB;

    const int b = bh >> 4;
    const int h = bh & 15;
    const int rowA = qt * 128 + wid * 16 + (lane >> 2);
    #pragma unroll
    for (int nf = 0; nf < 8; ++nf) {
        const int d0 = nf * 8 + (lane & 3) * 2;
        const size_t iA0 = (size_t)(b * N_ + rowA) * C_ + h * 64 + d0;
        const size_t iB0 = (size_t)(b * N_ + rowA + 8) * C_ + h * 64 + d0;
        uint32_t hi, lo;
        split2(oacc[nf][0] * iA, oacc[nf][1] * iA, hi, lo);
        *reinterpret_cast<uint32_t*>(&g_AOhi[iA0]) = hi;
        *reinterpret_cast<uint32_t*>(&g_AOlo[iA0]) = lo;
        split2(oacc[nf][2] * iB, oacc[nf][3] * iB, hi, lo);
        *reinterpret_cast<uint32_t*>(&g_AOhi[iB0]) = hi;
        *reinterpret_cast<uint32_t*>(&g_AOlo[iB0]) = lo;
    }
}

// ---------------------------------------------------------------------------
extern "C" void kernel_launch(void* const* d_in, const int* in_sizes, int n_in,
                              void* d_out, int out_size)
{
    (void)in_sizes; (void)n_in; (void)out_size;
    const float* q  = (const float*)d_in[0];
    const float* k  = (const float*)d_in[1];
    const float* v  = (const float*)d_in[2];
    const float* wq = (const float*)d_in[3];
    const float* bq = (const float*)d_in[4];
    const float* wk = (const float*)d_in[5];
    const float* bk = (const float*)d_in[6];
    const float* wv = (const float*)d_in[7];
    const float* bv = (const float*)d_in[8];
    const float* wo = (const float*)d_in[9];
    const float* bo = (const float*)d_in[10];
    float* out = (float*)d_out;

    cudaFuncSetAttribute(mha_qkv_ps_kernel,
                         cudaFuncAttributeMaxDynamicSharedMemorySize, GEMM_SMEM);
    cudaFuncSetAttribute(mha_out_ps_kernel,
                         cudaFuncAttributeMaxDynamicSharedMemorySize, GEMM_SMEM);
    cudaFuncSetAttribute(mha_attn_tc_kernel,
                         cudaFuncAttributeMaxDynamicSharedMemorySize, ATTN_SMEM);

    dim3 gsplit(XSEG / 4 / 256, 7);
    split_convert_kernel<<<gsplit, 256>>>(q, k, v, wq, wk, wv, wo);

    dim3 gproj(C_ / BN, (B_ * N_) / BM, 3);   // 16 x 32 x 3
    mha_qkv_ps_kernel<<<gproj, 256, GEMM_SMEM>>>(bq, bk, bv);

    dim3 gattn(N_ / 128, B_ * H_);            // 16 x 32
    mha_attn_tc_kernel<<<gattn, 256, ATTN_SMEM>>>();

    dim3 gout(C_ / BN, (B_ * N_) / BM);       // 16 x 32
    mha_out_ps_kernel<<<gout, 256, GEMM_SMEM>>>(bo, out);
}

// round 12
// speedup vs baseline: 1.6292x; 1.4322x over previous
#include <cuda_runtime.h>
#include <cuda_fp16.h>
#include <cstdint>

// ---------------------------------------------------------------------------
// MultiheadAttention: b=2, n=2048, c=1024, h=16, d=64
// Round 12: fp16 asymmetric 2-term arithmetic (activations split hi/lo,
//   weights/K/V single fp16). 2 MMAs per product instead of 3.
// ---------------------------------------------------------------------------

namespace {
constexpr int B_ = 2;
constexpr int N_ = 2048;
constexpr int C_ = 1024;
constexpr int H_ = 16;
constexpr int D_ = 64;
constexpr float QSCALE = 0.125f * 1.44269504088896340736f;  // scale * log2(e)

constexpr int XSEG = 4096 * 1024;
constexpr int WSEG = 1024 * 1024;

// GEMM tiling: CTA tile 128(M) x 64(N), 8 warps (4Mx2N), warp tile 32x32.
// K-super 64, ring of 2 buffers, barrier per super, 2 CTAs/SM.
constexpr int BM = 128, BN = 64;
constexpr int GPITCH = 144;                    // 128 B data + 16 pad
constexpr int TILE_A = BM * GPITCH;            // 18432 B (A hi or lo)
constexpr int TILE_B = BN * GPITCH;            // 9216 B  (B single)
constexpr int SUPER_PS = 2 * TILE_A + TILE_B;  // 46080 B
constexpr int GEMM_SMEM = 2 * SUPER_PS;        // 92160 B -> 2 CTAs/SM
constexpr int NSUPER = C_ / 64;                // 16

// Attention tiling: Q hi/lo resident; K,V single fp16, double-buffered.
constexpr int APITCH = 144;
constexpr int QTILE = 128 * APITCH;            // 18432 B per Q half
constexpr int KTILE = 64 * APITCH;             // 9216 B (K or V, 64 rows)
constexpr int KV_STAGE = 2 * KTILE;            // 18432 B
constexpr int ATTN_SMEM = 2 * QTILE + 2 * KV_STAGE;  // 73728 B -> 2 CTAs/SM
}

// fp16 buffers
__device__ __half g_Xhi[3 * XSEG];
__device__ __half g_Xlo[3 * XSEG];
__device__ __half g_W[4 * WSEG];               // weights single fp16
// Head-layout projections
__device__ __half g_Qhi[B_ * H_ * N_ * D_];    // Q split (A operand of S)
__device__ __half g_Qlo[B_ * H_ * N_ * D_];
__device__ __half g_K1[B_ * H_ * N_ * D_];     // K single (B operand of S)
__device__ __half g_V1[B_ * H_ * N_ * D_];     // V single (B operand of PV)
// Attention output split (A operand of out-proj)
__device__ __half g_AOhi[XSEG];
__device__ __half g_AOlo[XSEG];

// ---------------------------------------------------------------------------
__device__ __forceinline__ uint32_t smem_u32(const void* p) {
    uint32_t a;
    asm("{ .reg .u64 t; cvta.to.shared.u64 t, %1; cvt.u32.u64 %0, t; }" : "=r"(a) : "l"(p));
    return a;
}
__device__ __forceinline__ void ldm_x4(uint32_t* r, uint32_t addr) {
    asm volatile("ldmatrix.sync.aligned.m8n8.x4.shared.b16 {%0,%1,%2,%3}, [%4];"
                 : "=r"(r[0]), "=r"(r[1]), "=r"(r[2]), "=r"(r[3]) : "r"(addr));
}
__device__ __forceinline__ void ldm_x4_t(uint32_t* r, uint32_t addr) {
    asm volatile("ldmatrix.sync.aligned.m8n8.x4.trans.shared.b16 {%0,%1,%2,%3}, [%4];"
                 : "=r"(r[0]), "=r"(r[1]), "=r"(r[2]), "=r"(r[3]) : "r"(addr));
}
__device__ __forceinline__ void mma16816(float* c, const uint32_t* a, const uint32_t* b) {
    asm volatile(
        "mma.sync.aligned.m16n8k16.row.col.f32.f16.f16.f32 "
        "{%0,%1,%2,%3}, {%4,%5,%6,%7}, {%8,%9}, {%0,%1,%2,%3};"
        : "+f"(c[0]), "+f"(c[1]), "+f"(c[2]), "+f"(c[3])
        : "r"(a[0]), "r"(a[1]), "r"(a[2]), "r"(a[3]), "r"(b[0]), "r"(b[1]));
}
__device__ __forceinline__ uint32_t pack_h2(float a, float b) {
    __half2 h = __floats2half2_rn(a, b);
    return *reinterpret_cast<uint32_t*>(&h);
}
__device__ __forceinline__ void split2h(float a, float b, uint32_t& hi, uint32_t& lo) {
    __half2 h = __floats2half2_rn(a, b);
    float2 f = __half22float2(h);
    __half2 l = __floats2half2_rn(a - f.x, b - f.y);
    hi = *reinterpret_cast<uint32_t*>(&h);
    lo = *reinterpret_cast<uint32_t*>(&l);
}
__device__ __forceinline__ float ex2f(float x) {
    float y;
    asm("ex2.approx.ftz.f32 %0, %1;" : "=f"(y) : "f"(x));
    return y;
}
__device__ __forceinline__ void cpa16(uint32_t dst, const void* src) {
    asm volatile("cp.async.cg.shared.global [%0], [%1], 16;" :: "r"(dst), "l"(src));
}
__device__ __forceinline__ void cp_commit() {
    asm volatile("cp.async.commit_group;" ::: "memory");
}
template <int n> __device__ __forceinline__ void cp_wait() {
    asm volatile("cp.async.wait_group %0;" :: "n"(n) : "memory");
}

// ---------------------------------------------------------------------------
// K0: converter. segs 0-2: X fp32 -> fp16 hi/lo. segs 3-6: W fp32 -> fp16.
// ---------------------------------------------------------------------------
__global__ __launch_bounds__(256)
void split_convert_kernel(const float* __restrict__ q, const float* __restrict__ k,
                          const float* __restrict__ v,
                          const float* __restrict__ wq, const float* __restrict__ wk,
                          const float* __restrict__ wv, const float* __restrict__ wo)
{
    const int seg = blockIdx.y;
    const int idx = blockIdx.x * 256 + threadIdx.x;

    if (seg < 3) {
        const float* src = (seg == 0) ? q : (seg == 1) ? k : v;
        __half* hi = g_Xhi + (size_t)seg * XSEG;
        __half* lo = g_Xlo + (size_t)seg * XSEG;
        if (idx >= XSEG / 4) return;
        float4 x = reinterpret_cast<const float4*>(src)[idx];
        uint32_t h01, l01, h23, l23;
        split2h(x.x, x.y, h01, l01);
        split2h(x.z, x.w, h23, l23);
        reinterpret_cast<uint2*>(hi)[idx] = make_uint2(h01, h23);
        reinterpret_cast<uint2*>(lo)[idx] = make_uint2(l01, l23);
    } else {
        const int w = seg - 3;
        const float* src = (w == 0) ? wq : (w == 1) ? wk : (w == 2) ? wv : wo;
        __half* dst = g_W + (size_t)w * WSEG;
        if (idx >= WSEG / 4) return;
        float4 x = reinterpret_cast<const float4*>(src)[idx];
        reinterpret_cast<uint2*>(dst)[idx] =
            make_uint2(pack_h2(x.x, x.y), pack_h2(x.z, x.w));
    }
}

// ---------------------------------------------------------------------------
// GEMM tile: Y = (Ahi+Alo) @ W^T + bias. 256 threads, 8 warps (4Mx2N),
// warp tile 32x32, K-super 64, one barrier per super.
// outMode: 0 = head-layout split (Q), 1 = head-layout single (K/V),
//          2 = flat fp32 (out-proj), 3 = flat split (AO -- unused here)
// ---------------------------------------------------------------------------
__device__ __forceinline__ void gemm_h2_tile(
    const __half* __restrict__ Ahi, const __half* __restrict__ Alo,
    const __half* __restrict__ Bs,
    const float* __restrict__ bias,
    float* __restrict__ Yf32, __half* __restrict__ Yhi, __half* __restrict__ Ylo,
    float oscale, int outMode, int rowBase, int colBase, char* sm)
{
    const int tid = threadIdx.x;
    const int lane = tid & 31;
    const int wid = tid >> 5;
    const int warp_m = wid & 3;
    const int warp_n = wid >> 2;
    const uint32_t sb = smem_u32(sm);

    float acc[2][4][4] = {};

    const uint32_t aRow = (uint32_t)(warp_m * 32 + (lane & 15)) * GPITCH + (uint32_t)(lane & 16);
    const uint32_t bRow = (uint32_t)(warp_n * 32 + ((lane & 7) | ((lane & 16) >> 1))) * GPITCH
                          + (uint32_t)((lane & 8) * 2);

    auto load_super = [&](int k0, int buf) {
        const uint32_t base = sb + (uint32_t)buf * SUPER_PS;
        #pragma unroll
        for (int l = 0; l < 4; ++l) {
            const int id = tid + l * 256;            // 128 rows x 8 chunks
            const int r = id >> 3, c = id & 7;
            const uint32_t off = (uint32_t)(r * GPITCH + c * 16);
            const size_t ga = (size_t)(rowBase + r) * C_ + k0 + c * 8;
            cpa16(base + off,          Ahi + ga);
            cpa16(base + TILE_A + off, Alo + ga);
        }
        #pragma unroll
        for (int l = 0; l < 2; ++l) {
            const int id = tid + l * 256;            // 64 rows x 8 chunks
            const int r = id >> 3, c = id & 7;
            const uint32_t off = (uint32_t)(r * GPITCH + c * 16);
            const size_t gb = (size_t)(colBase + r) * C_ + k0 + c * 8;
            cpa16(base + 2 * TILE_A + off, Bs + gb);
        }
    };

    load_super(0, 0);
    cp_commit();

    for (int s = 0; s < NSUPER; ++s) {
        cp_wait<0>();
        __syncthreads();
        if (s + 1 < NSUPER) load_super((s + 1) * 64, (s + 1) & 1);
        cp_commit();

        const uint32_t stB = sb + (uint32_t)(s & 1) * SUPER_PS;
        const uint32_t sB = stB + 2 * TILE_A;
        #pragma unroll
        for (int ks = 0; ks < 4; ++ks) {
            uint32_t ah[2][4], al[2][4];
            ldm_x4(ah[0], stB + aRow + ks * 32);
            ldm_x4(ah[1], stB + aRow + 16 * GPITCH + ks * 32);
            ldm_x4(al[0], stB + TILE_A + aRow + ks * 32);
            ldm_x4(al[1], stB + TILE_A + aRow + 16 * GPITCH + ks * 32);
            #pragma unroll
            for (int t = 0; t < 2; ++t) {
                uint32_t b4[4];
                ldm_x4(b4, sB + bRow + t * 16 * GPITCH + ks * 32);
                #pragma unroll
                for (int f = 0; f < 2; ++f)
                    #pragma unroll
                    for (int sub = 0; sub < 2; ++sub)
                        mma16816(acc[f][t * 2 + sub], ah[f], &b4[2 * sub]);
                #pragma unroll
                for (int f = 0; f < 2; ++f)
                    #pragma unroll
                    for (int sub = 0; sub < 2; ++sub)
                        mma16816(acc[f][t * 2 + sub], al[f], &b4[2 * sub]);
            }
        }
    }

    const int r = lane >> 2;
    const int cc = (lane & 3) * 2;
    #pragma unroll
    for (int f = 0; f < 2; ++f) {
        #pragma unroll
        for (int nf = 0; nf < 4; ++nf) {
            const float* c = acc[f][nf];
            const int col0 = colBase + warp_n * 32 + nf * 8 + cc;
            const int row0 = rowBase + warp_m * 32 + f * 16 + r;
            const float b0 = bias[col0], b1 = bias[col0 + 1];
            #pragma unroll
            for (int rr = 0; rr < 2; ++rr) {
                const int row = row0 + rr * 8;
                const float v0 = (c[rr * 2 + 0] + b0) * oscale;
                const float v1 = (c[rr * 2 + 1] + b1) * oscale;
                if (outMode == 2) {
                    float* p = &Yf32[(size_t)row * C_ + col0];
                    p[0] = v0; p[1] = v1;
                } else {
                    const int bb = row >> 11, i = row & (N_ - 1);
                    const int h = col0 >> 6, dd = col0 & 63;
                    const size_t idx = ((size_t)(bb * H_ + h) * N_ + i) * D_ + dd;
                    if (outMode == 0) {
                        uint32_t hi, lo;
                        split2h(v0, v1, hi, lo);
                        *reinterpret_cast<uint32_t*>(&Yhi[idx]) = hi;
                        *reinterpret_cast<uint32_t*>(&Ylo[idx]) = lo;
                    } else {
                        *reinterpret_cast<uint32_t*>(&Yhi[idx]) = pack_h2(v0, v1);
                    }
                }
            }
        }
    }
}

__global__ __launch_bounds__(256, 2)
void mha_qkv_ps_kernel(const float* __restrict__ bq, const float* __restrict__ bk,
                       const float* __restrict__ bv)
{
    extern __shared__ __align__(16) char sm[];
    const int z = blockIdx.z;
    const __half* Ahi = g_Xhi + (size_t)z * XSEG;
    const __half* Alo = g_Xlo + (size_t)z * XSEG;
    const __half* Bs  = g_W + (size_t)z * WSEG;
    if (z == 0) {
        gemm_h2_tile(Ahi, Alo, Bs, bq, nullptr, g_Qhi, g_Qlo, QSCALE, 0,
                     blockIdx.y * BM, blockIdx.x * BN, sm);
    } else if (z == 1) {
        gemm_h2_tile(Ahi, Alo, Bs, bk, nullptr, g_K1, nullptr, 1.0f, 1,
                     blockIdx.y * BM, blockIdx.x * BN, sm);
    } else {
        gemm_h2_tile(Ahi, Alo, Bs, bv, nullptr, g_V1, nullptr, 1.0f, 1,
                     blockIdx.y * BM, blockIdx.x * BN, sm);
    }
}

__global__ __launch_bounds__(256, 2)
void mha_out_ps_kernel(const float* __restrict__ bo, float* __restrict__ out)
{
    extern __shared__ __align__(16) char sm[];
    gemm_h2_tile(g_AOhi, g_AOlo, g_W + 3 * WSEG, bo, out, nullptr, nullptr,
                 1.0f, 2, blockIdx.y * BM, blockIdx.x * BN, sm);
}

// ---------------------------------------------------------------------------
// K2: fp16 tensor-core flash attention. Q split (A), K/V single (B).
// ---------------------------------------------------------------------------
__device__ __forceinline__ void issue_kv(uint32_t dstbase, int tid,
                                         const __half* kk, const __half* vv)
{
    #pragma unroll
    for (int l = 0; l < 2; l++) {
        int cid = tid + l * 256;                 // 64 rows x 8 chunks
        int row = cid >> 3, c8 = cid & 7;
        uint32_t off = (uint32_t)(row * APITCH + c8 * 16);
        const size_t g = (size_t)row * 64 + c8 * 8;
        cpa16(dstbase + off,         kk + g);
        cpa16(dstbase + KTILE + off, vv + g);
    }
}

__global__ __launch_bounds__(256, 2)
void mha_attn_tc_kernel()
{
    extern __shared__ __align__(16) char sm[];
    const uint32_t sb = smem_u32(sm);
    const int tid = threadIdx.x;
    const int lane = tid & 31;
    const int wid = tid >> 5;
    const int bh = blockIdx.y;
    const int qt = blockIdx.x;

    const size_t hbase = (size_t)bh * N_ * D_;
    {
        const __half* qh = g_Qhi + hbase + (size_t)qt * 128 * D_;
        const __half* ql = g_Qlo + hbase + (size_t)qt * 128 * D_;
        #pragma unroll
        for (int l = 0; l < 4; l++) {
            int cid = tid + l * 256;
            int row = cid >> 3, c8 = cid & 7;
            const size_t g = (size_t)row * 64 + c8 * 8;
            uint32_t off = (uint32_t)(row * APITCH + c8 * 16);
            *reinterpret_cast<uint4*>(sm + off) = *reinterpret_cast<const uint4*>(qh + g);
            *reinterpret_cast<uint4*>(sm + QTILE + off) = *reinterpret_cast<const uint4*>(ql + g);
        }
    }

    issue_kv(sb + 2 * QTILE, tid, g_K1 + hbase, g_V1 + hbase);
    cp_commit();

    float mA = -1e30f, mB = -1e30f, lA = 0.0f, lB = 0.0f;
    float oacc[8][4] = {};

    const uint32_t qrow = sb + (uint32_t)((wid * 16 + (lane & 15)) * APITCH + (lane >> 4) * 16);
    const uint32_t krow = (uint32_t)((((lane & 7) | ((lane & 16) >> 1)) * APITCH) + (lane & 8) * 2);
    const uint32_t vrow = (uint32_t)((lane & 15) * APITCH + (lane >> 4) * 16);

    constexpr int NKT = N_ / 64;   // 32
    for (int kt = 0; kt < NKT; ++kt) {
        cp_wait<0>();
        __syncthreads();
        if (kt + 1 < NKT) {
            issue_kv(sb + 2 * QTILE + (uint32_t)((kt + 1) & 1) * KV_STAGE, tid,
                     g_K1 + hbase + (size_t)(kt + 1) * 64 * D_,
                     g_V1 + hbase + (size_t)(kt + 1) * 64 * D_);
        }
        cp_commit();

        const uint32_t kb = sb + 2 * QTILE + (uint32_t)(kt & 1) * KV_STAGE;
        const uint32_t Ks = kb, Vs = kb + KTILE;

        // S (16 q-rows x 64 keys), log2 domain
        float sacc[8][4] = {};
        #pragma unroll
        for (int ks = 0; ks < 4; ++ks) {
            uint32_t qh4[4], ql4[4];
            ldm_x4(qh4, qrow + ks * 32);
            ldm_x4(ql4, qrow + QTILE + ks * 32);
            #pragma unroll
            for (int t = 0; t < 4; ++t) {
                uint32_t k4[4];
                ldm_x4(k4, Ks + krow + t * 16 * APITCH + ks * 32);
                mma16816(sacc[t * 2 + 0], qh4, &k4[0]);
                mma16816(sacc[t * 2 + 1], qh4, &k4[2]);
                mma16816(sacc[t * 2 + 0], ql4, &k4[0]);
                mma16816(sacc[t * 2 + 1], ql4, &k4[2]);
            }
        }

        // Online softmax (base-2)
        float tA = -1e30f, tB = -1e30f;
        #pragma unroll
        for (int f = 0; f < 8; ++f) {
            tA = fmaxf(tA, fmaxf(sacc[f][0], sacc[f][1]));
            tB = fmaxf(tB, fmaxf(sacc[f][2], sacc[f][3]));
        }
        tA = fmaxf(tA, __shfl_xor_sync(0xffffffffu, tA, 1));
        tA = fmaxf(tA, __shfl_xor_sync(0xffffffffu, tA, 2));
        tB = fmaxf(tB, __shfl_xor_sync(0xffffffffu, tB, 1));
        tB = fmaxf(tB, __shfl_xor_sync(0xffffffffu, tB, 2));
        const float nmA = fmaxf(mA, tA), nmB = fmaxf(mB, tB);
        const float cA = ex2f(mA - nmA), cB = ex2f(mB - nmB);
        mA = nmA; mB = nmB;

        float psA = 0.0f, psB = 0.0f;
        #pragma unroll
        for (int f = 0; f < 8; ++f) {
            float p0 = ex2f(sacc[f][0] - mA);
            float p1 = ex2f(sacc[f][1] - mA);
            float p2 = ex2f(sacc[f][2] - mB);
            float p3 = ex2f(sacc[f][3] - mB);
            sacc[f][0] = p0; sacc[f][1] = p1; sacc[f][2] = p2; sacc[f][3] = p3;
            psA += p0 + p1; psB += p2 + p3;
        }
        lA = lA * cA + psA;
        lB = lB * cB + psB;
        #pragma unroll
        for (int nf = 0; nf < 8; ++nf) {
            oacc[nf][0] *= cA; oacc[nf][1] *= cA;
            oacc[nf][2] *= cB; oacc[nf][3] *= cB;
        }

        // O += P @ V  (P split hi/lo fp16, V single)
        #pragma unroll
        for (int ks = 0; ks < 4; ++ks) {
            uint32_t phi[4], plo[4];
            split2h(sacc[2 * ks][0],     sacc[2 * ks][1],     phi[0], plo[0]);
            split2h(sacc[2 * ks][2],     sacc[2 * ks][3],     phi[1], plo[1]);
            split2h(sacc[2 * ks + 1][0], sacc[2 * ks + 1][1], phi[2], plo[2]);
            split2h(sacc[2 * ks + 1][2], sacc[2 * ks + 1][3], phi[3], plo[3]);
            const uint32_t vb = vrow + (uint32_t)(16 * ks * APITCH);
            #pragma unroll
            for (int dg = 0; dg < 4; ++dg) {
                uint32_t v4[4];
                ldm_x4_t(v4, Vs + vb + dg * 32);
                mma16816(oacc[2 * dg],     phi, &v4[0]);
                mma16816(oacc[2 * dg + 1], phi, &v4[2]);
                mma16816(oacc[2 * dg],     plo, &v4[0]);
                mma16816(oacc[2 * dg + 1], plo, &v4[2]);
            }
        }
    }

    lA += __shfl_xor_sync(0xffffffffu, lA, 1);
    lA += __shfl_xor_sync(0xffffffffu, lA, 2);
    lB += __shfl_xor_sync(0xffffffffu, lB, 1);
    lB += __shfl_xor_sync(0xffffffffu, lB, 2);
    const float iA = 1.0f / lA, iB = 1.0f / lB;

    const int b = bh >> 4;
    const int h = bh & 15;
    const int rowA = qt * 128 + wid * 16 + (lane >> 2);
    #pragma unroll
    for (int nf = 0; nf < 8; ++nf) {
        const int d0 = nf * 8 + (lane & 3) * 2;
        const size_t iA0 = (size_t)(b * N_ + rowA) * C_ + h * 64 + d0;
        const size_t iB0 = (size_t)(b * N_ + rowA + 8) * C_ + h * 64 + d0;
        uint32_t hi, lo;
        split2h(oacc[nf][0] * iA, oacc[nf][1] * iA, hi, lo);
        *reinterpret_cast<uint32_t*>(&g_AOhi[iA0]) = hi;
        *reinterpret_cast<uint32_t*>(&g_AOlo[iA0]) = lo;
        split2h(oacc[nf][2] * iB, oacc[nf][3] * iB, hi, lo);
        *reinterpret_cast<uint32_t*>(&g_AOhi[iB0]) = hi;
        *reinterpret_cast<uint32_t*>(&g_AOlo[iB0]) = lo;
    }
}

// ---------------------------------------------------------------------------
extern "C" void kernel_launch(void* const* d_in, const int* in_sizes, int n_in,
                              void* d_out, int out_size)
{
    (void)in_sizes; (void)n_in; (void)out_size;
    const float* q  = (const float*)d_in[0];
    const float* k  = (const float*)d_in[1];
    const float* v  = (const float*)d_in[2];
    const float* wq = (const float*)d_in[3];
    const float* bq = (const float*)d_in[4];
    const float* wk = (const float*)d_in[5];
    const float* bk = (const float*)d_in[6];
    const float* wv = (const float*)d_in[7];
    const float* bv = (const float*)d_in[8];
    const float* wo = (const float*)d_in[9];
    const float* bo = (const float*)d_in[10];
    float* out = (float*)d_out;

    cudaFuncSetAttribute(mha_qkv_ps_kernel,
                         cudaFuncAttributeMaxDynamicSharedMemorySize, GEMM_SMEM);
    cudaFuncSetAttribute(mha_out_ps_kernel,
                         cudaFuncAttributeMaxDynamicSharedMemorySize, GEMM_SMEM);
    cudaFuncSetAttribute(mha_attn_tc_kernel,
                         cudaFuncAttributeMaxDynamicSharedMemorySize, ATTN_SMEM);

    dim3 gsplit(XSEG / 4 / 256, 7);           // 4096 x 7 (W segs exit early)
    split_convert_kernel<<<gsplit, 256>>>(q, k, v, wq, wk, wv, wo);

    dim3 gproj(C_ / BN, (B_ * N_) / BM, 3);   // 16 x 32 x 3
    mha_qkv_ps_kernel<<<gproj, 256, GEMM_SMEM>>>(bq, bk, bv);

    dim3 gattn(N_ / 128, B_ * H_);            // 16 x 32
    mha_attn_tc_kernel<<<gattn, 256, ATTN_SMEM>>>();

    dim3 gout(C_ / BN, (B_ * N_) / BM);       // 16 x 32
    mha_out_ps_kernel<<<gout, 256, GEMM_SMEM>>>(bo, out);
}

// round 13
// speedup vs baseline: 1.8980x; 1.1649x over previous
#include <cuda_runtime.h>
#include <cuda_fp16.h>
#include <cstdint>

// ---------------------------------------------------------------------------
// MultiheadAttention: b=2, n=2048, c=1024, h=16, d=64
// Round 13: GEMM CTA tile 128x128 (halved A traffic, 128 MMAs/barrier,
//   fewer CTAs/waves); attention PV uses hi-only P (1 MMA per product).
// ---------------------------------------------------------------------------

namespace {
constexpr int B_ = 2;
constexpr int N_ = 2048;
constexpr int C_ = 1024;
constexpr int H_ = 16;
constexpr int D_ = 64;
constexpr float QSCALE = 0.125f * 1.44269504088896340736f;  // scale * log2(e)

constexpr int XSEG = 4096 * 1024;
constexpr int WSEG = 1024 * 1024;

// GEMM tiling: CTA tile 128(M) x 128(N), 8 warps (4Mx2N), warp tile 32x64.
// K-super 64, ring of 2 buffers, barrier per super, 2 CTAs/SM.
constexpr int BM = 128, BN = 128;
constexpr int GPITCH = 144;                    // 128 B data + 16 pad
constexpr int TILE_A = BM * GPITCH;            // 18432 B (A hi or lo)
constexpr int TILE_B = BN * GPITCH;            // 18432 B (B single)
constexpr int SUPER_PS = 2 * TILE_A + TILE_B;  // 55296 B
constexpr int GEMM_SMEM = 2 * SUPER_PS;        // 110592 B -> 2 CTAs/SM
constexpr int NSUPER = C_ / 64;                // 16

// Attention tiling: Q hi/lo resident; K,V single fp16, double-buffered.
constexpr int APITCH = 144;
constexpr int QTILE = 128 * APITCH;            // 18432 B per Q half
constexpr int KTILE = 64 * APITCH;             // 9216 B (K or V, 64 rows)
constexpr int KV_STAGE = 2 * KTILE;            // 18432 B
constexpr int ATTN_SMEM = 2 * QTILE + 2 * KV_STAGE;  // 73728 B -> 2 CTAs/SM
}

// fp16 buffers
__device__ __half g_Xhi[3 * XSEG];
__device__ __half g_Xlo[3 * XSEG];
__device__ __half g_W[4 * WSEG];               // weights single fp16
// Head-layout projections
__device__ __half g_Qhi[B_ * H_ * N_ * D_];
__device__ __half g_Qlo[B_ * H_ * N_ * D_];
__device__ __half g_K1[B_ * H_ * N_ * D_];
__device__ __half g_V1[B_ * H_ * N_ * D_];
// Attention output split (A operand of out-proj)
__device__ __half g_AOhi[XSEG];
__device__ __half g_AOlo[XSEG];

// ---------------------------------------------------------------------------
__device__ __forceinline__ uint32_t smem_u32(const void* p) {
    uint32_t a;
    asm("{ .reg .u64 t; cvta.to.shared.u64 t, %1; cvt.u32.u64 %0, t; }" : "=r"(a) : "l"(p));
    return a;
}
__device__ __forceinline__ void ldm_x4(uint32_t* r, uint32_t addr) {
    asm volatile("ldmatrix.sync.aligned.m8n8.x4.shared.b16 {%0,%1,%2,%3}, [%4];"
                 : "=r"(r[0]), "=r"(r[1]), "=r"(r[2]), "=r"(r[3]) : "r"(addr));
}
__device__ __forceinline__ void ldm_x4_t(uint32_t* r, uint32_t addr) {
    asm volatile("ldmatrix.sync.aligned.m8n8.x4.trans.shared.b16 {%0,%1,%2,%3}, [%4];"
                 : "=r"(r[0]), "=r"(r[1]), "=r"(r[2]), "=r"(r[3]) : "r"(addr));
}
__device__ __forceinline__ void mma16816(float* c, const uint32_t* a, const uint32_t* b) {
    asm volatile(
        "mma.sync.aligned.m16n8k16.row.col.f32.f16.f16.f32 "
        "{%0,%1,%2,%3}, {%4,%5,%6,%7}, {%8,%9}, {%0,%1,%2,%3};"
        : "+f"(c[0]), "+f"(c[1]), "+f"(c[2]), "+f"(c[3])
        : "r"(a[0]), "r"(a[1]), "r"(a[2]), "r"(a[3]), "r"(b[0]), "r"(b[1]));
}
__device__ __forceinline__ uint32_t pack_h2(float a, float b) {
    __half2 h = __floats2half2_rn(a, b);
    return *reinterpret_cast<uint32_t*>(&h);
}
__device__ __forceinline__ void split2h(float a, float b, uint32_t& hi, uint32_t& lo) {
    __half2 h = __floats2half2_rn(a, b);
    float2 f = __half22float2(h);
    __half2 l = __floats2half2_rn(a - f.x, b - f.y);
    hi = *reinterpret_cast<uint32_t*>(&h);
    lo = *reinterpret_cast<uint32_t*>(&l);
}
__device__ __forceinline__ float ex2f(float x) {
    float y;
    asm("ex2.approx.ftz.f32 %0, %1;" : "=f"(y) : "f"(x));
    return y;
}
__device__ __forceinline__ void cpa16(uint32_t dst, const void* src) {
    asm volatile("cp.async.cg.shared.global [%0], [%1], 16;" :: "r"(dst), "l"(src));
}
__device__ __forceinline__ void cp_commit() {
    asm volatile("cp.async.commit_group;" ::: "memory");
}
template <int n> __device__ __forceinline__ void cp_wait() {
    asm volatile("cp.async.wait_group %0;" :: "n"(n) : "memory");
}

// ---------------------------------------------------------------------------
// K0: converter. segs 0-2: X fp32 -> fp16 hi/lo. segs 3-6: W fp32 -> fp16.
// ---------------------------------------------------------------------------
__global__ __launch_bounds__(256)
void split_convert_kernel(const float* __restrict__ q, const float* __restrict__ k,
                          const float* __restrict__ v,
                          const float* __restrict__ wq, const float* __restrict__ wk,
                          const float* __restrict__ wv, const float* __restrict__ wo)
{
    const int seg = blockIdx.y;
    const int idx = blockIdx.x * 256 + threadIdx.x;

    if (seg < 3) {
        const float* src = (seg == 0) ? q : (seg == 1) ? k : v;
        __half* hi = g_Xhi + (size_t)seg * XSEG;
        __half* lo = g_Xlo + (size_t)seg * XSEG;
        if (idx >= XSEG / 4) return;
        float4 x = reinterpret_cast<const float4*>(src)[idx];
        uint32_t h01, l01, h23, l23;
        split2h(x.x, x.y, h01, l01);
        split2h(x.z, x.w, h23, l23);
        reinterpret_cast<uint2*>(hi)[idx] = make_uint2(h01, h23);
        reinterpret_cast<uint2*>(lo)[idx] = make_uint2(l01, l23);
    } else {
        const int w = seg - 3;
        const float* src = (w == 0) ? wq : (w == 1) ? wk : (w == 2) ? wv : wo;
        __half* dst = g_W + (size_t)w * WSEG;
        if (idx >= WSEG / 4) return;
        float4 x = reinterpret_cast<const float4*>(src)[idx];
        reinterpret_cast<uint2*>(dst)[idx] =
            make_uint2(pack_h2(x.x, x.y), pack_h2(x.z, x.w));
    }
}

// ---------------------------------------------------------------------------
// GEMM tile: Y = (Ahi+Alo) @ W^T + bias. 256 threads, 8 warps (4Mx2N),
// warp tile 32x64, K-super 64, one barrier per super.
// outMode: 0 = head-layout split (Q), 1 = head-layout single (K/V),
//          2 = flat fp32 (out-proj)
// ---------------------------------------------------------------------------
__device__ __forceinline__ void gemm_h2_tile(
    const __half* __restrict__ Ahi, const __half* __restrict__ Alo,
    const __half* __restrict__ Bs,
    const float* __restrict__ bias,
    float* __restrict__ Yf32, __half* __restrict__ Yhi, __half* __restrict__ Ylo,
    float oscale, int outMode, int rowBase, int colBase, char* sm)
{
    const int tid = threadIdx.x;
    const int lane = tid & 31;
    const int wid = tid >> 5;
    const int warp_m = wid & 3;        // 4 x 32 rows
    const int warp_n = wid >> 2;       // 2 x 64 cols
    const uint32_t sb = smem_u32(sm);

    float acc[2][8][4] = {};

    const uint32_t aRow = (uint32_t)(warp_m * 32 + (lane & 15)) * GPITCH + (uint32_t)(lane & 16);
    const uint32_t bRow = (uint32_t)(warp_n * 64 + ((lane & 7) | ((lane & 16) >> 1))) * GPITCH
                          + (uint32_t)((lane & 8) * 2);

    auto load_super = [&](int k0, int buf) {
        const uint32_t base = sb + (uint32_t)buf * SUPER_PS;
        #pragma unroll
        for (int l = 0; l < 4; ++l) {
            const int id = tid + l * 256;            // 128 rows x 8 chunks
            const int r = id >> 3, c = id & 7;
            const uint32_t off = (uint32_t)(r * GPITCH + c * 16);
            const size_t ga = (size_t)(rowBase + r) * C_ + k0 + c * 8;
            cpa16(base + off,          Ahi + ga);
            cpa16(base + TILE_A + off, Alo + ga);
        }
        #pragma unroll
        for (int l = 0; l < 4; ++l) {
            const int id = tid + l * 256;            // 128 rows x 8 chunks
            const int r = id >> 3, c = id & 7;
            const uint32_t off = (uint32_t)(r * GPITCH + c * 16);
            const size_t gb = (size_t)(colBase + r) * C_ + k0 + c * 8;
            cpa16(base + 2 * TILE_A + off, Bs + gb);
        }
    };

    load_super(0, 0);
    cp_commit();

    for (int s = 0; s < NSUPER; ++s) {
        cp_wait<0>();
        __syncthreads();
        if (s + 1 < NSUPER) load_super((s + 1) * 64, (s + 1) & 1);
        cp_commit();

        const uint32_t stB = sb + (uint32_t)(s & 1) * SUPER_PS;
        const uint32_t sB = stB + 2 * TILE_A;
        #pragma unroll
        for (int ks = 0; ks < 4; ++ks) {
            uint32_t ah[2][4], al[2][4];
            ldm_x4(ah[0], stB + aRow + ks * 32);
            ldm_x4(ah[1], stB + aRow + 16 * GPITCH + ks * 32);
            ldm_x4(al[0], stB + TILE_A + aRow + ks * 32);
            ldm_x4(al[1], stB + TILE_A + aRow + 16 * GPITCH + ks * 32);
            #pragma unroll
            for (int t = 0; t < 4; ++t) {
                uint32_t b4[4];
                ldm_x4(b4, sB + bRow + t * 16 * GPITCH + ks * 32);
                #pragma unroll
                for (int f = 0; f < 2; ++f)
                    #pragma unroll
                    for (int sub = 0; sub < 2; ++sub)
                        mma16816(acc[f][t * 2 + sub], ah[f], &b4[2 * sub]);
                #pragma unroll
                for (int f = 0; f < 2; ++f)
                    #pragma unroll
                    for (int sub = 0; sub < 2; ++sub)
                        mma16816(acc[f][t * 2 + sub], al[f], &b4[2 * sub]);
            }
        }
    }

    const int r = lane >> 2;
    const int cc = (lane & 3) * 2;
    #pragma unroll
    for (int f = 0; f < 2; ++f) {
        #pragma unroll
        for (int nf = 0; nf < 8; ++nf) {
            const float* c = acc[f][nf];
            const int col0 = colBase + warp_n * 64 + nf * 8 + cc;
            const int row0 = rowBase + warp_m * 32 + f * 16 + r;
            const float b0 = bias[col0], b1 = bias[col0 + 1];
            #pragma unroll
            for (int rr = 0; rr < 2; ++rr) {
                const int row = row0 + rr * 8;
                const float v0 = (c[rr * 2 + 0] + b0) * oscale;
                const float v1 = (c[rr * 2 + 1] + b1) * oscale;
                if (outMode == 2) {
                    float* p = &Yf32[(size_t)row * C_ + col0];
                    p[0] = v0; p[1] = v1;
                } else {
                    const int bb = row >> 11, i = row & (N_ - 1);
                    const int h = col0 >> 6, dd = col0 & 63;
                    const size_t idx = ((size_t)(bb * H_ + h) * N_ + i) * D_ + dd;
                    if (outMode == 0) {
                        uint32_t hi, lo;
                        split2h(v0, v1, hi, lo);
                        *reinterpret_cast<uint32_t*>(&Yhi[idx]) = hi;
                        *reinterpret_cast<uint32_t*>(&Ylo[idx]) = lo;
                    } else {
                        *reinterpret_cast<uint32_t*>(&Yhi[idx]) = pack_h2(v0, v1);
                    }
                }
            }
        }
    }
}

__global__ __launch_bounds__(256, 2)
void mha_qkv_ps_kernel(const float* __restrict__ bq, const float* __restrict__ bk,
                       const float* __restrict__ bv)
{
    extern __shared__ __align__(16) char sm[];
    const int z = blockIdx.z;
    const __half* Ahi = g_Xhi + (size_t)z * XSEG;
    const __half* Alo = g_Xlo + (size_t)z * XSEG;
    const __half* Bs  = g_W + (size_t)z * WSEG;
    if (z == 0) {
        gemm_h2_tile(Ahi, Alo, Bs, bq, nullptr, g_Qhi, g_Qlo, QSCALE, 0,
                     blockIdx.y * BM, blockIdx.x * BN, sm);
    } else if (z == 1) {
        gemm_h2_tile(Ahi, Alo, Bs, bk, nullptr, g_K1, nullptr, 1.0f, 1,
                     blockIdx.y * BM, blockIdx.x * BN, sm);
    } else {
        gemm_h2_tile(Ahi, Alo, Bs, bv, nullptr, g_V1, nullptr, 1.0f, 1,
                     blockIdx.y * BM, blockIdx.x * BN, sm);
    }
}

__global__ __launch_bounds__(256, 2)
void mha_out_ps_kernel(const float* __restrict__ bo, float* __restrict__ out)
{
    extern __shared__ __align__(16) char sm[];
    gemm_h2_tile(g_AOhi, g_AOlo, g_W + 3 * WSEG, bo, out, nullptr, nullptr,
                 1.0f, 2, blockIdx.y * BM, blockIdx.x * BN, sm);
}

// ---------------------------------------------------------------------------
// K2: fp16 tensor-core flash attention. Q split (A), K/V single; P hi-only.
// ---------------------------------------------------------------------------
__device__ __forceinline__ void issue_kv(uint32_t dstbase, int tid,
                                         const __half* kk, const __half* vv)
{
    #pragma unroll
    for (int l = 0; l < 2; l++) {
        int cid = tid + l * 256;
        int row = cid >> 3, c8 = cid & 7;
        uint32_t off = (uint32_t)(row * APITCH + c8 * 16);
        const size_t g = (size_t)row * 64 + c8 * 8;
        cpa16(dstbase + off,         kk + g);
        cpa16(dstbase + KTILE + off, vv + g);
    }
}

__global__ __launch_bounds__(256, 2)
void mha_attn_tc_kernel()
{
    extern __shared__ __align__(16) char sm[];
    const uint32_t sb = smem_u32(sm);
    const int tid = threadIdx.x;
    const int lane = tid & 31;
    const int wid = tid >> 5;
    const int bh = blockIdx.y;
    const int qt = blockIdx.x;

    const size_t hbase = (size_t)bh * N_ * D_;
    {
        const __half* qh = g_Qhi + hbase + (size_t)qt * 128 * D_;
        const __half* ql = g_Qlo + hbase + (size_t)qt * 128 * D_;
        #pragma unroll
        for (int l = 0; l < 4; l++) {
            int cid = tid + l * 256;
            int row = cid >> 3, c8 = cid & 7;
            const size_t g = (size_t)row * 64 + c8 * 8;
            uint32_t off = (uint32_t)(row * APITCH + c8 * 16);
            *reinterpret_cast<uint4*>(sm + off) = *reinterpret_cast<const uint4*>(qh + g);
            *reinterpret_cast<uint4*>(sm + QTILE + off) = *reinterpret_cast<const uint4*>(ql + g);
        }
    }

    issue_kv(sb + 2 * QTILE, tid, g_K1 + hbase, g_V1 + hbase);
    cp_commit();

    float mA = -1e30f, mB = -1e30f, lA = 0.0f, lB = 0.0f;
    float oacc[8][4] = {};

    const uint32_t qrow = sb + (uint32_t)((wid * 16 + (lane & 15)) * APITCH + (lane >> 4) * 16);
    const uint32_t krow = (uint32_t)((((lane & 7) | ((lane & 16) >> 1)) * APITCH) + (lane & 8) * 2);
    const uint32_t vrow = (uint32_t)((lane & 15) * APITCH + (lane >> 4) * 16);

    constexpr int NKT = N_ / 64;   // 32
    for (int kt = 0; kt < NKT; ++kt) {
        cp_wait<0>();
        __syncthreads();
        if (kt + 1 < NKT) {
            issue_kv(sb + 2 * QTILE + (uint32_t)((kt + 1) & 1) * KV_STAGE, tid,
                     g_K1 + hbase + (size_t)(kt + 1) * 64 * D_,
                     g_V1 + hbase + (size_t)(kt + 1) * 64 * D_);
        }
        cp_commit();

        const uint32_t kb = sb + 2 * QTILE + (uint32_t)(kt & 1) * KV_STAGE;
        const uint32_t Ks = kb, Vs = kb + KTILE;

        // S (16 q-rows x 64 keys), log2 domain
        float sacc[8][4] = {};
        #pragma unroll
        for (int ks = 0; ks < 4; ++ks) {
            uint32_t qh4[4], ql4[4];
            ldm_x4(qh4, qrow + ks * 32);
            ldm_x4(ql4, qrow + QTILE + ks * 32);
            #pragma unroll
            for (int t = 0; t < 4; ++t) {
                uint32_t k4[4];
                ldm_x4(k4, Ks + krow + t * 16 * APITCH + ks * 32);
                mma16816(sacc[t * 2 + 0], qh4, &k4[0]);
                mma16816(sacc[t * 2 + 1], qh4, &k4[2]);
                mma16816(sacc[t * 2 + 0], ql4, &k4[0]);
                mma16816(sacc[t * 2 + 1], ql4, &k4[2]);
            }
        }

        // Online softmax (base-2)
        float tA = -1e30f, tB = -1e30f;
        #pragma unroll
        for (int f = 0; f < 8; ++f) {
            tA = fmaxf(tA, fmaxf(sacc[f][0], sacc[f][1]));
            tB = fmaxf(tB, fmaxf(sacc[f][2], sacc[f][3]));
        }
        tA = fmaxf(tA, __shfl_xor_sync(0xffffffffu, tA, 1));
        tA = fmaxf(tA, __shfl_xor_sync(0xffffffffu, tA, 2));
        tB = fmaxf(tB, __shfl_xor_sync(0xffffffffu, tB, 1));
        tB = fmaxf(tB, __shfl_xor_sync(0xffffffffu, tB, 2));
        const float nmA = fmaxf(mA, tA), nmB = fmaxf(mB, tB);
        const float cA = ex2f(mA - nmA), cB = ex2f(mB - nmB);
        mA = nmA; mB = nmB;

        float psA = 0.0f, psB = 0.0f;
        #pragma unroll
        for (int f = 0; f < 8; ++f) {
            float p0 = ex2f(sacc[f][0] - mA);
            float p1 = ex2f(sacc[f][1] - mA);
            float p2 = ex2f(sacc[f][2] - mB);
            float p3 = ex2f(sacc[f][3] - mB);
            sacc[f][0] = p0; sacc[f][1] = p1; sacc[f][2] = p2; sacc[f][3] = p3;
            psA += p0 + p1; psB += p2 + p3;
        }
        lA = lA * cA + psA;
        lB = lB * cB + psB;
        #pragma unroll
        for (int nf = 0; nf < 8; ++nf) {
            oacc[nf][0] *= cA; oacc[nf][1] *= cA;
            oacc[nf][2] *= cB; oacc[nf][3] *= cB;
        }

        // O += P @ V  (P hi-only fp16; V single)
        #pragma unroll
        for (int ks = 0; ks < 4; ++ks) {
            uint32_t phi[4];
            phi[0] = pack_h2(sacc[2 * ks][0],     sacc[2 * ks][1]);
            phi[1] = pack_h2(sacc[2 * ks][2],     sacc[2 * ks][3]);
            phi[2] = pack_h2(sacc[2 * ks + 1][0], sacc[2 * ks + 1][1]);
            phi[3] = pack_h2(sacc[2 * ks + 1][2], sacc[2 * ks + 1][3]);
            const uint32_t vb = vrow + (uint32_t)(16 * ks * APITCH);
            #pragma unroll
            for (int dg = 0; dg < 4; ++dg) {
                uint32_t v4[4];
                ldm_x4_t(v4, Vs + vb + dg * 32);
                mma16816(oacc[2 * dg],     phi, &v4[0]);
                mma16816(oacc[2 * dg + 1], phi, &v4[2]);
            }
        }
    }

    lA += __shfl_xor_sync(0xffffffffu, lA, 1);
    lA += __shfl_xor_sync(0xffffffffu, lA, 2);
    lB += __shfl_xor_sync(0xffffffffu, lB, 1);
    lB += __shfl_xor_sync(0xffffffffu, lB, 2);
    const float iA = 1.0f / lA, iB = 1.0f / lB;

    const int b = bh >> 4;
    const int h = bh & 15;
    const int rowA = qt * 128 + wid * 16 + (lane >> 2);
    #pragma unroll
    for (int nf = 0; nf < 8; ++nf) {
        const int d0 = nf * 8 + (lane & 3) * 2;
        const size_t iA0 = (size_t)(b * N_ + rowA) * C_ + h * 64 + d0;
        const size_t iB0 = (size_t)(b * N_ + rowA + 8) * C_ + h * 64 + d0;
        uint32_t hi, lo;
        split2h(oacc[nf][0] * iA, oacc[nf][1] * iA, hi, lo);
        *reinterpret_cast<uint32_t*>(&g_AOhi[iA0]) = hi;
        *reinterpret_cast<uint32_t*>(&g_AOlo[iA0]) = lo;
        split2h(oacc[nf][2] * iB, oacc[nf][3] * iB, hi, lo);
        *reinterpret_cast<uint32_t*>(&g_AOhi[iB0]) = hi;
        *reinterpret_cast<uint32_t*>(&g_AOlo[iB0]) = lo;
    }
}

// ---------------------------------------------------------------------------
extern "C" void kernel_launch(void* const* d_in, const int* in_sizes, int n_in,
                              void* d_out, int out_size)
{
    (void)in_sizes; (void)n_in; (void)out_size;
    const float* q  = (const float*)d_in[0];
    const float* k  = (const float*)d_in[1];
    const float* v  = (const float*)d_in[2];
    const float* wq = (const float*)d_in[3];
    const float* bq = (const float*)d_in[4];
    const float* wk = (const float*)d_in[5];
    const float* bk = (const float*)d_in[6];
    const float* wv = (const float*)d_in[7];
    const float* bv = (const float*)d_in[8];
    const float* wo = (const float*)d_in[9];
    const float* bo = (const float*)d_in[10];
    float* out = (float*)d_out;

    cudaFuncSetAttribute(mha_qkv_ps_kernel,
                         cudaFuncAttributeMaxDynamicSharedMemorySize, GEMM_SMEM);
    cudaFuncSetAttribute(mha_out_ps_kernel,
                         cudaFuncAttributeMaxDynamicSharedMemorySize, GEMM_SMEM);
    cudaFuncSetAttribute(mha_attn_tc_kernel,
                         cudaFuncAttributeMaxDynamicSharedMemorySize, ATTN_SMEM);

    dim3 gsplit(XSEG / 4 / 256, 7);
    split_convert_kernel<<<gsplit, 256>>>(q, k, v, wq, wk, wv, wo);

    dim3 gproj(C_ / BN, (B_ * N_) / BM, 3);   // 8 x 32 x 3
    mha_qkv_ps_kernel<<<gproj, 256, GEMM_SMEM>>>(bq, bk, bv);

    dim3 gattn(N_ / 128, B_ * H_);            // 16 x 32
    mha_attn_tc_kernel<<<gattn, 256, ATTN_SMEM>>>();

    dim3 gout(C_ / BN, (B_ * N_) / BM);       // 8 x 32
    mha_out_ps_kernel<<<gout, 256, GEMM_SMEM>>>(bo, out);
}

// round 14
// speedup vs baseline: 2.4156x; 1.2727x over previous
#include <cuda_runtime.h>
#include <cuda_fp16.h>
#include <cstdint>

// ---------------------------------------------------------------------------
// MultiheadAttention: b=2, n=2048, c=1024, h=16, d=64
// Round 14: single-fp16 activations in ALL projection GEMMs (1 MMA/product).
//   Attention keeps Q split (2-term S) + hi-only P. AO stored single fp16.
// ---------------------------------------------------------------------------

namespace {
constexpr int B_ = 2;
constexpr int N_ = 2048;
constexpr int C_ = 1024;
constexpr int H_ = 16;
constexpr int D_ = 64;
constexpr float QSCALE = 0.125f * 1.44269504088896340736f;  // scale * log2(e)

constexpr int XSEG = 4096 * 1024;
constexpr int WSEG = 1024 * 1024;

// GEMM tiling: CTA tile 128(M) x 128(N), 8 warps (4Mx2N), warp tile 32x64.
// K-super 64, ring of 2 buffers, barrier per super, 2 CTAs/SM.
constexpr int BM = 128, BN = 128;
constexpr int GPITCH = 144;                    // 128 B data + 16 pad
constexpr int TILE_A = BM * GPITCH;            // 18432 B (A single)
constexpr int TILE_B = BN * GPITCH;            // 18432 B (B single)
constexpr int SUPER_PS = TILE_A + TILE_B;      // 36864 B
constexpr int GEMM_SMEM = 2 * SUPER_PS;        // 73728 B -> 2 CTAs/SM
constexpr int NSUPER = C_ / 64;                // 16

// Attention tiling: Q hi/lo resident; K,V single fp16, double-buffered.
constexpr int APITCH = 144;
constexpr int QTILE = 128 * APITCH;            // 18432 B per Q half
constexpr int KTILE = 64 * APITCH;             // 9216 B
constexpr int KV_STAGE = 2 * KTILE;            // 18432 B
constexpr int ATTN_SMEM = 2 * QTILE + 2 * KV_STAGE;  // 73728 B -> 2 CTAs/SM
}

// fp16 buffers
__device__ __half g_X1[3 * XSEG];              // activations single fp16
__device__ __half g_W[4 * WSEG];               // weights single fp16
// Head-layout projections
__device__ __half g_Qhi[B_ * H_ * N_ * D_];    // Q split (A operand of S)
__device__ __half g_Qlo[B_ * H_ * N_ * D_];
__device__ __half g_K1[B_ * H_ * N_ * D_];
__device__ __half g_V1[B_ * H_ * N_ * D_];
// Attention output single fp16 (A operand of out-proj)
__device__ __half g_AO1[XSEG];

// ---------------------------------------------------------------------------
__device__ __forceinline__ uint32_t smem_u32(const void* p) {
    uint32_t a;
    asm("{ .reg .u64 t; cvta.to.shared.u64 t, %1; cvt.u32.u64 %0, t; }" : "=r"(a) : "l"(p));
    return a;
}
__device__ __forceinline__ void ldm_x4(uint32_t* r, uint32_t addr) {
    asm volatile("ldmatrix.sync.aligned.m8n8.x4.shared.b16 {%0,%1,%2,%3}, [%4];"
                 : "=r"(r[0]), "=r"(r[1]), "=r"(r[2]), "=r"(r[3]) : "r"(addr));
}
__device__ __forceinline__ void ldm_x4_t(uint32_t* r, uint32_t addr) {
    asm volatile("ldmatrix.sync.aligned.m8n8.x4.trans.shared.b16 {%0,%1,%2,%3}, [%4];"
                 : "=r"(r[0]), "=r"(r[1]), "=r"(r[2]), "=r"(r[3]) : "r"(addr));
}
__device__ __forceinline__ void mma16816(float* c, const uint32_t* a, const uint32_t* b) {
    asm volatile(
        "mma.sync.aligned.m16n8k16.row.col.f32.f16.f16.f32 "
        "{%0,%1,%2,%3}, {%4,%5,%6,%7}, {%8,%9}, {%0,%1,%2,%3};"
        : "+f"(c[0]), "+f"(c[1]), "+f"(c[2]), "+f"(c[3])
        : "r"(a[0]), "r"(a[1]), "r"(a[2]), "r"(a[3]), "r"(b[0]), "r"(b[1]));
}
__device__ __forceinline__ uint32_t pack_h2(float a, float b) {
    __half2 h = __floats2half2_rn(a, b);
    return *reinterpret_cast<uint32_t*>(&h);
}
__device__ __forceinline__ void split2h(float a, float b, uint32_t& hi, uint32_t& lo) {
    __half2 h = __floats2half2_rn(a, b);
    float2 f = __half22float2(h);
    __half2 l = __floats2half2_rn(a - f.x, b - f.y);
    hi = *reinterpret_cast<uint32_t*>(&h);
    lo = *reinterpret_cast<uint32_t*>(&l);
}
__device__ __forceinline__ float ex2f(float x) {
    float y;
    asm("ex2.approx.ftz.f32 %0, %1;" : "=f"(y) : "f"(x));
    return y;
}
__device__ __forceinline__ void cpa16(uint32_t dst, const void* src) {
    asm volatile("cp.async.cg.shared.global [%0], [%1], 16;" :: "r"(dst), "l"(src));
}
__device__ __forceinline__ void cp_commit() {
    asm volatile("cp.async.commit_group;" ::: "memory");
}
template <int n> __device__ __forceinline__ void cp_wait() {
    asm volatile("cp.async.wait_group %0;" :: "n"(n) : "memory");
}

// ---------------------------------------------------------------------------
// K0: fp32 -> fp16 single converter (7 segments: q,k,v,wq,wk,wv,wo)
// ---------------------------------------------------------------------------
__global__ __launch_bounds__(256)
void split_convert_kernel(const float* __restrict__ q, const float* __restrict__ k,
                          const float* __restrict__ v,
                          const float* __restrict__ wq, const float* __restrict__ wk,
                          const float* __restrict__ wv, const float* __restrict__ wo)
{
    const int seg = blockIdx.y;
    const int idx = blockIdx.x * 256 + threadIdx.x;

    const float* src;
    __half* dst;
    int n4;
    switch (seg) {
        case 0: src = q;  dst = g_X1;            n4 = XSEG / 4; break;
        case 1: src = k;  dst = g_X1 + XSEG;     n4 = XSEG / 4; break;
        case 2: src = v;  dst = g_X1 + 2 * XSEG; n4 = XSEG / 4; break;
        case 3: src = wq; dst = g_W;             n4 = WSEG / 4; break;
        case 4: src = wk; dst = g_W + WSEG;      n4 = WSEG / 4; break;
        case 5: src = wv; dst = g_W + 2 * WSEG;  n4 = WSEG / 4; break;
        default: src = wo; dst = g_W + 3 * WSEG; n4 = WSEG / 4; break;
    }
    if (idx >= n4) return;
    float4 x = reinterpret_cast<const float4*>(src)[idx];
    reinterpret_cast<uint2*>(dst)[idx] =
        make_uint2(pack_h2(x.x, x.y), pack_h2(x.z, x.w));
}

// ---------------------------------------------------------------------------
// GEMM tile: Y = A @ W^T + bias, both single fp16 (1 MMA per product).
// 256 threads, 8 warps (4Mx2N), warp tile 32x64, K-super 64.
// outMode: 0 = head-layout split (Q), 1 = head-layout single (K/V),
//          2 = flat fp32 (out-proj)
// ---------------------------------------------------------------------------
__device__ __forceinline__ void gemm_h1_tile(
    const __half* __restrict__ As, const __half* __restrict__ Bs,
    const float* __restrict__ bias,
    float* __restrict__ Yf32, __half* __restrict__ Yhi, __half* __restrict__ Ylo,
    float oscale, int outMode, int rowBase, int colBase, char* sm)
{
    const int tid = threadIdx.x;
    const int lane = tid & 31;
    const int wid = tid >> 5;
    const int warp_m = wid & 3;        // 4 x 32 rows
    const int warp_n = wid >> 2;       // 2 x 64 cols
    const uint32_t sb = smem_u32(sm);

    float acc[2][8][4] = {};

    const uint32_t aRow = (uint32_t)(warp_m * 32 + (lane & 15)) * GPITCH + (uint32_t)(lane & 16);
    const uint32_t bRow = (uint32_t)(warp_n * 64 + ((lane & 7) | ((lane & 16) >> 1))) * GPITCH
                          + (uint32_t)((lane & 8) * 2);

    auto load_super = [&](int k0, int buf) {
        const uint32_t base = sb + (uint32_t)buf * SUPER_PS;
        #pragma unroll
        for (int l = 0; l < 4; ++l) {
            const int id = tid + l * 256;            // 128 rows x 8 chunks
            const int r = id >> 3, c = id & 7;
            const uint32_t off = (uint32_t)(r * GPITCH + c * 16);
            cpa16(base + off,          As + (size_t)(rowBase + r) * C_ + k0 + c * 8);
            cpa16(base + TILE_A + off, Bs + (size_t)(colBase + r) * C_ + k0 + c * 8);
        }
    };

    load_super(0, 0);
    cp_commit();

    for (int s = 0; s < NSUPER; ++s) {
        cp_wait<0>();
        __syncthreads();
        if (s + 1 < NSUPER) load_super((s + 1) * 64, (s + 1) & 1);
        cp_commit();

        const uint32_t stB = sb + (uint32_t)(s & 1) * SUPER_PS;
        const uint32_t sB = stB + TILE_A;
        #pragma unroll
        for (int ks = 0; ks < 4; ++ks) {
            uint32_t a4[2][4];
            ldm_x4(a4[0], stB + aRow + ks * 32);
            ldm_x4(a4[1], stB + aRow + 16 * GPITCH + ks * 32);
            #pragma unroll
            for (int t = 0; t < 4; ++t) {
                uint32_t b4[4];
                ldm_x4(b4, sB + bRow + t * 16 * GPITCH + ks * 32);
                #pragma unroll
                for (int f = 0; f < 2; ++f)
                    #pragma unroll
                    for (int sub = 0; sub < 2; ++sub)
                        mma16816(acc[f][t * 2 + sub], a4[f], &b4[2 * sub]);
            }
        }
    }

    const int r = lane >> 2;
    const int cc = (lane & 3) * 2;
    #pragma unroll
    for (int f = 0; f < 2; ++f) {
        #pragma unroll
        for (int nf = 0; nf < 8; ++nf) {
            const float* c = acc[f][nf];
            const int col0 = colBase + warp_n * 64 + nf * 8 + cc;
            const int row0 = rowBase + warp_m * 32 + f * 16 + r;
            const float b0 = bias[col0], b1 = bias[col0 + 1];
            #pragma unroll
            for (int rr = 0; rr < 2; ++rr) {
                const int row = row0 + rr * 8;
                const float v0 = (c[rr * 2 + 0] + b0) * oscale;
                const float v1 = (c[rr * 2 + 1] + b1) * oscale;
                if (outMode == 2) {
                    float* p = &Yf32[(size_t)row * C_ + col0];
                    p[0] = v0; p[1] = v1;
                } else {
                    const int bb = row >> 11, i = row & (N_ - 1);
                    const int h = col0 >> 6, dd = col0 & 63;
                    const size_t idx = ((size_t)(bb * H_ + h) * N_ + i) * D_ + dd;
                    if (outMode == 0) {
                        uint32_t hi, lo;
                        split2h(v0, v1, hi, lo);
                        *reinterpret_cast<uint32_t*>(&Yhi[idx]) = hi;
                        *reinterpret_cast<uint32_t*>(&Ylo[idx]) = lo;
                    } else {
                        *reinterpret_cast<uint32_t*>(&Yhi[idx]) = pack_h2(v0, v1);
                    }
                }
            }
        }
    }
}

__global__ __launch_bounds__(256, 2)
void mha_qkv_ps_kernel(const float* __restrict__ bq, const float* __restrict__ bk,
                       const float* __restrict__ bv)
{
    extern __shared__ __align__(16) char sm[];
    const int z = blockIdx.z;
    const __half* As = g_X1 + (size_t)z * XSEG;
    const __half* Bs = g_W + (size_t)z * WSEG;
    if (z == 0) {
        gemm_h1_tile(As, Bs, bq, nullptr, g_Qhi, g_Qlo, QSCALE, 0,
                     blockIdx.y * BM, blockIdx.x * BN, sm);
    } else if (z == 1) {
        gemm_h1_tile(As, Bs, bk, nullptr, g_K1, nullptr, 1.0f, 1,
                     blockIdx.y * BM, blockIdx.x * BN, sm);
    } else {
        gemm_h1_tile(As, Bs, bv, nullptr, g_V1, nullptr, 1.0f, 1,
                     blockIdx.y * BM, blockIdx.x * BN, sm);
    }
}

__global__ __launch_bounds__(256, 2)
void mha_out_ps_kernel(const float* __restrict__ bo, float* __restrict__ out)
{
    extern __shared__ __align__(16) char sm[];
    gemm_h1_tile(g_AO1, g_W + 3 * WSEG, bo, out, nullptr, nullptr,
                 1.0f, 2, blockIdx.y * BM, blockIdx.x * BN, sm);
}

// ---------------------------------------------------------------------------
// K2: fp16 tensor-core flash attention. Q split (A), K/V single; P hi-only.
// ---------------------------------------------------------------------------
__device__ __forceinline__ void issue_kv(uint32_t dstbase, int tid,
                                         const __half* kk, const __half* vv)
{
    #pragma unroll
    for (int l = 0; l < 2; l++) {
        int cid = tid + l * 256;
        int row = cid >> 3, c8 = cid & 7;
        uint32_t off = (uint32_t)(row * APITCH + c8 * 16);
        const size_t g = (size_t)row * 64 + c8 * 8;
        cpa16(dstbase + off,         kk + g);
        cpa16(dstbase + KTILE + off, vv + g);
    }
}

__global__ __launch_bounds__(256, 2)
void mha_attn_tc_kernel()
{
    extern __shared__ __align__(16) char sm[];
    const uint32_t sb = smem_u32(sm);
    const int tid = threadIdx.x;
    const int lane = tid & 31;
    const int wid = tid >> 5;
    const int bh = blockIdx.y;
    const int qt = blockIdx.x;

    const size_t hbase = (size_t)bh * N_ * D_;
    {
        const __half* qh = g_Qhi + hbase + (size_t)qt * 128 * D_;
        const __half* ql = g_Qlo + hbase + (size_t)qt * 128 * D_;
        #pragma unroll
        for (int l = 0; l < 4; l++) {
            int cid = tid + l * 256;
            int row = cid >> 3, c8 = cid & 7;
            const size_t g = (size_t)row * 64 + c8 * 8;
            uint32_t off = (uint32_t)(row * APITCH + c8 * 16);
            *reinterpret_cast<uint4*>(sm + off) = *reinterpret_cast<const uint4*>(qh + g);
            *reinterpret_cast<uint4*>(sm + QTILE + off) = *reinterpret_cast<const uint4*>(ql + g);
        }
    }

    issue_kv(sb + 2 * QTILE, tid, g_K1 + hbase, g_V1 + hbase);
    cp_commit();

    float mA = -1e30f, mB = -1e30f, lA = 0.0f, lB = 0.0f;
    float oacc[8][4] = {};

    const uint32_t qrow = sb + (uint32_t)((wid * 16 + (lane & 15)) * APITCH + (lane >> 4) * 16);
    const uint32_t krow = (uint32_t)((((lane & 7) | ((lane & 16) >> 1)) * APITCH) + (lane & 8) * 2);
    const uint32_t vrow = (uint32_t)((lane & 15) * APITCH + (lane >> 4) * 16);

    constexpr int NKT = N_ / 64;   // 32
    for (int kt = 0; kt < NKT; ++kt) {
        cp_wait<0>();
        __syncthreads();
        if (kt + 1 < NKT) {
            issue_kv(sb + 2 * QTILE + (uint32_t)((kt + 1) & 1) * KV_STAGE, tid,
                     g_K1 + hbase + (size_t)(kt + 1) * 64 * D_,
                     g_V1 + hbase + (size_t)(kt + 1) * 64 * D_);
        }
        cp_commit();

        const uint32_t kb = sb + 2 * QTILE + (uint32_t)(kt & 1) * KV_STAGE;
        const uint32_t Ks = kb, Vs = kb + KTILE;

        // S (16 q-rows x 64 keys), log2 domain
        float sacc[8][4] = {};
        #pragma unroll
        for (int ks = 0; ks < 4; ++ks) {
            uint32_t qh4[4], ql4[4];
            ldm_x4(qh4, qrow + ks * 32);
            ldm_x4(ql4, qrow + QTILE + ks * 32);
            #pragma unroll
            for (int t = 0; t < 4; ++t) {
                uint32_t k4[4];
                ldm_x4(k4, Ks + krow + t * 16 * APITCH + ks * 32);
                mma16816(sacc[t * 2 + 0], qh4, &k4[0]);
                mma16816(sacc[t * 2 + 1], qh4, &k4[2]);
                mma16816(sacc[t * 2 + 0], ql4, &k4[0]);
                mma16816(sacc[t * 2 + 1], ql4, &k4[2]);
            }
        }

        // Online softmax (base-2)
        float tA = -1e30f, tB = -1e30f;
        #pragma unroll
        for (int f = 0; f < 8; ++f) {
            tA = fmaxf(tA, fmaxf(sacc[f][0], sacc[f][1]));
            tB = fmaxf(tB, fmaxf(sacc[f][2], sacc[f][3]));
        }
        tA = fmaxf(tA, __shfl_xor_sync(0xffffffffu, tA, 1));
        tA = fmaxf(tA, __shfl_xor_sync(0xffffffffu, tA, 2));
        tB = fmaxf(tB, __shfl_xor_sync(0xffffffffu, tB, 1));
        tB = fmaxf(tB, __shfl_xor_sync(0xffffffffu, tB, 2));
        const float nmA = fmaxf(mA, tA), nmB = fmaxf(mB, tB);
        const float cA = ex2f(mA - nmA), cB = ex2f(mB - nmB);
        mA = nmA; mB = nmB;

        float psA = 0.0f, psB = 0.0f;
        #pragma unroll
        for (int f = 0; f < 8; ++f) {
            float p0 = ex2f(sacc[f][0] - mA);
            float p1 = ex2f(sacc[f][1] - mA);
            float p2 = ex2f(sacc[f][2] - mB);
            float p3 = ex2f(sacc[f][3] - mB);
            sacc[f][0] = p0; sacc[f][1] = p1; sacc[f][2] = p2; sacc[f][3] = p3;
            psA += p0 + p1; psB += p2 + p3;
        }
        lA = lA * cA + psA;
        lB = lB * cB + psB;
        #pragma unroll
        for (int nf = 0; nf < 8; ++nf) {
            oacc[nf][0] *= cA; oacc[nf][1] *= cA;
            oacc[nf][2] *= cB; oacc[nf][3] *= cB;
        }

        // O += P @ V  (P hi-only fp16; V single)
        #pragma unroll
        for (int ks = 0; ks < 4; ++ks) {
            uint32_t phi[4];
            phi[0] = pack_h2(sacc[2 * ks][0],     sacc[2 * ks][1]);
            phi[1] = pack_h2(sacc[2 * ks][2],     sacc[2 * ks][3]);
            phi[2] = pack_h2(sacc[2 * ks + 1][0], sacc[2 * ks + 1][1]);
            phi[3] = pack_h2(sacc[2 * ks + 1][2], sacc[2 * ks + 1][3]);
            const uint32_t vb = vrow + (uint32_t)(16 * ks * APITCH);
            #pragma unroll
            for (int dg = 0; dg < 4; ++dg) {
                uint32_t v4[4];
                ldm_x4_t(v4, Vs + vb + dg * 32);
                mma16816(oacc[2 * dg],     phi, &v4[0]);
                mma16816(oacc[2 * dg + 1], phi, &v4[2]);
            }
        }
    }

    lA += __shfl_xor_sync(0xffffffffu, lA, 1);
    lA += __shfl_xor_sync(0xffffffffu, lA, 2);
    lB += __shfl_xor_sync(0xffffffffu, lB, 1);
    lB += __shfl_xor_sync(0xffffffffu, lB, 2);
    const float iA = 1.0f / lA, iB = 1.0f / lB;

    const int b = bh >> 4;
    const int h = bh & 15;
    const int rowA = qt * 128 + wid * 16 + (lane >> 2);
    #pragma unroll
    for (int nf = 0; nf < 8; ++nf) {
        const int d0 = nf * 8 + (lane & 3) * 2;
        const size_t iA0 = (size_t)(b * N_ + rowA) * C_ + h * 64 + d0;
        const size_t iB0 = (size_t)(b * N_ + rowA + 8) * C_ + h * 64 + d0;
        *reinterpret_cast<uint32_t*>(&g_AO1[iA0]) = pack_h2(oacc[nf][0] * iA, oacc[nf][1] * iA);
        *reinterpret_cast<uint32_t*>(&g_AO1[iB0]) = pack_h2(oacc[nf][2] * iB, oacc[nf][3] * iB);
    }
}

// ---------------------------------------------------------------------------
extern "C" void kernel_launch(void* const* d_in, const int* in_sizes, int n_in,
                              void* d_out, int out_size)
{
    (void)in_sizes; (void)n_in; (void)out_size;
    const float* q  = (const float*)d_in[0];
    const float* k  = (const float*)d_in[1];
    const float* v  = (const float*)d_in[2];
    const float* wq = (const float*)d_in[3];
    const float* bq = (const float*)d_in[4];
    const float* wk = (const float*)d_in[5];
    const float* bk = (const float*)d_in[6];
    const float* wv = (const float*)d_in[7];
    const float* bv = (const float*)d_in[8];
    const float* wo = (const float*)d_in[9];
    const float* bo = (const float*)d_in[10];
    float* out = (float*)d_out;

    cudaFuncSetAttribute(mha_qkv_ps_kernel,
                         cudaFuncAttributeMaxDynamicSharedMemorySize, GEMM_SMEM);
    cudaFuncSetAttribute(mha_out_ps_kernel,
                         cudaFuncAttributeMaxDynamicSharedMemorySize, GEMM_SMEM);
    cudaFuncSetAttribute(mha_attn_tc_kernel,
                         cudaFuncAttributeMaxDynamicSharedMemorySize, ATTN_SMEM);

    dim3 gsplit(XSEG / 4 / 256, 7);
    split_convert_kernel<<<gsplit, 256>>>(q, k, v, wq, wk, wv, wo);

    dim3 gproj(C_ / BN, (B_ * N_) / BM, 3);   // 8 x 32 x 3
    mha_qkv_ps_kernel<<<gproj, 256, GEMM_SMEM>>>(bq, bk, bv);

    dim3 gattn(N_ / 128, B_ * H_);            // 16 x 32
    mha_attn_tc_kernel<<<gattn, 256, ATTN_SMEM>>>();

    dim3 gout(C_ / BN, (B_ * N_) / BM);       // 8 x 32
    mha_out_ps_kernel<<<gout, 256, GEMM_SMEM>>>(bo, out);
}